// round 10
// baseline (speedup 1.0000x reference)
#include <cuda_runtime.h>
#include <cuda_bf16.h>
#include <math.h>
#include <stdint.h>

#define FULL 0xffffffffu
typedef unsigned long long u64;

constexpr int Nn = 100000;
constexpr int Ee = 1600000;
constexpr int Gg = 1000;
constexpr int Ss = 32;
constexpr int Hh = 128;
constexpr int ROUNDS = 5;
constexpr float NEG_SLOPE = 0.01f;
constexpr float LN_EPS = 1e-5f;

constexpr int APITCH = 272;
constexpr int AWARP = 16 * APITCH;                  // one 16x128 bf16 tile
constexpr int EDGE_WARPS = 8;
// per warp: tile0-hi, tile0-lo, tile1-hi, tile1-lo  (4 * AWARP)
constexpr int OFF_B_H = EDGE_WARPS * 4 * AWARP;     // 139264
constexpr int OFF_B_L = OFF_B_H + 32 * APITCH;      // 147968
constexpr int EDGE_DSMEM = OFF_B_L + 32 * APITCH;   // 156672 (1 block/SM)
constexpr int EDGE_GRID = 148;

__device__ float g_state[2][Nn * Ss];
__device__ float g_y[Nn * Hh];
__device__ float4 g_stats[Nn];
__device__ float g_gs[Gg * Ss];

__device__ __forceinline__ float lrelu(float v) { return v >= 0.f ? v : NEG_SLOPE * v; }

// ---- packed f32x2 helpers ----
__device__ __forceinline__ u64 pack2(float lo, float hi) {
    u64 r; asm("mov.b64 %0,{%1,%2};" : "=l"(r) : "f"(lo), "f"(hi)); return r;
}
__device__ __forceinline__ void unpack2(u64 v, float& lo, float& hi) {
    asm("mov.b64 {%0,%1},%2;" : "=f"(lo), "=f"(hi) : "l"(v));
}
__device__ __forceinline__ u64 fma2(u64 a, u64 b, u64 c) {
    u64 d; asm("fma.rn.f32x2 %0,%1,%2,%3;" : "=l"(d) : "l"(a), "l"(b), "l"(c)); return d;
}
__device__ __forceinline__ u64 add2(u64 a, u64 b) {
    u64 d; asm("add.rn.f32x2 %0,%1,%2;" : "=l"(d) : "l"(a), "l"(b)); return d;
}
__device__ __forceinline__ u64 mul2(u64 a, u64 b) {
    u64 d; asm("mul.rn.f32x2 %0,%1,%2;" : "=l"(d) : "l"(a), "l"(b)); return d;
}

__device__ __forceinline__ uint32_t smem_u32(const void* p) {
    uint32_t a;
    asm("{ .reg .u64 t; cvta.to.shared.u64 t, %1; cvt.u32.u64 %0, t; }" : "=r"(a) : "l"(p));
    return a;
}

__device__ __forceinline__ void ldsm4(uint32_t r[4], uint32_t addr) {
    asm volatile("ldmatrix.sync.aligned.m8n8.x4.shared.b16 {%0,%1,%2,%3}, [%4];"
                 : "=r"(r[0]), "=r"(r[1]), "=r"(r[2]), "=r"(r[3]) : "r"(addr));
}

__device__ __forceinline__ void mma16816(float acc[4], const uint32_t a[4],
                                         uint32_t b0, uint32_t b1) {
    asm volatile(
        "mma.sync.aligned.m16n8k16.row.col.f32.bf16.bf16.f32 "
        "{%0,%1,%2,%3}, {%4,%5,%6,%7}, {%8,%9}, {%0,%1,%2,%3};"
        : "+f"(acc[0]), "+f"(acc[1]), "+f"(acc[2]), "+f"(acc[3])
        : "r"(a[0]), "r"(a[1]), "r"(a[2]), "r"(a[3]), "r"(b0), "r"(b1));
}

// ---------------------------------------------------------------------------
__global__ void zero_kernel() {
    int i = blockIdx.x * blockDim.x + threadIdx.x;
    int stride = gridDim.x * blockDim.x;
    for (int k = i; k < Nn * Ss; k += stride) g_state[0][k] = 0.f;
    for (int k = i; k < Gg * Ss; k += stride) g_gs[k] = 0.f;
}

// ---------------------------------------------------------------------------
// y = state @ W1[:32] + b1 ; stats (Sy,Qy,P) ; fused copy.  4 nodes/warp.
__global__ void __launch_bounds__(192) node_gemm_kernel(
    int inb, const float* __restrict__ W1, const float* __restrict__ b1)
{
    __shared__ float sW1[32 * 128];
    __shared__ float sb1[128];
    const float* __restrict__ state_in = g_state[inb];
    float* __restrict__ state_out = g_state[inb ^ 1];

    int tid = threadIdx.x;
    for (int i = tid; i < 32 * 128; i += 192) sW1[i] = W1[i];
    if (tid < 128) sb1[tid] = b1[tid];
    __syncthreads();

    int lane = tid & 31;
    int w = tid >> 5;
    int warp_global = blockIdx.x * 6 + w;
    int nwarps = gridDim.x * 6;
    int ngroups = Nn / 4;

    float4 b1v = *(const float4*)&sb1[4 * lane];
    float4 w32v = *(const float4*)&W1[32 * 128 + 4 * lane];

    for (int g = warp_global; g < ngroups; g += nwarps) {
        int nbase = g * 4;
        float x0 = state_in[(nbase + 0) * Ss + lane];
        float x1 = state_in[(nbase + 1) * Ss + lane];
        float x2 = state_in[(nbase + 2) * Ss + lane];
        float x3 = state_in[(nbase + 3) * Ss + lane];

        state_out[(nbase + 0) * Ss + lane] = x0;   // fused copy
        state_out[(nbase + 1) * Ss + lane] = x1;
        state_out[(nbase + 2) * Ss + lane] = x2;
        state_out[(nbase + 3) * Ss + lane] = x3;

        float4 a0 = b1v, a1 = b1v, a2 = b1v, a3 = b1v;
#pragma unroll
        for (int i = 0; i < 32; i++) {
            float4 wv = *(const float4*)&sW1[i * 128 + 4 * lane];
            float s0 = __shfl_sync(FULL, x0, i);
            float s1 = __shfl_sync(FULL, x1, i);
            float s2 = __shfl_sync(FULL, x2, i);
            float s3 = __shfl_sync(FULL, x3, i);
            a0.x += s0 * wv.x; a0.y += s0 * wv.y; a0.z += s0 * wv.z; a0.w += s0 * wv.w;
            a1.x += s1 * wv.x; a1.y += s1 * wv.y; a1.z += s1 * wv.z; a1.w += s1 * wv.w;
            a2.x += s2 * wv.x; a2.y += s2 * wv.y; a2.z += s2 * wv.z; a2.w += s2 * wv.w;
            a3.x += s3 * wv.x; a3.y += s3 * wv.y; a3.z += s3 * wv.z; a3.w += s3 * wv.w;
        }
        *(float4*)&g_y[(nbase + 0) * Hh + 4 * lane] = a0;
        *(float4*)&g_y[(nbase + 1) * Hh + 4 * lane] = a1;
        *(float4*)&g_y[(nbase + 2) * Hh + 4 * lane] = a2;
        *(float4*)&g_y[(nbase + 3) * Hh + 4 * lane] = a3;

#pragma unroll
        for (int e = 0; e < 4; e++) {
            float4 a = (e == 0) ? a0 : (e == 1) ? a1 : (e == 2) ? a2 : a3;
            float s = a.x + a.y + a.z + a.w;
            float q = a.x * a.x + a.y * a.y + a.z * a.z + a.w * a.w;
            float p = a.x * w32v.x + a.y * w32v.y + a.z * w32v.z + a.w * w32v.w;
#pragma unroll
            for (int o = 16; o; o >>= 1) {
                s += __shfl_xor_sync(FULL, s, o);
                q += __shfl_xor_sync(FULL, q, o);
                p += __shfl_xor_sync(FULL, p, o);
            }
            if (lane == 0) g_stats[nbase + e] = make_float4(s, q, p, 0.f);
        }
    }
}

// ---------------------------------------------------------------------------
// per-tile epilogue: packed bias + LN2 (quad reduce) + 4 float4 atomics
__device__ __forceinline__ void epilogue_tile(
    const float acc[4][4], int dstA, int dstB, int q,
    const u64 b2p[4], const u64 g2p[4], const u64 be2p[4], u64 C001,
    float* __restrict__ state_out)
{
    u64 mA[4], mB[4];
#pragma unroll
    for (int t = 0; t < 4; t++) {
        mA[t] = add2(pack2(acc[t][0], acc[t][1]), b2p[t]);
        mB[t] = add2(pack2(acc[t][2], acc[t][3]), b2p[t]);
    }
    u64 sA2 = add2(add2(mA[0], mA[1]), add2(mA[2], mA[3]));
    u64 sB2 = add2(add2(mB[0], mB[1]), add2(mB[2], mB[3]));
    u64 qA2 = fma2(mA[0], mA[0], fma2(mA[1], mA[1], fma2(mA[2], mA[2], mul2(mA[3], mA[3]))));
    u64 qB2 = fma2(mB[0], mB[0], fma2(mB[1], mB[1], fma2(mB[2], mB[2], mul2(mB[3], mB[3]))));
    float t0, t1;
    unpack2(sA2, t0, t1); float sA = t0 + t1;
    unpack2(qA2, t0, t1); float qA = t0 + t1;
    unpack2(sB2, t0, t1); float sB = t0 + t1;
    unpack2(qB2, t0, t1); float qB = t0 + t1;
#pragma unroll
    for (int o = 2; o; o >>= 1) {
        sA += __shfl_xor_sync(FULL, sA, o);
        qA += __shfl_xor_sync(FULL, qA, o);
        sB += __shfl_xor_sync(FULL, sB, o);
        qB += __shfl_xor_sync(FULL, qB, o);
    }
    float meanA = sA * (1.f / 32.f);
    float rstdA = rsqrtf(qA * (1.f / 32.f) - meanA * meanA + LN_EPS);
    float meanB = sB * (1.f / 32.f);
    float rstdB = rsqrtf(qB * (1.f / 32.f) - meanB * meanB + LN_EPS);

    u64 rA2p = pack2(rstdA, rstdA), nmA2 = pack2(-meanA, -meanA);
    u64 rB2p = pack2(rstdB, rstdB), nmB2 = pack2(-meanB, -meanB);

    float vA[8], vB[8];
#pragma unroll
    for (int t = 0; t < 4; t++) {
        u64 agA = mul2(rA2p, g2p[t]);
        u64 offA = fma2(nmA2, agA, be2p[t]);
        u64 hA = fma2(mA[t], agA, offA);
        u64 pA = mul2(hA, C001);
        float h0, h1, p0, p1;
        unpack2(hA, h0, h1); unpack2(pA, p0, p1);
        vA[2 * t] = fmaxf(h0, p0); vA[2 * t + 1] = fmaxf(h1, p1);

        u64 agB = mul2(rB2p, g2p[t]);
        u64 offB = fma2(nmB2, agB, be2p[t]);
        u64 hB = fma2(mB[t], agB, offB);
        u64 pB = mul2(hB, C001);
        unpack2(hB, h0, h1); unpack2(pB, p0, p1);
        vB[2 * t] = fmaxf(h0, p0); vB[2 * t + 1] = fmaxf(h1, p1);
    }

    float* rowA = &state_out[dstA * Ss + 8 * q];
    float* rowB = &state_out[dstB * Ss + 8 * q];
    atomicAdd((float4*)&rowA[0], make_float4(vA[0], vA[1], vA[2], vA[3]));
    atomicAdd((float4*)&rowA[4], make_float4(vA[4], vA[5], vA[6], vA[7]));
    atomicAdd((float4*)&rowB[0], make_float4(vB[0], vB[1], vB[2], vB[3]));
    atomicAdd((float4*)&rowB[4], make_float4(vB[4], vB[5], vB[6], vB[7]));
}

// ---------------------------------------------------------------------------
// Edge kernel: 32-edge groups (two 16-row A tiles); B fragments loaded once
// per k-step and reused by both tiles (halves LDSM-B wavefronts per edge).
__global__ void __launch_bounds__(256, 1) edge_kernel(
    int inb,
    const int* __restrict__ nf, const int* __restrict__ nt,
    const float* __restrict__ ec,
    const float* __restrict__ W1,
    const float* __restrict__ g1, const float* __restrict__ be1,
    const float* __restrict__ W2, const float* __restrict__ b2,
    const float* __restrict__ g2, const float* __restrict__ be2)
{
    extern __shared__ char dsm[];
    uint32_t sbase = smem_u32(dsm);

    int tid = threadIdx.x;
    int lane = tid & 31;
    int wid = tid >> 5;

    // B staging with column permutation pi(8t+2q+r) = 8q+2t+r
    for (int p = tid; p < 32 * 128; p += 256) {
        int n = p >> 7;
        int k = p & 127;
        int t = n >> 3, q0 = (n >> 1) & 3, r = n & 1;
        int pn = 8 * q0 + 2 * t + r;
        float wv = W2[k * 32 + pn];
        __nv_bfloat16 hb = __float2bfloat16(wv);
        __nv_bfloat16 lb = __float2bfloat16(wv - __bfloat162float(hb));
        *(__nv_bfloat16*)(dsm + OFF_B_H + n * APITCH + k * 2) = hb;
        *(__nv_bfloat16*)(dsm + OFF_B_L + n * APITCH + k * 2) = lb;
    }
    __syncthreads();

    float4 w32v = *(const float4*)&W1[32 * 128 + 4 * lane];
    float4 g1v  = *(const float4*)&g1[4 * lane];
    float4 be1v = *(const float4*)&be1[4 * lane];

    float Sw = w32v.x + w32v.y + w32v.z + w32v.w;
    float Qw = w32v.x * w32v.x + w32v.y * w32v.y + w32v.z * w32v.z + w32v.w * w32v.w;
#pragma unroll
    for (int o = 16; o; o >>= 1) {
        Sw += __shfl_xor_sync(FULL, Sw, o);
        Qw += __shfl_xor_sync(FULL, Qw, o);
    }

    int q = lane & 3;
    int rA = lane >> 2;
    int rB = rA + 8;

    u64 b2p[4], g2p[4], be2p[4];
#pragma unroll
    for (int t = 0; t < 4; t++) {
        int c = 8 * q + 2 * t;
        b2p[t]  = pack2(b2[c],  b2[c + 1]);
        g2p[t]  = pack2(g2[c],  g2[c + 1]);
        be2p[t] = pack2(be2[c], be2[c + 1]);
    }
    const u64 C001 = pack2(NEG_SLOPE, NEG_SLOPE);

    // staging base for this warp (4 tiles: t0h, t0l, t1h, t1l)
    char* aStore = dsm + wid * 4 * AWARP + lane * 8;

    int aRow = lane & 15;
    int aColB = ((lane >> 4) & 1) * 16;
    uint32_t ldA0H = sbase + wid * 4 * AWARP + aRow * APITCH + aColB;
    uint32_t ldA0L = ldA0H + AWARP;
    uint32_t ldA1H = ldA0H + 2 * AWARP;
    uint32_t ldA1L = ldA0H + 3 * AWARP;

    int bRow = ((lane >> 4) & 1) * 8 + (lane & 7);
    int bKB = ((lane >> 3) & 1) * 16;
    uint32_t ldBH01 = sbase + OFF_B_H + bRow * APITCH + bKB;
    uint32_t ldBH23 = ldBH01 + 16 * APITCH;
    uint32_t ldBL01 = sbase + OFF_B_L + bRow * APITCH + bKB;
    uint32_t ldBL23 = ldBL01 + 16 * APITCH;

    const float4* __restrict__ yv = (const float4*)g_y;
    float* __restrict__ state_out = g_state[inb ^ 1];

    int ngroups = Ee / 32;          // 50000
    int wg = blockIdx.x * EDGE_WARPS + wid;
    int nw = gridDim.x * EDGE_WARPS;

    for (int g = wg; g < ngroups; g += nw) {
        int base = g * 32;

        // ---- gather + stats-based LN1 + bf16 split + stage (32 rows) ----
#pragma unroll
        for (int j = 0; j < 8; j++) {
            int4 NF = *(const int4*)&nf[base + 4 * j];
            float4 C = *(const float4*)&ec[base + 4 * j];
            int srcs[4] = {NF.x, NF.y, NF.z, NF.w};
            float cs[4] = {C.x, C.y, C.z, C.w};
#pragma unroll
            for (int e = 0; e < 4; e++) {
                int src = srcs[e];
                float c = cs[e];
                float4 st = g_stats[src];
                float4 a = yv[src * (Hh / 4) + lane];
                a.x = fmaf(c, w32v.x, a.x);
                a.y = fmaf(c, w32v.y, a.y);
                a.z = fmaf(c, w32v.z, a.z);
                a.w = fmaf(c, w32v.w, a.w);

                float s = fmaf(c, Sw, st.x);
                float qq = fmaf(c * c, Qw, fmaf(2.f * c, st.z, st.y));
                float mean = s * (1.f / 128.f);
                float var = qq * (1.f / 128.f) - mean * mean;
                float rstd = rsqrtf(var + LN_EPS);

                float4 hv;
                hv.x = lrelu(fmaf((a.x - mean) * rstd, g1v.x, be1v.x));
                hv.y = lrelu(fmaf((a.y - mean) * rstd, g1v.y, be1v.y));
                hv.z = lrelu(fmaf((a.z - mean) * rstd, g1v.z, be1v.z));
                hv.w = lrelu(fmaf((a.w - mean) * rstd, g1v.w, be1v.w));

                __nv_bfloat162 h01 = __float22bfloat162_rn(make_float2(hv.x, hv.y));
                __nv_bfloat162 h23 = __float22bfloat162_rn(make_float2(hv.z, hv.w));
                float2 f01 = __bfloat1622float2(h01);
                float2 f23 = __bfloat1622float2(h23);
                __nv_bfloat162 l01 = __float22bfloat162_rn(make_float2(hv.x - f01.x, hv.y - f01.y));
                __nv_bfloat162 l23 = __float22bfloat162_rn(make_float2(hv.z - f23.x, hv.w - f23.y));
                u64 packh = (u64)(*(uint32_t*)&h01) | ((u64)(*(uint32_t*)&h23) << 32);
                u64 packl = (u64)(*(uint32_t*)&l01) | ((u64)(*(uint32_t*)&l23) << 32);
                int row = 4 * j + e;                 // 0..31
                char* dst = aStore + (row >> 4) * 2 * AWARP + (row & 15) * APITCH;
                *(u64*)dst = packh;
                *(u64*)(dst + AWARP) = packl;
            }
        }
        __syncwarp();

        // hoist destination loads (latency hides behind MMA)
        int dstA0 = __ldg(&nt[base + rA]);
        int dstB0 = __ldg(&nt[base + rB]);
        int dstA1 = __ldg(&nt[base + 16 + rA]);
        int dstB1 = __ldg(&nt[base + 16 + rB]);

        // ---- MMA: both tiles share each k-step's B fragments ----
        float acc0[4][4], acc1[4][4];
#pragma unroll
        for (int t = 0; t < 4; t++)
#pragma unroll
            for (int j2 = 0; j2 < 4; j2++) { acc0[t][j2] = 0.f; acc1[t][j2] = 0.f; }

#pragma unroll
        for (int k = 0; k < 8; k++) {
            uint32_t bh01[4], bh23[4], bl01[4], bl23[4];
            ldsm4(bh01, ldBH01 + k * 32);
            ldsm4(bh23, ldBH23 + k * 32);
            ldsm4(bl01, ldBL01 + k * 32);
            ldsm4(bl23, ldBL23 + k * 32);

            uint32_t ah[4], al[4];
            ldsm4(ah, ldA0H + k * 32);
            ldsm4(al, ldA0L + k * 32);
            mma16816(acc0[0], ah, bh01[0], bh01[1]);
            mma16816(acc0[1], ah, bh01[2], bh01[3]);
            mma16816(acc0[2], ah, bh23[0], bh23[1]);
            mma16816(acc0[3], ah, bh23[2], bh23[3]);
            mma16816(acc0[0], ah, bl01[0], bl01[1]);
            mma16816(acc0[1], ah, bl01[2], bl01[3]);
            mma16816(acc0[2], ah, bl23[0], bl23[1]);
            mma16816(acc0[3], ah, bl23[2], bl23[3]);
            mma16816(acc0[0], al, bh01[0], bh01[1]);
            mma16816(acc0[1], al, bh01[2], bh01[3]);
            mma16816(acc0[2], al, bh23[0], bh23[1]);
            mma16816(acc0[3], al, bh23[2], bh23[3]);

            ldsm4(ah, ldA1H + k * 32);
            ldsm4(al, ldA1L + k * 32);
            mma16816(acc1[0], ah, bh01[0], bh01[1]);
            mma16816(acc1[1], ah, bh01[2], bh01[3]);
            mma16816(acc1[2], ah, bh23[0], bh23[1]);
            mma16816(acc1[3], ah, bh23[2], bh23[3]);
            mma16816(acc1[0], ah, bl01[0], bl01[1]);
            mma16816(acc1[1], ah, bl01[2], bl01[3]);
            mma16816(acc1[2], ah, bl23[0], bl23[1]);
            mma16816(acc1[3], ah, bl23[2], bl23[3]);
            mma16816(acc1[0], al, bh01[0], bh01[1]);
            mma16816(acc1[1], al, bh01[2], bh01[3]);
            mma16816(acc1[2], al, bh23[0], bh23[1]);
            mma16816(acc1[3], al, bh23[2], bh23[3]);
        }
        __syncwarp();

        // ---- epilogues ----
        epilogue_tile(acc0, dstA0, dstB0, q, b2p, g2p, be2p, C001, state_out);
        epilogue_tile(acc1, dstA1, dstB1, q, b2p, g2p, be2p, C001, state_out);
    }
}

// ---------------------------------------------------------------------------
__global__ void graphsum_kernel(int inb, const int* __restrict__ ngi) {
    int t = blockIdx.x * blockDim.x + threadIdx.x;
    int total = Nn * (Ss / 4);
    if (t >= total) return;
    int n = t >> 3;
    int q = t & 7;
    const float4* s = reinterpret_cast<const float4*>(g_state[inb]);
    float4 v = s[t];
    int g = ngi[n];
    atomicAdd(reinterpret_cast<float4*>(&g_gs[g * Ss + 4 * q]), v);
}

// ---------------------------------------------------------------------------
__global__ void __launch_bounds__(128) readout_kernel(
    const float* __restrict__ Wo1, const float* __restrict__ bo1,
    const float* __restrict__ go, const float* __restrict__ beo,
    const float* __restrict__ Wo2, const float* __restrict__ bo2,
    float* __restrict__ out)
{
    __shared__ float sW[32 * 128];
    __shared__ float sb[128], sg[128], sbe[128];
    __shared__ float sW2[256];
    __shared__ float sb2[2];

    int tid = threadIdx.x;
    for (int i = tid; i < 32 * 128; i += 128) sW[i] = Wo1[i];
    sb[tid] = bo1[tid]; sg[tid] = go[tid]; sbe[tid] = beo[tid];
    sW2[tid] = Wo2[tid];
    sW2[tid + 128] = Wo2[tid + 128];
    if (tid < 2) sb2[tid] = bo2[tid];
    __syncthreads();

    int lane = tid & 31;
    int w = tid >> 5;
    int g = blockIdx.x * 4 + w;
    if (g >= Gg) return;

    float x = g_gs[g * Ss + lane];
    float4 a;
    a.x = sb[4 * lane]; a.y = sb[4 * lane + 1]; a.z = sb[4 * lane + 2]; a.w = sb[4 * lane + 3];
#pragma unroll
    for (int i = 0; i < 32; i++) {
        float xi = __shfl_sync(FULL, x, i);
        float4 wv = *(const float4*)&sW[i * 128 + 4 * lane];
        a.x += xi * wv.x; a.y += xi * wv.y; a.z += xi * wv.z; a.w += xi * wv.w;
    }
    float s = a.x + a.y + a.z + a.w;
    float s2 = a.x * a.x + a.y * a.y + a.z * a.z + a.w * a.w;
#pragma unroll
    for (int o = 16; o; o >>= 1) {
        s += __shfl_xor_sync(FULL, s, o);
        s2 += __shfl_xor_sync(FULL, s2, o);
    }
    float mean = s * (1.f / 128.f);
    float var = s2 * (1.f / 128.f) - mean * mean;
    float rstd = rsqrtf(var + LN_EPS);
    float h0 = lrelu((a.x - mean) * rstd * sg[4 * lane + 0] + sbe[4 * lane + 0]);
    float h1 = lrelu((a.y - mean) * rstd * sg[4 * lane + 1] + sbe[4 * lane + 1]);
    float h2 = lrelu((a.z - mean) * rstd * sg[4 * lane + 2] + sbe[4 * lane + 2]);
    float h3 = lrelu((a.w - mean) * rstd * sg[4 * lane + 3] + sbe[4 * lane + 3]);

    float p0 = h0 * sW2[(4 * lane + 0) * 2] + h1 * sW2[(4 * lane + 1) * 2]
             + h2 * sW2[(4 * lane + 2) * 2] + h3 * sW2[(4 * lane + 3) * 2];
    float p1 = h0 * sW2[(4 * lane + 0) * 2 + 1] + h1 * sW2[(4 * lane + 1) * 2 + 1]
             + h2 * sW2[(4 * lane + 2) * 2 + 1] + h3 * sW2[(4 * lane + 3) * 2 + 1];
#pragma unroll
    for (int o = 16; o; o >>= 1) {
        p0 += __shfl_xor_sync(FULL, p0, o);
        p1 += __shfl_xor_sync(FULL, p1, o);
    }
    if (lane == 0) {
        float mu = p0 + sb2[0];
        float v = p1 + sb2[1];
        float sp = (v > 0.f) ? v + log1pf(expf(-v)) : log1pf(expf(v));
        out[g * 2 + 0] = mu;
        out[g * 2 + 1] = sp;
    }
}

// ---------------------------------------------------------------------------
extern "C" void kernel_launch(void* const* d_in, const int* in_sizes, int n_in,
                              void* d_out, int out_size) {
    const int* nf = (const int*)d_in[0];
    const int* nt = (const int*)d_in[1];
    const float* ec = (const float*)d_in[2];
    const int* ngi = (const int*)d_in[3];
    const float* W1 = (const float*)d_in[6];
    const float* b1 = (const float*)d_in[7];
    const float* g1 = (const float*)d_in[8];
    const float* be1 = (const float*)d_in[9];
    const float* W2 = (const float*)d_in[10];
    const float* b2 = (const float*)d_in[11];
    const float* g2 = (const float*)d_in[12];
    const float* be2 = (const float*)d_in[13];
    const float* Wo1 = (const float*)d_in[14];
    const float* bo1 = (const float*)d_in[15];
    const float* go = (const float*)d_in[16];
    const float* beo = (const float*)d_in[17];
    const float* Wo2 = (const float*)d_in[18];
    const float* bo2 = (const float*)d_in[19];
    float* out = (float*)d_out;

    cudaFuncSetAttribute(edge_kernel, cudaFuncAttributeMaxDynamicSharedMemorySize, EDGE_DSMEM);

    zero_kernel<<<4096, 256>>>();

    int cur = 0;
    for (int r = 0; r < ROUNDS; r++) {
        node_gemm_kernel<<<1024, 192>>>(cur, W1, b1);   // also copies state cur -> cur^1
        edge_kernel<<<EDGE_GRID, 256, EDGE_DSMEM>>>(cur, nf, nt, ec,
                                                    W1, g1, be1, W2, b2, g2, be2);
        cur ^= 1;
    }

    graphsum_kernel<<<(Nn * 8 + 255) / 256, 256>>>(cur, ngi);
    readout_kernel<<<(Gg + 3) / 4, 128>>>(Wo1, bo1, go, beo, Wo2, bo2, out);
}

// round 11
// speedup vs baseline: 1.1211x; 1.1211x over previous
#include <cuda_runtime.h>
#include <cuda_bf16.h>
#include <math.h>
#include <stdint.h>

#define FULL 0xffffffffu
typedef unsigned long long u64;

constexpr int Nn = 100000;
constexpr int Ee = 1600000;
constexpr int Gg = 1000;
constexpr int Ss = 32;
constexpr int Hh = 128;
constexpr int ROUNDS = 5;
constexpr float NEG_SLOPE = 0.01f;
constexpr float LN_EPS = 1e-5f;

constexpr int APITCH = 272;
constexpr int AWARP = 16 * APITCH;
constexpr int EDGE_WARPS = 8;                       // 256-thread blocks
constexpr int OFF_B_H = EDGE_WARPS * 2 * AWARP;     // 69632
constexpr int OFF_B_L = OFF_B_H + 32 * APITCH;      // 78336
constexpr int EDGE_DSMEM = OFF_B_L + 32 * APITCH;   // 87040  (2 blocks/SM, 16 warps/SM)
constexpr int EDGE_GRID = 296;

__device__ float g_state[2][Nn * Ss];
__device__ float g_y[Nn * Hh];
__device__ float4 g_stats[Nn];
__device__ float g_gs[Gg * Ss];

__device__ __forceinline__ float lrelu(float v) { return v >= 0.f ? v : NEG_SLOPE * v; }

// ---- packed f32x2 helpers ----
__device__ __forceinline__ u64 pack2(float lo, float hi) {
    u64 r; asm("mov.b64 %0,{%1,%2};" : "=l"(r) : "f"(lo), "f"(hi)); return r;
}
__device__ __forceinline__ void unpack2(u64 v, float& lo, float& hi) {
    asm("mov.b64 {%0,%1},%2;" : "=f"(lo), "=f"(hi) : "l"(v));
}
__device__ __forceinline__ u64 fma2(u64 a, u64 b, u64 c) {
    u64 d; asm("fma.rn.f32x2 %0,%1,%2,%3;" : "=l"(d) : "l"(a), "l"(b), "l"(c)); return d;
}
__device__ __forceinline__ u64 add2(u64 a, u64 b) {
    u64 d; asm("add.rn.f32x2 %0,%1,%2;" : "=l"(d) : "l"(a), "l"(b)); return d;
}
__device__ __forceinline__ u64 mul2(u64 a, u64 b) {
    u64 d; asm("mul.rn.f32x2 %0,%1,%2;" : "=l"(d) : "l"(a), "l"(b)); return d;
}

__device__ __forceinline__ uint32_t smem_u32(const void* p) {
    uint32_t a;
    asm("{ .reg .u64 t; cvta.to.shared.u64 t, %1; cvt.u32.u64 %0, t; }" : "=r"(a) : "l"(p));
    return a;
}

__device__ __forceinline__ void ldsm4(uint32_t r[4], uint32_t addr) {
    asm volatile("ldmatrix.sync.aligned.m8n8.x4.shared.b16 {%0,%1,%2,%3}, [%4];"
                 : "=r"(r[0]), "=r"(r[1]), "=r"(r[2]), "=r"(r[3]) : "r"(addr));
}

__device__ __forceinline__ void mma16816(float acc[4], const uint32_t a[4],
                                         uint32_t b0, uint32_t b1) {
    asm volatile(
        "mma.sync.aligned.m16n8k16.row.col.f32.bf16.bf16.f32 "
        "{%0,%1,%2,%3}, {%4,%5,%6,%7}, {%8,%9}, {%0,%1,%2,%3};"
        : "+f"(acc[0]), "+f"(acc[1]), "+f"(acc[2]), "+f"(acc[3])
        : "r"(a[0]), "r"(a[1]), "r"(a[2]), "r"(a[3]), "r"(b0), "r"(b1));
}

// ---------------------------------------------------------------------------
__global__ void zero_kernel() {
    int i = blockIdx.x * blockDim.x + threadIdx.x;
    int stride = gridDim.x * blockDim.x;
    for (int k = i; k < Nn * Ss; k += stride) g_state[0][k] = 0.f;
    for (int k = i; k < Gg * Ss; k += stride) g_gs[k] = 0.f;
}

// ---------------------------------------------------------------------------
// y = state @ W1[:32] + b1 ; stats (Sy,Qy,P) ; fused copy.  4 nodes/warp.
__global__ void __launch_bounds__(192) node_gemm_kernel(
    int inb, const float* __restrict__ W1, const float* __restrict__ b1)
{
    __shared__ float sW1[32 * 128];
    __shared__ float sb1[128];
    const float* __restrict__ state_in = g_state[inb];
    float* __restrict__ state_out = g_state[inb ^ 1];

    int tid = threadIdx.x;
    for (int i = tid; i < 32 * 128; i += 192) sW1[i] = W1[i];
    if (tid < 128) sb1[tid] = b1[tid];
    __syncthreads();

    int lane = tid & 31;
    int w = tid >> 5;
    int warp_global = blockIdx.x * 6 + w;
    int nwarps = gridDim.x * 6;
    int ngroups = Nn / 4;

    float4 b1v = *(const float4*)&sb1[4 * lane];
    float4 w32v = *(const float4*)&W1[32 * 128 + 4 * lane];

    for (int g = warp_global; g < ngroups; g += nwarps) {
        int nbase = g * 4;
        float x0 = state_in[(nbase + 0) * Ss + lane];
        float x1 = state_in[(nbase + 1) * Ss + lane];
        float x2 = state_in[(nbase + 2) * Ss + lane];
        float x3 = state_in[(nbase + 3) * Ss + lane];

        state_out[(nbase + 0) * Ss + lane] = x0;   // fused copy
        state_out[(nbase + 1) * Ss + lane] = x1;
        state_out[(nbase + 2) * Ss + lane] = x2;
        state_out[(nbase + 3) * Ss + lane] = x3;

        float4 a0 = b1v, a1 = b1v, a2 = b1v, a3 = b1v;
#pragma unroll
        for (int i = 0; i < 32; i++) {
            float4 wv = *(const float4*)&sW1[i * 128 + 4 * lane];
            float s0 = __shfl_sync(FULL, x0, i);
            float s1 = __shfl_sync(FULL, x1, i);
            float s2 = __shfl_sync(FULL, x2, i);
            float s3 = __shfl_sync(FULL, x3, i);
            a0.x += s0 * wv.x; a0.y += s0 * wv.y; a0.z += s0 * wv.z; a0.w += s0 * wv.w;
            a1.x += s1 * wv.x; a1.y += s1 * wv.y; a1.z += s1 * wv.z; a1.w += s1 * wv.w;
            a2.x += s2 * wv.x; a2.y += s2 * wv.y; a2.z += s2 * wv.z; a2.w += s2 * wv.w;
            a3.x += s3 * wv.x; a3.y += s3 * wv.y; a3.z += s3 * wv.z; a3.w += s3 * wv.w;
        }
        *(float4*)&g_y[(nbase + 0) * Hh + 4 * lane] = a0;
        *(float4*)&g_y[(nbase + 1) * Hh + 4 * lane] = a1;
        *(float4*)&g_y[(nbase + 2) * Hh + 4 * lane] = a2;
        *(float4*)&g_y[(nbase + 3) * Hh + 4 * lane] = a3;

#pragma unroll
        for (int e = 0; e < 4; e++) {
            float4 a = (e == 0) ? a0 : (e == 1) ? a1 : (e == 2) ? a2 : a3;
            float s = a.x + a.y + a.z + a.w;
            float q = a.x * a.x + a.y * a.y + a.z * a.z + a.w * a.w;
            float p = a.x * w32v.x + a.y * w32v.y + a.z * w32v.z + a.w * w32v.w;
#pragma unroll
            for (int o = 16; o; o >>= 1) {
                s += __shfl_xor_sync(FULL, s, o);
                q += __shfl_xor_sync(FULL, q, o);
                p += __shfl_xor_sync(FULL, p, o);
            }
            if (lane == 0) g_stats[nbase + e] = make_float4(s, q, p, 0.f);
        }
    }
}

// ---------------------------------------------------------------------------
// Edge kernel: R9 champion config (256 thr, 2 blocks/SM, 16-edge groups),
// plus batched gather loads (MLP~8) and packed-f32x2 LN1 epilogue.
__global__ void __launch_bounds__(256, 2) edge_kernel(
    int inb,
    const int* __restrict__ nf, const int* __restrict__ nt,
    const float* __restrict__ ec,
    const float* __restrict__ W1,
    const float* __restrict__ g1, const float* __restrict__ be1,
    const float* __restrict__ W2, const float* __restrict__ b2,
    const float* __restrict__ g2, const float* __restrict__ be2)
{
    extern __shared__ char dsm[];
    uint32_t sbase = smem_u32(dsm);

    int tid = threadIdx.x;
    int lane = tid & 31;
    int wid = tid >> 5;

    // B staging with column permutation pi(8t+2q+r) = 8q+2t+r
    for (int p = tid; p < 32 * 128; p += 256) {
        int n = p >> 7;
        int k = p & 127;
        int t = n >> 3, q0 = (n >> 1) & 3, r = n & 1;
        int pn = 8 * q0 + 2 * t + r;
        float wv = W2[k * 32 + pn];
        __nv_bfloat16 hb = __float2bfloat16(wv);
        __nv_bfloat16 lb = __float2bfloat16(wv - __bfloat162float(hb));
        *(__nv_bfloat16*)(dsm + OFF_B_H + n * APITCH + k * 2) = hb;
        *(__nv_bfloat16*)(dsm + OFF_B_L + n * APITCH + k * 2) = lb;
    }
    __syncthreads();

    float4 w32v = *(const float4*)&W1[32 * 128 + 4 * lane];
    // packed per-lane LN1 constants
    u64 w32p0 = pack2(w32v.x, w32v.y), w32p1 = pack2(w32v.z, w32v.w);
    u64 g1p0, g1p1, be1p0, be1p1;
    {
        float4 g1v  = *(const float4*)&g1[4 * lane];
        float4 be1v = *(const float4*)&be1[4 * lane];
        g1p0 = pack2(g1v.x, g1v.y);  g1p1 = pack2(g1v.z, g1v.w);
        be1p0 = pack2(be1v.x, be1v.y); be1p1 = pack2(be1v.z, be1v.w);
    }

    float Sw = w32v.x + w32v.y + w32v.z + w32v.w;
    float Qw = w32v.x * w32v.x + w32v.y * w32v.y + w32v.z * w32v.z + w32v.w * w32v.w;
#pragma unroll
    for (int o = 16; o; o >>= 1) {
        Sw += __shfl_xor_sync(FULL, Sw, o);
        Qw += __shfl_xor_sync(FULL, Qw, o);
    }

    int q = lane & 3;
    int rA = lane >> 2;
    int rB = rA + 8;

    u64 b2p[4], g2p[4], be2p[4];
#pragma unroll
    for (int t = 0; t < 4; t++) {
        int c = 8 * q + 2 * t;
        b2p[t]  = pack2(b2[c],  b2[c + 1]);
        g2p[t]  = pack2(g2[c],  g2[c + 1]);
        be2p[t] = pack2(be2[c], be2[c + 1]);
    }
    const u64 C001 = pack2(NEG_SLOPE, NEG_SLOPE);

    char* aStoreH = dsm + wid * 2 * AWARP + lane * 8;
    char* aStoreL = aStoreH + AWARP;

    int aRow = lane & 15;
    int aColB = ((lane >> 4) & 1) * 16;
    uint32_t ldAH = sbase + wid * 2 * AWARP + aRow * APITCH + aColB;
    uint32_t ldAL = ldAH + AWARP;

    int bRow = ((lane >> 4) & 1) * 8 + (lane & 7);
    int bKB = ((lane >> 3) & 1) * 16;
    uint32_t ldBH01 = sbase + OFF_B_H + bRow * APITCH + bKB;
    uint32_t ldBH23 = ldBH01 + 16 * APITCH;
    uint32_t ldBL01 = sbase + OFF_B_L + bRow * APITCH + bKB;
    uint32_t ldBL23 = ldBL01 + 16 * APITCH;

    const float4* __restrict__ yv = (const float4*)g_y;
    float* __restrict__ state_out = g_state[inb ^ 1];

    int ngroups = Ee / 16;
    int wg = blockIdx.x * EDGE_WARPS + wid;
    int nw = gridDim.x * EDGE_WARPS;

    for (int g = wg; g < ngroups; g += nw) {
        int base = g * 16;

        // ---- gather (batched loads) + stats-LN1 (packed) + split + stage ----
#pragma unroll
        for (int j = 0; j < 4; j++) {
            int4 NF = *(const int4*)&nf[base + 4 * j];
            float4 C = *(const float4*)&ec[base + 4 * j];
            int srcs[4] = {NF.x, NF.y, NF.z, NF.w};
            float cs[4] = {C.x, C.y, C.z, C.w};

            // batch all 8 independent loads before any dependent math
            float4 st[4], av[4];
#pragma unroll
            for (int e = 0; e < 4; e++) st[e] = g_stats[srcs[e]];
#pragma unroll
            for (int e = 0; e < 4; e++) av[e] = yv[srcs[e] * (Hh / 4) + lane];

#pragma unroll
            for (int e = 0; e < 4; e++) {
                float c = cs[e];
                u64 cp = pack2(c, c);
                u64 a01 = fma2(cp, w32p0, pack2(av[e].x, av[e].y));
                u64 a23 = fma2(cp, w32p1, pack2(av[e].z, av[e].w));

                float s = fmaf(c, Sw, st[e].x);
                float qq = fmaf(c * c, Qw, fmaf(2.f * c, st[e].z, st[e].y));
                float mean = s * (1.f / 128.f);
                float var = qq * (1.f / 128.f) - mean * mean;
                float rstd = rsqrtf(var + LN_EPS);

                // packed affine: h = (a - mean)*rstd*g1 + be1
                u64 rp = pack2(rstd, rstd);
                u64 nm = pack2(-mean, -mean);
                u64 ag0 = mul2(rp, g1p0);
                u64 ag1 = mul2(rp, g1p1);
                u64 off0 = fma2(nm, ag0, be1p0);
                u64 off1 = fma2(nm, ag1, be1p1);
                u64 h01 = fma2(a01, ag0, off0);
                u64 h23 = fma2(a23, ag1, off1);
                u64 p01 = mul2(h01, C001);
                u64 p23 = mul2(h23, C001);
                float hx, hy, hz, hw, px, py, pz, pw;
                unpack2(h01, hx, hy); unpack2(p01, px, py);
                unpack2(h23, hz, hw); unpack2(p23, pz, pw);
                hx = fmaxf(hx, px); hy = fmaxf(hy, py);
                hz = fmaxf(hz, pz); hw = fmaxf(hw, pw);

                __nv_bfloat162 hb01 = __float22bfloat162_rn(make_float2(hx, hy));
                __nv_bfloat162 hb23 = __float22bfloat162_rn(make_float2(hz, hw));
                float2 f01 = __bfloat1622float2(hb01);
                float2 f23 = __bfloat1622float2(hb23);
                __nv_bfloat162 lb01 = __float22bfloat162_rn(make_float2(hx - f01.x, hy - f01.y));
                __nv_bfloat162 lb23 = __float22bfloat162_rn(make_float2(hz - f23.x, hw - f23.y));
                u64 packh = (u64)(*(uint32_t*)&hb01) | ((u64)(*(uint32_t*)&hb23) << 32);
                u64 packl = (u64)(*(uint32_t*)&lb01) | ((u64)(*(uint32_t*)&lb23) << 32);
                int row = 4 * j + e;
                *(u64*)(aStoreH + row * APITCH) = packh;
                *(u64*)(aStoreL + row * APITCH) = packl;
            }
        }
        __syncwarp();

        // hoist destination loads: latency hides behind the MMA section
        int dstA = __ldg(&nt[base + rA]);
        int dstB = __ldg(&nt[base + rB]);

        // ---- MMA: D = Ah@Bh + Ah@Bl + Al@Bh ----
        float acc[4][4];
#pragma unroll
        for (int t = 0; t < 4; t++)
#pragma unroll
            for (int j2 = 0; j2 < 4; j2++) acc[t][j2] = 0.f;

#pragma unroll
        for (int k = 0; k < 8; k++) {
            uint32_t ah[4], al[4], bh01[4], bh23[4], bl01[4], bl23[4];
            ldsm4(ah, ldAH + k * 32);
            ldsm4(al, ldAL + k * 32);
            ldsm4(bh01, ldBH01 + k * 32);
            ldsm4(bh23, ldBH23 + k * 32);
            ldsm4(bl01, ldBL01 + k * 32);
            ldsm4(bl23, ldBL23 + k * 32);

            mma16816(acc[0], ah, bh01[0], bh01[1]);
            mma16816(acc[1], ah, bh01[2], bh01[3]);
            mma16816(acc[2], ah, bh23[0], bh23[1]);
            mma16816(acc[3], ah, bh23[2], bh23[3]);

            mma16816(acc[0], ah, bl01[0], bl01[1]);
            mma16816(acc[1], ah, bl01[2], bl01[3]);
            mma16816(acc[2], ah, bl23[0], bl23[1]);
            mma16816(acc[3], ah, bl23[2], bl23[3]);

            mma16816(acc[0], al, bh01[0], bh01[1]);
            mma16816(acc[1], al, bh01[2], bh01[3]);
            mma16816(acc[2], al, bh23[0], bh23[1]);
            mma16816(acc[3], al, bh23[2], bh23[3]);
        }
        __syncwarp();

        // ---- epilogue: packed bias + LN2 (quad reduction) + float4 scatter ----
        u64 mA[4], mB[4];
#pragma unroll
        for (int t = 0; t < 4; t++) {
            mA[t] = add2(pack2(acc[t][0], acc[t][1]), b2p[t]);
            mB[t] = add2(pack2(acc[t][2], acc[t][3]), b2p[t]);
        }
        u64 sA2 = add2(add2(mA[0], mA[1]), add2(mA[2], mA[3]));
        u64 sB2 = add2(add2(mB[0], mB[1]), add2(mB[2], mB[3]));
        u64 qA2 = fma2(mA[0], mA[0], fma2(mA[1], mA[1], fma2(mA[2], mA[2], mul2(mA[3], mA[3]))));
        u64 qB2 = fma2(mB[0], mB[0], fma2(mB[1], mB[1], fma2(mB[2], mB[2], mul2(mB[3], mB[3]))));
        float t0, t1;
        unpack2(sA2, t0, t1); float sA = t0 + t1;
        unpack2(qA2, t0, t1); float qA = t0 + t1;
        unpack2(sB2, t0, t1); float sB = t0 + t1;
        unpack2(qB2, t0, t1); float qB = t0 + t1;
#pragma unroll
        for (int o = 2; o; o >>= 1) {
            sA += __shfl_xor_sync(FULL, sA, o);
            qA += __shfl_xor_sync(FULL, qA, o);
            sB += __shfl_xor_sync(FULL, sB, o);
            qB += __shfl_xor_sync(FULL, qB, o);
        }
        float meanA = sA * (1.f / 32.f);
        float rstdA = rsqrtf(qA * (1.f / 32.f) - meanA * meanA + LN_EPS);
        float meanB = sB * (1.f / 32.f);
        float rstdB = rsqrtf(qB * (1.f / 32.f) - meanB * meanB + LN_EPS);

        u64 rA2p = pack2(rstdA, rstdA), nmA2 = pack2(-meanA, -meanA);
        u64 rB2p = pack2(rstdB, rstdB), nmB2 = pack2(-meanB, -meanB);

        float vA[8], vB[8];
#pragma unroll
        for (int t = 0; t < 4; t++) {
            u64 agA = mul2(rA2p, g2p[t]);
            u64 offA = fma2(nmA2, agA, be2p[t]);
            u64 hA = fma2(mA[t], agA, offA);
            u64 pA = mul2(hA, C001);
            float h0, h1, p0, p1;
            unpack2(hA, h0, h1); unpack2(pA, p0, p1);
            vA[2 * t] = fmaxf(h0, p0); vA[2 * t + 1] = fmaxf(h1, p1);

            u64 agB = mul2(rB2p, g2p[t]);
            u64 offB = fma2(nmB2, agB, be2p[t]);
            u64 hB = fma2(mB[t], agB, offB);
            u64 pB = mul2(hB, C001);
            unpack2(hB, h0, h1); unpack2(pB, p0, p1);
            vB[2 * t] = fmaxf(h0, p0); vB[2 * t + 1] = fmaxf(h1, p1);
        }

        float* rowA = &state_out[dstA * Ss + 8 * q];
        float* rowB = &state_out[dstB * Ss + 8 * q];
        atomicAdd((float4*)&rowA[0], make_float4(vA[0], vA[1], vA[2], vA[3]));
        atomicAdd((float4*)&rowA[4], make_float4(vA[4], vA[5], vA[6], vA[7]));
        atomicAdd((float4*)&rowB[0], make_float4(vB[0], vB[1], vB[2], vB[3]));
        atomicAdd((float4*)&rowB[4], make_float4(vB[4], vB[5], vB[6], vB[7]));
    }
}

// ---------------------------------------------------------------------------
__global__ void graphsum_kernel(int inb, const int* __restrict__ ngi) {
    int t = blockIdx.x * blockDim.x + threadIdx.x;
    int total = Nn * (Ss / 4);
    if (t >= total) return;
    int n = t >> 3;
    int q = t & 7;
    const float4* s = reinterpret_cast<const float4*>(g_state[inb]);
    float4 v = s[t];
    int g = ngi[n];
    atomicAdd(reinterpret_cast<float4*>(&g_gs[g * Ss + 4 * q]), v);
}

// ---------------------------------------------------------------------------
__global__ void __launch_bounds__(128) readout_kernel(
    const float* __restrict__ Wo1, const float* __restrict__ bo1,
    const float* __restrict__ go, const float* __restrict__ beo,
    const float* __restrict__ Wo2, const float* __restrict__ bo2,
    float* __restrict__ out)
{
    __shared__ float sW[32 * 128];
    __shared__ float sb[128], sg[128], sbe[128];
    __shared__ float sW2[256];
    __shared__ float sb2[2];

    int tid = threadIdx.x;
    for (int i = tid; i < 32 * 128; i += 128) sW[i] = Wo1[i];
    sb[tid] = bo1[tid]; sg[tid] = go[tid]; sbe[tid] = beo[tid];
    sW2[tid] = Wo2[tid];
    sW2[tid + 128] = Wo2[tid + 128];
    if (tid < 2) sb2[tid] = bo2[tid];
    __syncthreads();

    int lane = tid & 31;
    int w = tid >> 5;
    int g = blockIdx.x * 4 + w;
    if (g >= Gg) return;

    float x = g_gs[g * Ss + lane];
    float4 a;
    a.x = sb[4 * lane]; a.y = sb[4 * lane + 1]; a.z = sb[4 * lane + 2]; a.w = sb[4 * lane + 3];
#pragma unroll
    for (int i = 0; i < 32; i++) {
        float xi = __shfl_sync(FULL, x, i);
        float4 wv = *(const float4*)&sW[i * 128 + 4 * lane];
        a.x += xi * wv.x; a.y += xi * wv.y; a.z += xi * wv.z; a.w += xi * wv.w;
    }
    float s = a.x + a.y + a.z + a.w;
    float s2 = a.x * a.x + a.y * a.y + a.z * a.z + a.w * a.w;
#pragma unroll
    for (int o = 16; o; o >>= 1) {
        s += __shfl_xor_sync(FULL, s, o);
        s2 += __shfl_xor_sync(FULL, s2, o);
    }
    float mean = s * (1.f / 128.f);
    float var = s2 * (1.f / 128.f) - mean * mean;
    float rstd = rsqrtf(var + LN_EPS);
    float h0 = lrelu((a.x - mean) * rstd * sg[4 * lane + 0] + sbe[4 * lane + 0]);
    float h1 = lrelu((a.y - mean) * rstd * sg[4 * lane + 1] + sbe[4 * lane + 1]);
    float h2 = lrelu((a.z - mean) * rstd * sg[4 * lane + 2] + sbe[4 * lane + 2]);
    float h3 = lrelu((a.w - mean) * rstd * sg[4 * lane + 3] + sbe[4 * lane + 3]);

    float p0 = h0 * sW2[(4 * lane + 0) * 2] + h1 * sW2[(4 * lane + 1) * 2]
             + h2 * sW2[(4 * lane + 2) * 2] + h3 * sW2[(4 * lane + 3) * 2];
    float p1 = h0 * sW2[(4 * lane + 0) * 2 + 1] + h1 * sW2[(4 * lane + 1) * 2 + 1]
             + h2 * sW2[(4 * lane + 2) * 2 + 1] + h3 * sW2[(4 * lane + 3) * 2 + 1];
#pragma unroll
    for (int o = 16; o; o >>= 1) {
        p0 += __shfl_xor_sync(FULL, p0, o);
        p1 += __shfl_xor_sync(FULL, p1, o);
    }
    if (lane == 0) {
        float mu = p0 + sb2[0];
        float v = p1 + sb2[1];
        float sp = (v > 0.f) ? v + log1pf(expf(-v)) : log1pf(expf(v));
        out[g * 2 + 0] = mu;
        out[g * 2 + 1] = sp;
    }
}

// ---------------------------------------------------------------------------
extern "C" void kernel_launch(void* const* d_in, const int* in_sizes, int n_in,
                              void* d_out, int out_size) {
    const int* nf = (const int*)d_in[0];
    const int* nt = (const int*)d_in[1];
    const float* ec = (const float*)d_in[2];
    const int* ngi = (const int*)d_in[3];
    const float* W1 = (const float*)d_in[6];
    const float* b1 = (const float*)d_in[7];
    const float* g1 = (const float*)d_in[8];
    const float* be1 = (const float*)d_in[9];
    const float* W2 = (const float*)d_in[10];
    const float* b2 = (const float*)d_in[11];
    const float* g2 = (const float*)d_in[12];
    const float* be2 = (const float*)d_in[13];
    const float* Wo1 = (const float*)d_in[14];
    const float* bo1 = (const float*)d_in[15];
    const float* go = (const float*)d_in[16];
    const float* beo = (const float*)d_in[17];
    const float* Wo2 = (const float*)d_in[18];
    const float* bo2 = (const float*)d_in[19];
    float* out = (float*)d_out;

    cudaFuncSetAttribute(edge_kernel, cudaFuncAttributeMaxDynamicSharedMemorySize, EDGE_DSMEM);

    zero_kernel<<<4096, 256>>>();

    int cur = 0;
    for (int r = 0; r < ROUNDS; r++) {
        node_gemm_kernel<<<1024, 192>>>(cur, W1, b1);   // also copies state cur -> cur^1
        edge_kernel<<<EDGE_GRID, 256, EDGE_DSMEM>>>(cur, nf, nt, ec,
                                                    W1, g1, be1, W2, b2, g2, be2);
        cur ^= 1;
    }

    graphsum_kernel<<<(Nn * 8 + 255) / 256, 256>>>(cur, ngi);
    readout_kernel<<<(Gg + 3) / 4, 128>>>(Wo1, bo1, go, beo, Wo2, bo2, out);
}

// round 12
// speedup vs baseline: 1.2551x; 1.1195x over previous
#include <cuda_runtime.h>
#include <cuda_bf16.h>
#include <math.h>
#include <stdint.h>

#define FULL 0xffffffffu
typedef unsigned long long u64;

constexpr int Nn = 100000;
constexpr int Ee = 1600000;
constexpr int Gg = 1000;
constexpr int Ss = 32;
constexpr int Hh = 128;
constexpr int ROUNDS = 5;
constexpr float NEG_SLOPE = 0.01f;
constexpr float LN_EPS = 1e-5f;

constexpr int APITCH = 272;
constexpr int AWARP = 16 * APITCH;
constexpr int EDGE_WARPS = 8;                       // 256-thread blocks
constexpr int OFF_B_H = EDGE_WARPS * 2 * AWARP;     // 69632
constexpr int OFF_B_L = OFF_B_H + 32 * APITCH;      // 78336
constexpr int EDGE_DSMEM = OFF_B_L + 32 * APITCH;   // 87040  (2 blocks/SM, 16 warps/SM)
constexpr int EDGE_GRID = 296;

// single state buffer (in-place accumulation; edge kernel never reads it)
__device__ float g_state[Nn * Ss];
__device__ float g_y[Nn * Hh];
__device__ float4 g_stats[Nn];
__device__ float g_gs[Gg * Ss];

__device__ __forceinline__ float lrelu(float v) { return v >= 0.f ? v : NEG_SLOPE * v; }

// ---- packed f32x2 helpers ----
__device__ __forceinline__ u64 pack2(float lo, float hi) {
    u64 r; asm("mov.b64 %0,{%1,%2};" : "=l"(r) : "f"(lo), "f"(hi)); return r;
}
__device__ __forceinline__ void unpack2(u64 v, float& lo, float& hi) {
    asm("mov.b64 {%0,%1},%2;" : "=f"(lo), "=f"(hi) : "l"(v));
}
__device__ __forceinline__ u64 fma2(u64 a, u64 b, u64 c) {
    u64 d; asm("fma.rn.f32x2 %0,%1,%2,%3;" : "=l"(d) : "l"(a), "l"(b), "l"(c)); return d;
}
__device__ __forceinline__ u64 add2(u64 a, u64 b) {
    u64 d; asm("add.rn.f32x2 %0,%1,%2;" : "=l"(d) : "l"(a), "l"(b)); return d;
}
__device__ __forceinline__ u64 mul2(u64 a, u64 b) {
    u64 d; asm("mul.rn.f32x2 %0,%1,%2;" : "=l"(d) : "l"(a), "l"(b)); return d;
}

__device__ __forceinline__ uint32_t smem_u32(const void* p) {
    uint32_t a;
    asm("{ .reg .u64 t; cvta.to.shared.u64 t, %1; cvt.u32.u64 %0, t; }" : "=r"(a) : "l"(p));
    return a;
}

__device__ __forceinline__ void ldsm4(uint32_t r[4], uint32_t addr) {
    asm volatile("ldmatrix.sync.aligned.m8n8.x4.shared.b16 {%0,%1,%2,%3}, [%4];"
                 : "=r"(r[0]), "=r"(r[1]), "=r"(r[2]), "=r"(r[3]) : "r"(addr));
}

__device__ __forceinline__ void mma16816(float acc[4], const uint32_t a[4],
                                         uint32_t b0, uint32_t b1) {
    asm volatile(
        "mma.sync.aligned.m16n8k16.row.col.f32.bf16.bf16.f32 "
        "{%0,%1,%2,%3}, {%4,%5,%6,%7}, {%8,%9}, {%0,%1,%2,%3};"
        : "+f"(acc[0]), "+f"(acc[1]), "+f"(acc[2]), "+f"(acc[3])
        : "r"(a[0]), "r"(a[1]), "r"(a[2]), "r"(a[3]), "r"(b0), "r"(b1));
}

// ---------------------------------------------------------------------------
__global__ void zero_kernel() {
    int i = blockIdx.x * blockDim.x + threadIdx.x;
    int stride = gridDim.x * blockDim.x;
    for (int k = i; k < Nn * Ss; k += stride) g_state[k] = 0.f;
    for (int k = i; k < Gg * Ss; k += stride) g_gs[k] = 0.f;
}

// ---------------------------------------------------------------------------
// y = state @ W1[:32] + b1 ; stats (Sy,Qy,P).  4 nodes/warp. (no copy: in-place)
__global__ void __launch_bounds__(192) node_gemm_kernel(
    const float* __restrict__ W1, const float* __restrict__ b1)
{
    __shared__ float sW1[32 * 128];
    __shared__ float sb1[128];
    const float* __restrict__ state_in = g_state;

    int tid = threadIdx.x;
    for (int i = tid; i < 32 * 128; i += 192) sW1[i] = W1[i];
    if (tid < 128) sb1[tid] = b1[tid];
    __syncthreads();

    int lane = tid & 31;
    int w = tid >> 5;
    int warp_global = blockIdx.x * 6 + w;
    int nwarps = gridDim.x * 6;
    int ngroups = Nn / 4;

    float4 b1v = *(const float4*)&sb1[4 * lane];
    float4 w32v = *(const float4*)&W1[32 * 128 + 4 * lane];

    for (int g = warp_global; g < ngroups; g += nwarps) {
        int nbase = g * 4;
        float x0 = state_in[(nbase + 0) * Ss + lane];
        float x1 = state_in[(nbase + 1) * Ss + lane];
        float x2 = state_in[(nbase + 2) * Ss + lane];
        float x3 = state_in[(nbase + 3) * Ss + lane];

        float4 a0 = b1v, a1 = b1v, a2 = b1v, a3 = b1v;
#pragma unroll
        for (int i = 0; i < 32; i++) {
            float4 wv = *(const float4*)&sW1[i * 128 + 4 * lane];
            float s0 = __shfl_sync(FULL, x0, i);
            float s1 = __shfl_sync(FULL, x1, i);
            float s2 = __shfl_sync(FULL, x2, i);
            float s3 = __shfl_sync(FULL, x3, i);
            a0.x += s0 * wv.x; a0.y += s0 * wv.y; a0.z += s0 * wv.z; a0.w += s0 * wv.w;
            a1.x += s1 * wv.x; a1.y += s1 * wv.y; a1.z += s1 * wv.z; a1.w += s1 * wv.w;
            a2.x += s2 * wv.x; a2.y += s2 * wv.y; a2.z += s2 * wv.z; a2.w += s2 * wv.w;
            a3.x += s3 * wv.x; a3.y += s3 * wv.y; a3.z += s3 * wv.z; a3.w += s3 * wv.w;
        }
        *(float4*)&g_y[(nbase + 0) * Hh + 4 * lane] = a0;
        *(float4*)&g_y[(nbase + 1) * Hh + 4 * lane] = a1;
        *(float4*)&g_y[(nbase + 2) * Hh + 4 * lane] = a2;
        *(float4*)&g_y[(nbase + 3) * Hh + 4 * lane] = a3;

#pragma unroll
        for (int e = 0; e < 4; e++) {
            float4 a = (e == 0) ? a0 : (e == 1) ? a1 : (e == 2) ? a2 : a3;
            float s = a.x + a.y + a.z + a.w;
            float q = a.x * a.x + a.y * a.y + a.z * a.z + a.w * a.w;
            float p = a.x * w32v.x + a.y * w32v.y + a.z * w32v.z + a.w * w32v.w;
#pragma unroll
            for (int o = 16; o; o >>= 1) {
                s += __shfl_xor_sync(FULL, s, o);
                q += __shfl_xor_sync(FULL, q, o);
                p += __shfl_xor_sync(FULL, p, o);
            }
            if (lane == 0) g_stats[nbase + e] = make_float4(s, q, p, 0.f);
        }
    }
}

// ---------------------------------------------------------------------------
// Edge kernel (R9 champion body). ROUND0: state==0 => y==b1 uniform, no gather.
template <bool ROUND0>
__global__ void __launch_bounds__(256, 2) edge_kernel(
    const int* __restrict__ nf, const int* __restrict__ nt,
    const float* __restrict__ ec,
    const float* __restrict__ W1, const float* __restrict__ b1,
    const float* __restrict__ g1, const float* __restrict__ be1,
    const float* __restrict__ W2, const float* __restrict__ b2,
    const float* __restrict__ g2, const float* __restrict__ be2)
{
    extern __shared__ char dsm[];
    uint32_t sbase = smem_u32(dsm);

    int tid = threadIdx.x;
    int lane = tid & 31;
    int wid = tid >> 5;

    // B staging with column permutation pi(8t+2q+r) = 8q+2t+r
    for (int p = tid; p < 32 * 128; p += 256) {
        int n = p >> 7;
        int k = p & 127;
        int t = n >> 3, q0 = (n >> 1) & 3, r = n & 1;
        int pn = 8 * q0 + 2 * t + r;
        float wv = W2[k * 32 + pn];
        __nv_bfloat16 hb = __float2bfloat16(wv);
        __nv_bfloat16 lb = __float2bfloat16(wv - __bfloat162float(hb));
        *(__nv_bfloat16*)(dsm + OFF_B_H + n * APITCH + k * 2) = hb;
        *(__nv_bfloat16*)(dsm + OFF_B_L + n * APITCH + k * 2) = lb;
    }
    __syncthreads();

    float4 w32v = *(const float4*)&W1[32 * 128 + 4 * lane];
    float4 g1v  = *(const float4*)&g1[4 * lane];
    float4 be1v = *(const float4*)&be1[4 * lane];
    float4 b1v  = *(const float4*)&b1[4 * lane];

    // warp-wide scalars over w32 (and, for round 0, over b1)
    float Sw = w32v.x + w32v.y + w32v.z + w32v.w;
    float Qw = w32v.x * w32v.x + w32v.y * w32v.y + w32v.z * w32v.z + w32v.w * w32v.w;
    float Sb = b1v.x + b1v.y + b1v.z + b1v.w;
    float Qb = b1v.x * b1v.x + b1v.y * b1v.y + b1v.z * b1v.z + b1v.w * b1v.w;
    float Pb = b1v.x * w32v.x + b1v.y * w32v.y + b1v.z * w32v.z + b1v.w * w32v.w;
#pragma unroll
    for (int o = 16; o; o >>= 1) {
        Sw += __shfl_xor_sync(FULL, Sw, o);
        Qw += __shfl_xor_sync(FULL, Qw, o);
        Sb += __shfl_xor_sync(FULL, Sb, o);
        Qb += __shfl_xor_sync(FULL, Qb, o);
        Pb += __shfl_xor_sync(FULL, Pb, o);
    }

    int q = lane & 3;
    int rA = lane >> 2;
    int rB = rA + 8;

    u64 b2p[4], g2p[4], be2p[4];
#pragma unroll
    for (int t = 0; t < 4; t++) {
        int c = 8 * q + 2 * t;
        b2p[t]  = pack2(b2[c],  b2[c + 1]);
        g2p[t]  = pack2(g2[c],  g2[c + 1]);
        be2p[t] = pack2(be2[c], be2[c + 1]);
    }
    const u64 C001 = pack2(NEG_SLOPE, NEG_SLOPE);

    char* aStoreH = dsm + wid * 2 * AWARP + lane * 8;
    char* aStoreL = aStoreH + AWARP;

    int aRow = lane & 15;
    int aColB = ((lane >> 4) & 1) * 16;
    uint32_t ldAH = sbase + wid * 2 * AWARP + aRow * APITCH + aColB;
    uint32_t ldAL = ldAH + AWARP;

    int bRow = ((lane >> 4) & 1) * 8 + (lane & 7);
    int bKB = ((lane >> 3) & 1) * 16;
    uint32_t ldBH01 = sbase + OFF_B_H + bRow * APITCH + bKB;
    uint32_t ldBH23 = ldBH01 + 16 * APITCH;
    uint32_t ldBL01 = sbase + OFF_B_L + bRow * APITCH + bKB;
    uint32_t ldBL23 = ldBL01 + 16 * APITCH;

    const float4* __restrict__ yv = (const float4*)g_y;
    float* __restrict__ state_out = g_state;

    int ngroups = Ee / 16;
    int wg = blockIdx.x * EDGE_WARPS + wid;
    int nw = gridDim.x * EDGE_WARPS;

    for (int g = wg; g < ngroups; g += nw) {
        int base = g * 16;

        // ---- gather + stats-based LN1 + bf16 split + stage ----
#pragma unroll
        for (int j = 0; j < 4; j++) {
            float4 C = *(const float4*)&ec[base + 4 * j];
            float cs[4] = {C.x, C.y, C.z, C.w};
            int srcs[4];
            if constexpr (!ROUND0) {
                int4 NF = *(const int4*)&nf[base + 4 * j];
                srcs[0] = NF.x; srcs[1] = NF.y; srcs[2] = NF.z; srcs[3] = NF.w;
            }
#pragma unroll
            for (int e = 0; e < 4; e++) {
                float c = cs[e];
                float4 a;
                float s, qq;
                if constexpr (ROUND0) {
                    a = b1v;                          // y == b1 (state == 0)
                    s = fmaf(c, Sw, Sb);
                    qq = fmaf(c * c, Qw, fmaf(2.f * c, Pb, Qb));
                } else {
                    int src = srcs[e];
                    float4 st = g_stats[src];
                    a = yv[src * (Hh / 4) + lane];
                    s = fmaf(c, Sw, st.x);
                    qq = fmaf(c * c, Qw, fmaf(2.f * c, st.z, st.y));
                }
                a.x = fmaf(c, w32v.x, a.x);
                a.y = fmaf(c, w32v.y, a.y);
                a.z = fmaf(c, w32v.z, a.z);
                a.w = fmaf(c, w32v.w, a.w);

                float mean = s * (1.f / 128.f);
                float var = qq * (1.f / 128.f) - mean * mean;
                float rstd = rsqrtf(var + LN_EPS);

                float4 hv;
                hv.x = lrelu(fmaf((a.x - mean) * rstd, g1v.x, be1v.x));
                hv.y = lrelu(fmaf((a.y - mean) * rstd, g1v.y, be1v.y));
                hv.z = lrelu(fmaf((a.z - mean) * rstd, g1v.z, be1v.z));
                hv.w = lrelu(fmaf((a.w - mean) * rstd, g1v.w, be1v.w));

                __nv_bfloat162 h01 = __float22bfloat162_rn(make_float2(hv.x, hv.y));
                __nv_bfloat162 h23 = __float22bfloat162_rn(make_float2(hv.z, hv.w));
                float2 f01 = __bfloat1622float2(h01);
                float2 f23 = __bfloat1622float2(h23);
                __nv_bfloat162 l01 = __float22bfloat162_rn(make_float2(hv.x - f01.x, hv.y - f01.y));
                __nv_bfloat162 l23 = __float22bfloat162_rn(make_float2(hv.z - f23.x, hv.w - f23.y));
                u64 packh = (u64)(*(uint32_t*)&h01) | ((u64)(*(uint32_t*)&h23) << 32);
                u64 packl = (u64)(*(uint32_t*)&l01) | ((u64)(*(uint32_t*)&l23) << 32);
                int row = 4 * j + e;
                *(u64*)(aStoreH + row * APITCH) = packh;
                *(u64*)(aStoreL + row * APITCH) = packl;
            }
        }
        __syncwarp();

        // hoist destination loads: latency hides behind the MMA section
        int dstA = __ldg(&nt[base + rA]);
        int dstB = __ldg(&nt[base + rB]);

        // ---- MMA: D = Ah@Bh + Ah@Bl + Al@Bh ----
        float acc[4][4];
#pragma unroll
        for (int t = 0; t < 4; t++)
#pragma unroll
            for (int j2 = 0; j2 < 4; j2++) acc[t][j2] = 0.f;

#pragma unroll
        for (int k = 0; k < 8; k++) {
            uint32_t ah[4], al[4], bh01[4], bh23[4], bl01[4], bl23[4];
            ldsm4(ah, ldAH + k * 32);
            ldsm4(al, ldAL + k * 32);
            ldsm4(bh01, ldBH01 + k * 32);
            ldsm4(bh23, ldBH23 + k * 32);
            ldsm4(bl01, ldBL01 + k * 32);
            ldsm4(bl23, ldBL23 + k * 32);

            mma16816(acc[0], ah, bh01[0], bh01[1]);
            mma16816(acc[1], ah, bh01[2], bh01[3]);
            mma16816(acc[2], ah, bh23[0], bh23[1]);
            mma16816(acc[3], ah, bh23[2], bh23[3]);

            mma16816(acc[0], ah, bl01[0], bl01[1]);
            mma16816(acc[1], ah, bl01[2], bl01[3]);
            mma16816(acc[2], ah, bl23[0], bl23[1]);
            mma16816(acc[3], ah, bl23[2], bl23[3]);

            mma16816(acc[0], al, bh01[0], bh01[1]);
            mma16816(acc[1], al, bh01[2], bh01[3]);
            mma16816(acc[2], al, bh23[0], bh23[1]);
            mma16816(acc[3], al, bh23[2], bh23[3]);
        }
        __syncwarp();

        // ---- epilogue: packed bias + LN2 (quad reduction) + float4 scatter ----
        u64 mA[4], mB[4];
#pragma unroll
        for (int t = 0; t < 4; t++) {
            mA[t] = add2(pack2(acc[t][0], acc[t][1]), b2p[t]);
            mB[t] = add2(pack2(acc[t][2], acc[t][3]), b2p[t]);
        }
        u64 sA2 = add2(add2(mA[0], mA[1]), add2(mA[2], mA[3]));
        u64 sB2 = add2(add2(mB[0], mB[1]), add2(mB[2], mB[3]));
        u64 qA2 = fma2(mA[0], mA[0], fma2(mA[1], mA[1], fma2(mA[2], mA[2], mul2(mA[3], mA[3]))));
        u64 qB2 = fma2(mB[0], mB[0], fma2(mB[1], mB[1], fma2(mB[2], mB[2], mul2(mB[3], mB[3]))));
        float t0, t1;
        unpack2(sA2, t0, t1); float sA = t0 + t1;
        unpack2(qA2, t0, t1); float qA = t0 + t1;
        unpack2(sB2, t0, t1); float sB = t0 + t1;
        unpack2(qB2, t0, t1); float qB = t0 + t1;
#pragma unroll
        for (int o = 2; o; o >>= 1) {
            sA += __shfl_xor_sync(FULL, sA, o);
            qA += __shfl_xor_sync(FULL, qA, o);
            sB += __shfl_xor_sync(FULL, sB, o);
            qB += __shfl_xor_sync(FULL, qB, o);
        }
        float meanA = sA * (1.f / 32.f);
        float rstdA = rsqrtf(qA * (1.f / 32.f) - meanA * meanA + LN_EPS);
        float meanB = sB * (1.f / 32.f);
        float rstdB = rsqrtf(qB * (1.f / 32.f) - meanB * meanB + LN_EPS);

        u64 rA2p = pack2(rstdA, rstdA), nmA2 = pack2(-meanA, -meanA);
        u64 rB2p = pack2(rstdB, rstdB), nmB2 = pack2(-meanB, -meanB);

        float vA[8], vB[8];
#pragma unroll
        for (int t = 0; t < 4; t++) {
            u64 agA = mul2(rA2p, g2p[t]);
            u64 offA = fma2(nmA2, agA, be2p[t]);
            u64 hA = fma2(mA[t], agA, offA);
            u64 pA = mul2(hA, C001);
            float h0, h1, p0, p1;
            unpack2(hA, h0, h1); unpack2(pA, p0, p1);
            vA[2 * t] = fmaxf(h0, p0); vA[2 * t + 1] = fmaxf(h1, p1);

            u64 agB = mul2(rB2p, g2p[t]);
            u64 offB = fma2(nmB2, agB, be2p[t]);
            u64 hB = fma2(mB[t], agB, offB);
            u64 pB = mul2(hB, C001);
            unpack2(hB, h0, h1); unpack2(pB, p0, p1);
            vB[2 * t] = fmaxf(h0, p0); vB[2 * t + 1] = fmaxf(h1, p1);
        }

        float* rowA = &state_out[dstA * Ss + 8 * q];
        float* rowB = &state_out[dstB * Ss + 8 * q];
        atomicAdd((float4*)&rowA[0], make_float4(vA[0], vA[1], vA[2], vA[3]));
        atomicAdd((float4*)&rowA[4], make_float4(vA[4], vA[5], vA[6], vA[7]));
        atomicAdd((float4*)&rowB[0], make_float4(vB[0], vB[1], vB[2], vB[3]));
        atomicAdd((float4*)&rowB[4], make_float4(vB[4], vB[5], vB[6], vB[7]));
    }
}

// ---------------------------------------------------------------------------
__global__ void graphsum_kernel(const int* __restrict__ ngi) {
    int t = blockIdx.x * blockDim.x + threadIdx.x;
    int total = Nn * (Ss / 4);
    if (t >= total) return;
    int n = t >> 3;
    int q = t & 7;
    const float4* s = reinterpret_cast<const float4*>(g_state);
    float4 v = s[t];
    int g = ngi[n];
    atomicAdd(reinterpret_cast<float4*>(&g_gs[g * Ss + 4 * q]), v);
}

// ---------------------------------------------------------------------------
__global__ void __launch_bounds__(128) readout_kernel(
    const float* __restrict__ Wo1, const float* __restrict__ bo1,
    const float* __restrict__ go, const float* __restrict__ beo,
    const float* __restrict__ Wo2, const float* __restrict__ bo2,
    float* __restrict__ out)
{
    __shared__ float sW[32 * 128];
    __shared__ float sb[128], sg[128], sbe[128];
    __shared__ float sW2[256];
    __shared__ float sb2[2];

    int tid = threadIdx.x;
    for (int i = tid; i < 32 * 128; i += 128) sW[i] = Wo1[i];
    sb[tid] = bo1[tid]; sg[tid] = go[tid]; sbe[tid] = beo[tid];
    sW2[tid] = Wo2[tid];
    sW2[tid + 128] = Wo2[tid + 128];
    if (tid < 2) sb2[tid] = bo2[tid];
    __syncthreads();

    int lane = tid & 31;
    int w = tid >> 5;
    int g = blockIdx.x * 4 + w;
    if (g >= Gg) return;

    float x = g_gs[g * Ss + lane];
    float4 a;
    a.x = sb[4 * lane]; a.y = sb[4 * lane + 1]; a.z = sb[4 * lane + 2]; a.w = sb[4 * lane + 3];
#pragma unroll
    for (int i = 0; i < 32; i++) {
        float xi = __shfl_sync(FULL, x, i);
        float4 wv = *(const float4*)&sW[i * 128 + 4 * lane];
        a.x += xi * wv.x; a.y += xi * wv.y; a.z += xi * wv.z; a.w += xi * wv.w;
    }
    float s = a.x + a.y + a.z + a.w;
    float s2 = a.x * a.x + a.y * a.y + a.z * a.z + a.w * a.w;
#pragma unroll
    for (int o = 16; o; o >>= 1) {
        s += __shfl_xor_sync(FULL, s, o);
        s2 += __shfl_xor_sync(FULL, s2, o);
    }
    float mean = s * (1.f / 128.f);
    float var = s2 * (1.f / 128.f) - mean * mean;
    float rstd = rsqrtf(var + LN_EPS);
    float h0 = lrelu((a.x - mean) * rstd * sg[4 * lane + 0] + sbe[4 * lane + 0]);
    float h1 = lrelu((a.y - mean) * rstd * sg[4 * lane + 1] + sbe[4 * lane + 1]);
    float h2 = lrelu((a.z - mean) * rstd * sg[4 * lane + 2] + sbe[4 * lane + 2]);
    float h3 = lrelu((a.w - mean) * rstd * sg[4 * lane + 3] + sbe[4 * lane + 3]);

    float p0 = h0 * sW2[(4 * lane + 0) * 2] + h1 * sW2[(4 * lane + 1) * 2]
             + h2 * sW2[(4 * lane + 2) * 2] + h3 * sW2[(4 * lane + 3) * 2];
    float p1 = h0 * sW2[(4 * lane + 0) * 2 + 1] + h1 * sW2[(4 * lane + 1) * 2 + 1]
             + h2 * sW2[(4 * lane + 2) * 2 + 1] + h3 * sW2[(4 * lane + 3) * 2 + 1];
#pragma unroll
    for (int o = 16; o; o >>= 1) {
        p0 += __shfl_xor_sync(FULL, p0, o);
        p1 += __shfl_xor_sync(FULL, p1, o);
    }
    if (lane == 0) {
        float mu = p0 + sb2[0];
        float v = p1 + sb2[1];
        float sp = (v > 0.f) ? v + log1pf(expf(-v)) : log1pf(expf(v));
        out[g * 2 + 0] = mu;
        out[g * 2 + 1] = sp;
    }
}

// ---------------------------------------------------------------------------
extern "C" void kernel_launch(void* const* d_in, const int* in_sizes, int n_in,
                              void* d_out, int out_size) {
    const int* nf = (const int*)d_in[0];
    const int* nt = (const int*)d_in[1];
    const float* ec = (const float*)d_in[2];
    const int* ngi = (const int*)d_in[3];
    const float* W1 = (const float*)d_in[6];
    const float* b1 = (const float*)d_in[7];
    const float* g1 = (const float*)d_in[8];
    const float* be1 = (const float*)d_in[9];
    const float* W2 = (const float*)d_in[10];
    const float* b2 = (const float*)d_in[11];
    const float* g2 = (const float*)d_in[12];
    const float* be2 = (const float*)d_in[13];
    const float* Wo1 = (const float*)d_in[14];
    const float* bo1 = (const float*)d_in[15];
    const float* go = (const float*)d_in[16];
    const float* beo = (const float*)d_in[17];
    const float* Wo2 = (const float*)d_in[18];
    const float* bo2 = (const float*)d_in[19];
    float* out = (float*)d_out;

    cudaFuncSetAttribute(edge_kernel<true>, cudaFuncAttributeMaxDynamicSharedMemorySize, EDGE_DSMEM);
    cudaFuncSetAttribute(edge_kernel<false>, cudaFuncAttributeMaxDynamicSharedMemorySize, EDGE_DSMEM);

    zero_kernel<<<4096, 256>>>();

    // round 0: state == 0 -> y == b1 uniform; skip node_gemm, no gather
    edge_kernel<true><<<EDGE_GRID, 256, EDGE_DSMEM>>>(nf, nt, ec,
                                                      W1, b1, g1, be1, W2, b2, g2, be2);
    // rounds 1..4: node_gemm (in-place read) + edge (in-place accumulate)
    for (int r = 1; r < ROUNDS; r++) {
        node_gemm_kernel<<<1024, 192>>>(W1, b1);
        edge_kernel<false><<<EDGE_GRID, 256, EDGE_DSMEM>>>(nf, nt, ec,
                                                           W1, b1, g1, be1, W2, b2, g2, be2);
    }

    graphsum_kernel<<<(Nn * 8 + 255) / 256, 256>>>(ngi);
    readout_kernel<<<(Gg + 3) / 4, 128>>>(Wo1, bo1, go, beo, Wo2, bo2, out);
}

// round 13
// speedup vs baseline: 1.5462x; 1.2319x over previous
#include <cuda_runtime.h>
#include <cuda_fp16.h>
#include <math.h>
#include <stdint.h>

#define FULL 0xffffffffu
typedef unsigned long long u64;

constexpr int Nn = 100000;
constexpr int Ee = 1600000;
constexpr int Gg = 1000;
constexpr int Ss = 32;
constexpr int Hh = 128;
constexpr int ROUNDS = 5;
constexpr float NEG_SLOPE = 0.01f;
constexpr float LN_EPS = 1e-5f;

constexpr int APITCH = 272;
constexpr int AWARP = 16 * APITCH;
constexpr int EDGE_WARPS = 8;                       // 256-thread blocks
// per warp: A tile0 + A tile1 (fp16, single precision-level) = 2 * AWARP
constexpr int OFF_B_H = EDGE_WARPS * 2 * AWARP;     // 69632
constexpr int OFF_B_L = OFF_B_H + 32 * APITCH;      // 78336
constexpr int EDGE_DSMEM = OFF_B_L + 32 * APITCH;   // 87040  (2 blocks/SM, 16 warps/SM)
constexpr int EDGE_GRID = 296;

// single state buffer (in-place accumulation; edge kernel never reads it)
__device__ float g_state[Nn * Ss];
__device__ float g_y[Nn * Hh];
__device__ float4 g_stats[Nn];
__device__ float g_gs[Gg * Ss];

__device__ __forceinline__ float lrelu(float v) { return v >= 0.f ? v : NEG_SLOPE * v; }

// ---- packed f32x2 helpers ----
__device__ __forceinline__ u64 pack2(float lo, float hi) {
    u64 r; asm("mov.b64 %0,{%1,%2};" : "=l"(r) : "f"(lo), "f"(hi)); return r;
}
__device__ __forceinline__ void unpack2(u64 v, float& lo, float& hi) {
    asm("mov.b64 {%0,%1},%2;" : "=f"(lo), "=f"(hi) : "l"(v));
}
__device__ __forceinline__ u64 fma2(u64 a, u64 b, u64 c) {
    u64 d; asm("fma.rn.f32x2 %0,%1,%2,%3;" : "=l"(d) : "l"(a), "l"(b), "l"(c)); return d;
}
__device__ __forceinline__ u64 add2(u64 a, u64 b) {
    u64 d; asm("add.rn.f32x2 %0,%1,%2;" : "=l"(d) : "l"(a), "l"(b)); return d;
}
__device__ __forceinline__ u64 mul2(u64 a, u64 b) {
    u64 d; asm("mul.rn.f32x2 %0,%1,%2;" : "=l"(d) : "l"(a), "l"(b)); return d;
}

__device__ __forceinline__ uint32_t smem_u32(const void* p) {
    uint32_t a;
    asm("{ .reg .u64 t; cvta.to.shared.u64 t, %1; cvt.u32.u64 %0, t; }" : "=r"(a) : "l"(p));
    return a;
}

__device__ __forceinline__ void ldsm4(uint32_t r[4], uint32_t addr) {
    asm volatile("ldmatrix.sync.aligned.m8n8.x4.shared.b16 {%0,%1,%2,%3}, [%4];"
                 : "=r"(r[0]), "=r"(r[1]), "=r"(r[2]), "=r"(r[3]) : "r"(addr));
}

__device__ __forceinline__ void mma16816h(float acc[4], const uint32_t a[4],
                                          uint32_t b0, uint32_t b1) {
    asm volatile(
        "mma.sync.aligned.m16n8k16.row.col.f32.f16.f16.f32 "
        "{%0,%1,%2,%3}, {%4,%5,%6,%7}, {%8,%9}, {%0,%1,%2,%3};"
        : "+f"(acc[0]), "+f"(acc[1]), "+f"(acc[2]), "+f"(acc[3])
        : "r"(a[0]), "r"(a[1]), "r"(a[2]), "r"(a[3]), "r"(b0), "r"(b1));
}

// ---------------------------------------------------------------------------
__global__ void zero_kernel() {
    int i = blockIdx.x * blockDim.x + threadIdx.x;
    int stride = gridDim.x * blockDim.x;
    for (int k = i; k < Nn * Ss; k += stride) g_state[k] = 0.f;
    for (int k = i; k < Gg * Ss; k += stride) g_gs[k] = 0.f;
}

// ---------------------------------------------------------------------------
// y = state @ W1[:32] + b1 ; stats (Sy,Qy,P).  4 nodes/warp. (in-place read)
__global__ void __launch_bounds__(192) node_gemm_kernel(
    const float* __restrict__ W1, const float* __restrict__ b1)
{
    __shared__ float sW1[32 * 128];
    __shared__ float sb1[128];
    const float* __restrict__ state_in = g_state;

    int tid = threadIdx.x;
    for (int i = tid; i < 32 * 128; i += 192) sW1[i] = W1[i];
    if (tid < 128) sb1[tid] = b1[tid];
    __syncthreads();

    int lane = tid & 31;
    int w = tid >> 5;
    int warp_global = blockIdx.x * 6 + w;
    int nwarps = gridDim.x * 6;
    int ngroups = Nn / 4;

    float4 b1v = *(const float4*)&sb1[4 * lane];
    float4 w32v = *(const float4*)&W1[32 * 128 + 4 * lane];

    for (int g = warp_global; g < ngroups; g += nwarps) {
        int nbase = g * 4;
        float x0 = state_in[(nbase + 0) * Ss + lane];
        float x1 = state_in[(nbase + 1) * Ss + lane];
        float x2 = state_in[(nbase + 2) * Ss + lane];
        float x3 = state_in[(nbase + 3) * Ss + lane];

        float4 a0 = b1v, a1 = b1v, a2 = b1v, a3 = b1v;
#pragma unroll
        for (int i = 0; i < 32; i++) {
            float4 wv = *(const float4*)&sW1[i * 128 + 4 * lane];
            float s0 = __shfl_sync(FULL, x0, i);
            float s1 = __shfl_sync(FULL, x1, i);
            float s2 = __shfl_sync(FULL, x2, i);
            float s3 = __shfl_sync(FULL, x3, i);
            a0.x += s0 * wv.x; a0.y += s0 * wv.y; a0.z += s0 * wv.z; a0.w += s0 * wv.w;
            a1.x += s1 * wv.x; a1.y += s1 * wv.y; a1.z += s1 * wv.z; a1.w += s1 * wv.w;
            a2.x += s2 * wv.x; a2.y += s2 * wv.y; a2.z += s2 * wv.z; a2.w += s2 * wv.w;
            a3.x += s3 * wv.x; a3.y += s3 * wv.y; a3.z += s3 * wv.z; a3.w += s3 * wv.w;
        }
        *(float4*)&g_y[(nbase + 0) * Hh + 4 * lane] = a0;
        *(float4*)&g_y[(nbase + 1) * Hh + 4 * lane] = a1;
        *(float4*)&g_y[(nbase + 2) * Hh + 4 * lane] = a2;
        *(float4*)&g_y[(nbase + 3) * Hh + 4 * lane] = a3;

#pragma unroll
        for (int e = 0; e < 4; e++) {
            float4 a = (e == 0) ? a0 : (e == 1) ? a1 : (e == 2) ? a2 : a3;
            float s = a.x + a.y + a.z + a.w;
            float q = a.x * a.x + a.y * a.y + a.z * a.z + a.w * a.w;
            float p = a.x * w32v.x + a.y * w32v.y + a.z * w32v.z + a.w * w32v.w;
#pragma unroll
            for (int o = 16; o; o >>= 1) {
                s += __shfl_xor_sync(FULL, s, o);
                q += __shfl_xor_sync(FULL, q, o);
                p += __shfl_xor_sync(FULL, p, o);
            }
            if (lane == 0) g_stats[nbase + e] = make_float4(s, q, p, 0.f);
        }
    }
}

// ---------------------------------------------------------------------------
// per-tile epilogue: packed bias + LN2 (quad reduce) + 4 float4 atomics
__device__ __forceinline__ void epilogue_tile(
    const float acc[4][4], int dstA, int dstB, int q,
    const u64 b2p[4], const u64 g2p[4], const u64 be2p[4], u64 C001,
    float* __restrict__ state_out)
{
    u64 mA[4], mB[4];
#pragma unroll
    for (int t = 0; t < 4; t++) {
        mA[t] = add2(pack2(acc[t][0], acc[t][1]), b2p[t]);
        mB[t] = add2(pack2(acc[t][2], acc[t][3]), b2p[t]);
    }
    u64 sA2 = add2(add2(mA[0], mA[1]), add2(mA[2], mA[3]));
    u64 sB2 = add2(add2(mB[0], mB[1]), add2(mB[2], mB[3]));
    u64 qA2 = fma2(mA[0], mA[0], fma2(mA[1], mA[1], fma2(mA[2], mA[2], mul2(mA[3], mA[3]))));
    u64 qB2 = fma2(mB[0], mB[0], fma2(mB[1], mB[1], fma2(mB[2], mB[2], mul2(mB[3], mB[3]))));
    float t0, t1;
    unpack2(sA2, t0, t1); float sA = t0 + t1;
    unpack2(qA2, t0, t1); float qA = t0 + t1;
    unpack2(sB2, t0, t1); float sB = t0 + t1;
    unpack2(qB2, t0, t1); float qB = t0 + t1;
#pragma unroll
    for (int o = 2; o; o >>= 1) {
        sA += __shfl_xor_sync(FULL, sA, o);
        qA += __shfl_xor_sync(FULL, qA, o);
        sB += __shfl_xor_sync(FULL, sB, o);
        qB += __shfl_xor_sync(FULL, qB, o);
    }
    float meanA = sA * (1.f / 32.f);
    float rstdA = rsqrtf(qA * (1.f / 32.f) - meanA * meanA + LN_EPS);
    float meanB = sB * (1.f / 32.f);
    float rstdB = rsqrtf(qB * (1.f / 32.f) - meanB * meanB + LN_EPS);

    u64 rA2p = pack2(rstdA, rstdA), nmA2 = pack2(-meanA, -meanA);
    u64 rB2p = pack2(rstdB, rstdB), nmB2 = pack2(-meanB, -meanB);

    float vA[8], vB[8];
#pragma unroll
    for (int t = 0; t < 4; t++) {
        u64 agA = mul2(rA2p, g2p[t]);
        u64 offA = fma2(nmA2, agA, be2p[t]);
        u64 hA = fma2(mA[t], agA, offA);
        u64 pA = mul2(hA, C001);
        float h0, h1, p0, p1;
        unpack2(hA, h0, h1); unpack2(pA, p0, p1);
        vA[2 * t] = fmaxf(h0, p0); vA[2 * t + 1] = fmaxf(h1, p1);

        u64 agB = mul2(rB2p, g2p[t]);
        u64 offB = fma2(nmB2, agB, be2p[t]);
        u64 hB = fma2(mB[t], agB, offB);
        u64 pB = mul2(hB, C001);
        unpack2(hB, h0, h1); unpack2(pB, p0, p1);
        vB[2 * t] = fmaxf(h0, p0); vB[2 * t + 1] = fmaxf(h1, p1);
    }

    float* rowA = &state_out[dstA * Ss + 8 * q];
    float* rowB = &state_out[dstB * Ss + 8 * q];
    atomicAdd((float4*)&rowA[0], make_float4(vA[0], vA[1], vA[2], vA[3]));
    atomicAdd((float4*)&rowA[4], make_float4(vA[4], vA[5], vA[6], vA[7]));
    atomicAdd((float4*)&rowB[0], make_float4(vB[0], vB[1], vB[2], vB[3]));
    atomicAdd((float4*)&rowB[4], make_float4(vB[4], vB[5], vB[6], vB[7]));
}

// ---------------------------------------------------------------------------
// Edge kernel: fp16 (A single-precision tile, B hi/lo split), 32-edge groups
// with B-fragment reuse across the two 16-row A tiles. Same 87KB / 2 blocks /
// 16 warps per SM operating point as the R9/R12 champion.
template <bool ROUND0>
__global__ void __launch_bounds__(256, 2) edge_kernel(
    const int* __restrict__ nf, const int* __restrict__ nt,
    const float* __restrict__ ec,
    const float* __restrict__ W1, const float* __restrict__ b1,
    const float* __restrict__ g1, const float* __restrict__ be1,
    const float* __restrict__ W2, const float* __restrict__ b2,
    const float* __restrict__ g2, const float* __restrict__ be2)
{
    extern __shared__ char dsm[];
    uint32_t sbase = smem_u32(dsm);

    int tid = threadIdx.x;
    int lane = tid & 31;
    int wid = tid >> 5;

    // B staging (fp16 hi/lo) with column permutation pi(8t+2q+r) = 8q+2t+r
    for (int p = tid; p < 32 * 128; p += 256) {
        int n = p >> 7;
        int k = p & 127;
        int t = n >> 3, q0 = (n >> 1) & 3, r = n & 1;
        int pn = 8 * q0 + 2 * t + r;
        float wv = W2[k * 32 + pn];
        __half hb = __float2half_rn(wv);
        __half lb = __float2half_rn(wv - __half2float(hb));
        *(__half*)(dsm + OFF_B_H + n * APITCH + k * 2) = hb;
        *(__half*)(dsm + OFF_B_L + n * APITCH + k * 2) = lb;
    }
    __syncthreads();

    float4 w32v = *(const float4*)&W1[32 * 128 + 4 * lane];
    float4 g1v  = *(const float4*)&g1[4 * lane];
    float4 be1v = *(const float4*)&be1[4 * lane];
    float4 b1v  = *(const float4*)&b1[4 * lane];

    float Sw = w32v.x + w32v.y + w32v.z + w32v.w;
    float Qw = w32v.x * w32v.x + w32v.y * w32v.y + w32v.z * w32v.z + w32v.w * w32v.w;
    float Sb = b1v.x + b1v.y + b1v.z + b1v.w;
    float Qb = b1v.x * b1v.x + b1v.y * b1v.y + b1v.z * b1v.z + b1v.w * b1v.w;
    float Pb = b1v.x * w32v.x + b1v.y * w32v.y + b1v.z * w32v.z + b1v.w * w32v.w;
#pragma unroll
    for (int o = 16; o; o >>= 1) {
        Sw += __shfl_xor_sync(FULL, Sw, o);
        Qw += __shfl_xor_sync(FULL, Qw, o);
        Sb += __shfl_xor_sync(FULL, Sb, o);
        Qb += __shfl_xor_sync(FULL, Qb, o);
        Pb += __shfl_xor_sync(FULL, Pb, o);
    }

    int q = lane & 3;
    int rA = lane >> 2;
    int rB = rA + 8;

    u64 b2p[4], g2p[4], be2p[4];
#pragma unroll
    for (int t = 0; t < 4; t++) {
        int c = 8 * q + 2 * t;
        b2p[t]  = pack2(b2[c],  b2[c + 1]);
        g2p[t]  = pack2(g2[c],  g2[c + 1]);
        be2p[t] = pack2(be2[c], be2[c + 1]);
    }
    const u64 C001 = pack2(NEG_SLOPE, NEG_SLOPE);

    // staging: tile0 at wid*2*AWARP, tile1 at +AWARP
    char* aStore = dsm + wid * 2 * AWARP + lane * 8;

    int aRow = lane & 15;
    int aColB = ((lane >> 4) & 1) * 16;
    uint32_t ldA0 = sbase + wid * 2 * AWARP + aRow * APITCH + aColB;
    uint32_t ldA1 = ldA0 + AWARP;

    int bRow = ((lane >> 4) & 1) * 8 + (lane & 7);
    int bKB = ((lane >> 3) & 1) * 16;
    uint32_t ldBH01 = sbase + OFF_B_H + bRow * APITCH + bKB;
    uint32_t ldBH23 = ldBH01 + 16 * APITCH;
    uint32_t ldBL01 = sbase + OFF_B_L + bRow * APITCH + bKB;
    uint32_t ldBL23 = ldBL01 + 16 * APITCH;

    const float4* __restrict__ yv = (const float4*)g_y;
    float* __restrict__ state_out = g_state;

    int ngroups = Ee / 32;          // 50000
    int wg = blockIdx.x * EDGE_WARPS + wid;
    int nw = gridDim.x * EDGE_WARPS;

    for (int g = wg; g < ngroups; g += nw) {
        int base = g * 32;

        // ---- gather + stats-based LN1 + fp16 convert + stage (32 rows) ----
#pragma unroll
        for (int j = 0; j < 8; j++) {
            float4 C = *(const float4*)&ec[base + 4 * j];
            float cs[4] = {C.x, C.y, C.z, C.w};
            int srcs[4];
            if constexpr (!ROUND0) {
                int4 NF = *(const int4*)&nf[base + 4 * j];
                srcs[0] = NF.x; srcs[1] = NF.y; srcs[2] = NF.z; srcs[3] = NF.w;
            }
#pragma unroll
            for (int e = 0; e < 4; e++) {
                float c = cs[e];
                float4 a;
                float s, qq;
                if constexpr (ROUND0) {
                    a = b1v;                          // y == b1 (state == 0)
                    s = fmaf(c, Sw, Sb);
                    qq = fmaf(c * c, Qw, fmaf(2.f * c, Pb, Qb));
                } else {
                    int src = srcs[e];
                    float4 st = g_stats[src];
                    a = yv[src * (Hh / 4) + lane];
                    s = fmaf(c, Sw, st.x);
                    qq = fmaf(c * c, Qw, fmaf(2.f * c, st.z, st.y));
                }
                a.x = fmaf(c, w32v.x, a.x);
                a.y = fmaf(c, w32v.y, a.y);
                a.z = fmaf(c, w32v.z, a.z);
                a.w = fmaf(c, w32v.w, a.w);

                float mean = s * (1.f / 128.f);
                float var = qq * (1.f / 128.f) - mean * mean;
                float rstd = rsqrtf(var + LN_EPS);

                float4 hv;
                hv.x = lrelu(fmaf((a.x - mean) * rstd, g1v.x, be1v.x));
                hv.y = lrelu(fmaf((a.y - mean) * rstd, g1v.y, be1v.y));
                hv.z = lrelu(fmaf((a.z - mean) * rstd, g1v.z, be1v.z));
                hv.w = lrelu(fmaf((a.w - mean) * rstd, g1v.w, be1v.w));

                __half2 h01 = __float22half2_rn(make_float2(hv.x, hv.y));
                __half2 h23 = __float22half2_rn(make_float2(hv.z, hv.w));
                u64 packh = (u64)(*(uint32_t*)&h01) | ((u64)(*(uint32_t*)&h23) << 32);
                int row = 4 * j + e;                 // 0..31
                char* dst = aStore + (row >> 4) * AWARP + (row & 15) * APITCH;
                *(u64*)dst = packh;
            }
        }
        __syncwarp();

        // hoist destination loads (latency hides behind MMA)
        int dstA0 = __ldg(&nt[base + rA]);
        int dstB0 = __ldg(&nt[base + rB]);
        int dstA1 = __ldg(&nt[base + 16 + rA]);
        int dstB1 = __ldg(&nt[base + 16 + rB]);

        // ---- MMA: D = A@Bh + A@Bl per tile; B fragments shared by both tiles
        float acc0[4][4], acc1[4][4];
#pragma unroll
        for (int t = 0; t < 4; t++)
#pragma unroll
            for (int j2 = 0; j2 < 4; j2++) { acc0[t][j2] = 0.f; acc1[t][j2] = 0.f; }

#pragma unroll
        for (int k = 0; k < 8; k++) {
            uint32_t bh01[4], bh23[4], bl01[4], bl23[4];
            ldsm4(bh01, ldBH01 + k * 32);
            ldsm4(bh23, ldBH23 + k * 32);
            ldsm4(bl01, ldBL01 + k * 32);
            ldsm4(bl23, ldBL23 + k * 32);

            uint32_t a0[4], a1[4];
            ldsm4(a0, ldA0 + k * 32);
            ldsm4(a1, ldA1 + k * 32);

            mma16816h(acc0[0], a0, bh01[0], bh01[1]);
            mma16816h(acc0[1], a0, bh01[2], bh01[3]);
            mma16816h(acc0[2], a0, bh23[0], bh23[1]);
            mma16816h(acc0[3], a0, bh23[2], bh23[3]);
            mma16816h(acc0[0], a0, bl01[0], bl01[1]);
            mma16816h(acc0[1], a0, bl01[2], bl01[3]);
            mma16816h(acc0[2], a0, bl23[0], bl23[1]);
            mma16816h(acc0[3], a0, bl23[2], bl23[3]);

            mma16816h(acc1[0], a1, bh01[0], bh01[1]);
            mma16816h(acc1[1], a1, bh01[2], bh01[3]);
            mma16816h(acc1[2], a1, bh23[0], bh23[1]);
            mma16816h(acc1[3], a1, bh23[2], bh23[3]);
            mma16816h(acc1[0], a1, bl01[0], bl01[1]);
            mma16816h(acc1[1], a1, bl01[2], bl01[3]);
            mma16816h(acc1[2], a1, bl23[0], bl23[1]);
            mma16816h(acc1[3], a1, bl23[2], bl23[3]);
        }
        __syncwarp();

        // ---- epilogues ----
        epilogue_tile(acc0, dstA0, dstB0, q, b2p, g2p, be2p, C001, state_out);
        epilogue_tile(acc1, dstA1, dstB1, q, b2p, g2p, be2p, C001, state_out);
    }
}

// ---------------------------------------------------------------------------
__global__ void graphsum_kernel(const int* __restrict__ ngi) {
    int t = blockIdx.x * blockDim.x + threadIdx.x;
    int total = Nn * (Ss / 4);
    if (t >= total) return;
    int n = t >> 3;
    int q = t & 7;
    const float4* s = reinterpret_cast<const float4*>(g_state);
    float4 v = s[t];
    int g = ngi[n];
    atomicAdd(reinterpret_cast<float4*>(&g_gs[g * Ss + 4 * q]), v);
}

// ---------------------------------------------------------------------------
__global__ void __launch_bounds__(128) readout_kernel(
    const float* __restrict__ Wo1, const float* __restrict__ bo1,
    const float* __restrict__ go, const float* __restrict__ beo,
    const float* __restrict__ Wo2, const float* __restrict__ bo2,
    float* __restrict__ out)
{
    __shared__ float sW[32 * 128];
    __shared__ float sb[128], sg[128], sbe[128];
    __shared__ float sW2[256];
    __shared__ float sb2[2];

    int tid = threadIdx.x;
    for (int i = tid; i < 32 * 128; i += 128) sW[i] = Wo1[i];
    sb[tid] = bo1[tid]; sg[tid] = go[tid]; sbe[tid] = beo[tid];
    sW2[tid] = Wo2[tid];
    sW2[tid + 128] = Wo2[tid + 128];
    if (tid < 2) sb2[tid] = bo2[tid];
    __syncthreads();

    int lane = tid & 31;
    int w = tid >> 5;
    int g = blockIdx.x * 4 + w;
    if (g >= Gg) return;

    float x = g_gs[g * Ss + lane];
    float4 a;
    a.x = sb[4 * lane]; a.y = sb[4 * lane + 1]; a.z = sb[4 * lane + 2]; a.w = sb[4 * lane + 3];
#pragma unroll
    for (int i = 0; i < 32; i++) {
        float xi = __shfl_sync(FULL, x, i);
        float4 wv = *(const float4*)&sW[i * 128 + 4 * lane];
        a.x += xi * wv.x; a.y += xi * wv.y; a.z += xi * wv.z; a.w += xi * wv.w;
    }
    float s = a.x + a.y + a.z + a.w;
    float s2 = a.x * a.x + a.y * a.y + a.z * a.z + a.w * a.w;
#pragma unroll
    for (int o = 16; o; o >>= 1) {
        s += __shfl_xor_sync(FULL, s, o);
        s2 += __shfl_xor_sync(FULL, s2, o);
    }
    float mean = s * (1.f / 128.f);
    float var = s2 * (1.f / 128.f) - mean * mean;
    float rstd = rsqrtf(var + LN_EPS);
    float h0 = lrelu((a.x - mean) * rstd * sg[4 * lane + 0] + sbe[4 * lane + 0]);
    float h1 = lrelu((a.y - mean) * rstd * sg[4 * lane + 1] + sbe[4 * lane + 1]);
    float h2 = lrelu((a.z - mean) * rstd * sg[4 * lane + 2] + sbe[4 * lane + 2]);
    float h3 = lrelu((a.w - mean) * rstd * sg[4 * lane + 3] + sbe[4 * lane + 3]);

    float p0 = h0 * sW2[(4 * lane + 0) * 2] + h1 * sW2[(4 * lane + 1) * 2]
             + h2 * sW2[(4 * lane + 2) * 2] + h3 * sW2[(4 * lane + 3) * 2];
    float p1 = h0 * sW2[(4 * lane + 0) * 2 + 1] + h1 * sW2[(4 * lane + 1) * 2 + 1]
             + h2 * sW2[(4 * lane + 2) * 2 + 1] + h3 * sW2[(4 * lane + 3) * 2 + 1];
#pragma unroll
    for (int o = 16; o; o >>= 1) {
        p0 += __shfl_xor_sync(FULL, p0, o);
        p1 += __shfl_xor_sync(FULL, p1, o);
    }
    if (lane == 0) {
        float mu = p0 + sb2[0];
        float v = p1 + sb2[1];
        float sp = (v > 0.f) ? v + log1pf(expf(-v)) : log1pf(expf(v));
        out[g * 2 + 0] = mu;
        out[g * 2 + 1] = sp;
    }
}

// ---------------------------------------------------------------------------
extern "C" void kernel_launch(void* const* d_in, const int* in_sizes, int n_in,
                              void* d_out, int out_size) {
    const int* nf = (const int*)d_in[0];
    const int* nt = (const int*)d_in[1];
    const float* ec = (const float*)d_in[2];
    const int* ngi = (const int*)d_in[3];
    const float* W1 = (const float*)d_in[6];
    const float* b1 = (const float*)d_in[7];
    const float* g1 = (const float*)d_in[8];
    const float* be1 = (const float*)d_in[9];
    const float* W2 = (const float*)d_in[10];
    const float* b2 = (const float*)d_in[11];
    const float* g2 = (const float*)d_in[12];
    const float* be2 = (const float*)d_in[13];
    const float* Wo1 = (const float*)d_in[14];
    const float* bo1 = (const float*)d_in[15];
    const float* go = (const float*)d_in[16];
    const float* beo = (const float*)d_in[17];
    const float* Wo2 = (const float*)d_in[18];
    const float* bo2 = (const float*)d_in[19];
    float* out = (float*)d_out;

    cudaFuncSetAttribute(edge_kernel<true>, cudaFuncAttributeMaxDynamicSharedMemorySize, EDGE_DSMEM);
    cudaFuncSetAttribute(edge_kernel<false>, cudaFuncAttributeMaxDynamicSharedMemorySize, EDGE_DSMEM);

    zero_kernel<<<4096, 256>>>();

    // round 0: state == 0 -> y == b1 uniform; skip node_gemm, no gather
    edge_kernel<true><<<EDGE_GRID, 256, EDGE_DSMEM>>>(nf, nt, ec,
                                                      W1, b1, g1, be1, W2, b2, g2, be2);
    // rounds 1..4
    for (int r = 1; r < ROUNDS; r++) {
        node_gemm_kernel<<<1024, 192>>>(W1, b1);
        edge_kernel<false><<<EDGE_GRID, 256, EDGE_DSMEM>>>(nf, nt, ec,
                                                           W1, b1, g1, be1, W2, b2, g2, be2);
    }

    graphsum_kernel<<<(Nn * 8 + 255) / 256, 256>>>(ngi);
    readout_kernel<<<(Gg + 3) / 4, 128>>>(Wo1, bo1, go, beo, Wo2, bo2, out);
}

// round 14
// speedup vs baseline: 1.6031x; 1.0368x over previous
#include <cuda_runtime.h>
#include <cuda_fp16.h>
#include <math.h>
#include <stdint.h>

#define FULL 0xffffffffu
typedef unsigned long long u64;

constexpr int Nn = 100000;
constexpr int Ee = 1600000;
constexpr int Gg = 1000;
constexpr int Ss = 32;
constexpr int Hh = 128;
constexpr int ROUNDS = 5;
constexpr float NEG_SLOPE = 0.01f;
constexpr float LN_EPS = 1e-5f;

constexpr int APITCH = 272;
constexpr int AWARP = 16 * APITCH;
constexpr int EDGE_WARPS = 8;                       // 256-thread blocks
constexpr int OFF_B_H = EDGE_WARPS * 2 * AWARP;     // 69632
constexpr int OFF_B_L = OFF_B_H + 32 * APITCH;      // 78336
constexpr int EDGE_DSMEM = OFF_B_L + 32 * APITCH;   // 87040  (2 blocks/SM, 16 warps/SM)
constexpr int EDGE_GRID = 296;

// single state buffer (in-place accumulation; edge kernel never reads it)
__device__ float g_state[Nn * Ss];
__device__ __half g_y[Nn * Hh];          // fp16 y (25.6MB): halves gather traffic
__device__ float4 g_stats[Nn];           // stats computed from ROUNDED y
__device__ float g_gs[Gg * Ss];

__device__ __forceinline__ float lrelu(float v) { return v >= 0.f ? v : NEG_SLOPE * v; }

// ---- packed f32x2 helpers ----
__device__ __forceinline__ u64 pack2(float lo, float hi) {
    u64 r; asm("mov.b64 %0,{%1,%2};" : "=l"(r) : "f"(lo), "f"(hi)); return r;
}
__device__ __forceinline__ void unpack2(u64 v, float& lo, float& hi) {
    asm("mov.b64 {%0,%1},%2;" : "=f"(lo), "=f"(hi) : "l"(v));
}
__device__ __forceinline__ u64 fma2(u64 a, u64 b, u64 c) {
    u64 d; asm("fma.rn.f32x2 %0,%1,%2,%3;" : "=l"(d) : "l"(a), "l"(b), "l"(c)); return d;
}
__device__ __forceinline__ u64 add2(u64 a, u64 b) {
    u64 d; asm("add.rn.f32x2 %0,%1,%2;" : "=l"(d) : "l"(a), "l"(b)); return d;
}
__device__ __forceinline__ u64 mul2(u64 a, u64 b) {
    u64 d; asm("mul.rn.f32x2 %0,%1,%2;" : "=l"(d) : "l"(a), "l"(b)); return d;
}

__device__ __forceinline__ uint32_t smem_u32(const void* p) {
    uint32_t a;
    asm("{ .reg .u64 t; cvta.to.shared.u64 t, %1; cvt.u32.u64 %0, t; }" : "=r"(a) : "l"(p));
    return a;
}

__device__ __forceinline__ void ldsm4(uint32_t r[4], uint32_t addr) {
    asm volatile("ldmatrix.sync.aligned.m8n8.x4.shared.b16 {%0,%1,%2,%3}, [%4];"
                 : "=r"(r[0]), "=r"(r[1]), "=r"(r[2]), "=r"(r[3]) : "r"(addr));
}

__device__ __forceinline__ void mma16816h(float acc[4], const uint32_t a[4],
                                          uint32_t b0, uint32_t b1) {
    asm volatile(
        "mma.sync.aligned.m16n8k16.row.col.f32.f16.f16.f32 "
        "{%0,%1,%2,%3}, {%4,%5,%6,%7}, {%8,%9}, {%0,%1,%2,%3};"
        : "+f"(acc[0]), "+f"(acc[1]), "+f"(acc[2]), "+f"(acc[3])
        : "r"(a[0]), "r"(a[1]), "r"(a[2]), "r"(a[3]), "r"(b0), "r"(b1));
}

// ---------------------------------------------------------------------------
__global__ void zero_kernel() {
    int i = blockIdx.x * blockDim.x + threadIdx.x;
    int stride = gridDim.x * blockDim.x;
    for (int k = i; k < Nn * Ss; k += stride) g_state[k] = 0.f;
    for (int k = i; k < Gg * Ss; k += stride) g_gs[k] = 0.f;
}

// ---------------------------------------------------------------------------
// y = fp16(state @ W1[:32] + b1) ; stats (Sy,Qy,P) from the ROUNDED values.
__global__ void __launch_bounds__(192) node_gemm_kernel(
    const float* __restrict__ W1, const float* __restrict__ b1)
{
    __shared__ float sW1[32 * 128];
    __shared__ float sb1[128];
    const float* __restrict__ state_in = g_state;

    int tid = threadIdx.x;
    for (int i = tid; i < 32 * 128; i += 192) sW1[i] = W1[i];
    if (tid < 128) sb1[tid] = b1[tid];
    __syncthreads();

    int lane = tid & 31;
    int w = tid >> 5;
    int warp_global = blockIdx.x * 6 + w;
    int nwarps = gridDim.x * 6;
    int ngroups = Nn / 4;

    float4 b1v = *(const float4*)&sb1[4 * lane];
    float4 w32v = *(const float4*)&W1[32 * 128 + 4 * lane];

    for (int g = warp_global; g < ngroups; g += nwarps) {
        int nbase = g * 4;
        float x0 = state_in[(nbase + 0) * Ss + lane];
        float x1 = state_in[(nbase + 1) * Ss + lane];
        float x2 = state_in[(nbase + 2) * Ss + lane];
        float x3 = state_in[(nbase + 3) * Ss + lane];

        float4 a0 = b1v, a1 = b1v, a2 = b1v, a3 = b1v;
#pragma unroll
        for (int i = 0; i < 32; i++) {
            float4 wv = *(const float4*)&sW1[i * 128 + 4 * lane];
            float s0 = __shfl_sync(FULL, x0, i);
            float s1 = __shfl_sync(FULL, x1, i);
            float s2 = __shfl_sync(FULL, x2, i);
            float s3 = __shfl_sync(FULL, x3, i);
            a0.x += s0 * wv.x; a0.y += s0 * wv.y; a0.z += s0 * wv.z; a0.w += s0 * wv.w;
            a1.x += s1 * wv.x; a1.y += s1 * wv.y; a1.z += s1 * wv.z; a1.w += s1 * wv.w;
            a2.x += s2 * wv.x; a2.y += s2 * wv.y; a2.z += s2 * wv.z; a2.w += s2 * wv.w;
            a3.x += s3 * wv.x; a3.y += s3 * wv.y; a3.z += s3 * wv.z; a3.w += s3 * wv.w;
        }

#pragma unroll
        for (int e = 0; e < 4; e++) {
            float4 a = (e == 0) ? a0 : (e == 1) ? a1 : (e == 2) ? a2 : a3;
            // round to fp16, store packed
            __half2 h01 = __float22half2_rn(make_float2(a.x, a.y));
            __half2 h23 = __float22half2_rn(make_float2(a.z, a.w));
            uint2 pk;
            pk.x = *(uint32_t*)&h01;
            pk.y = *(uint32_t*)&h23;
            *(uint2*)&g_y[(nbase + e) * Hh + 4 * lane] = pk;

            // stats from ROUNDED values (so LN1 is exact for the values used)
            float2 r01 = __half22float2(h01);
            float2 r23 = __half22float2(h23);
            float rx = r01.x, ry = r01.y, rz = r23.x, rw = r23.y;
            float s = rx + ry + rz + rw;
            float q = rx * rx + ry * ry + rz * rz + rw * rw;
            float p = rx * w32v.x + ry * w32v.y + rz * w32v.z + rw * w32v.w;
#pragma unroll
            for (int o = 16; o; o >>= 1) {
                s += __shfl_xor_sync(FULL, s, o);
                q += __shfl_xor_sync(FULL, q, o);
                p += __shfl_xor_sync(FULL, p, o);
            }
            if (lane == 0) g_stats[nbase + e] = make_float4(s, q, p, 0.f);
        }
    }
}

// ---------------------------------------------------------------------------
// per-tile epilogue: packed bias + LN2 (quad reduce) + 4 float4 atomics
__device__ __forceinline__ void epilogue_tile(
    const float acc[4][4], int dstA, int dstB, int q,
    const u64 b2p[4], const u64 g2p[4], const u64 be2p[4], u64 C001,
    float* __restrict__ state_out)
{
    u64 mA[4], mB[4];
#pragma unroll
    for (int t = 0; t < 4; t++) {
        mA[t] = add2(pack2(acc[t][0], acc[t][1]), b2p[t]);
        mB[t] = add2(pack2(acc[t][2], acc[t][3]), b2p[t]);
    }
    u64 sA2 = add2(add2(mA[0], mA[1]), add2(mA[2], mA[3]));
    u64 sB2 = add2(add2(mB[0], mB[1]), add2(mB[2], mB[3]));
    u64 qA2 = fma2(mA[0], mA[0], fma2(mA[1], mA[1], fma2(mA[2], mA[2], mul2(mA[3], mA[3]))));
    u64 qB2 = fma2(mB[0], mB[0], fma2(mB[1], mB[1], fma2(mB[2], mB[2], mul2(mB[3], mB[3]))));
    float t0, t1;
    unpack2(sA2, t0, t1); float sA = t0 + t1;
    unpack2(qA2, t0, t1); float qA = t0 + t1;
    unpack2(sB2, t0, t1); float sB = t0 + t1;
    unpack2(qB2, t0, t1); float qB = t0 + t1;
#pragma unroll
    for (int o = 2; o; o >>= 1) {
        sA += __shfl_xor_sync(FULL, sA, o);
        qA += __shfl_xor_sync(FULL, qA, o);
        sB += __shfl_xor_sync(FULL, sB, o);
        qB += __shfl_xor_sync(FULL, qB, o);
    }
    float meanA = sA * (1.f / 32.f);
    float rstdA = rsqrtf(qA * (1.f / 32.f) - meanA * meanA + LN_EPS);
    float meanB = sB * (1.f / 32.f);
    float rstdB = rsqrtf(qB * (1.f / 32.f) - meanB * meanB + LN_EPS);

    u64 rA2p = pack2(rstdA, rstdA), nmA2 = pack2(-meanA, -meanA);
    u64 rB2p = pack2(rstdB, rstdB), nmB2 = pack2(-meanB, -meanB);

    float vA[8], vB[8];
#pragma unroll
    for (int t = 0; t < 4; t++) {
        u64 agA = mul2(rA2p, g2p[t]);
        u64 offA = fma2(nmA2, agA, be2p[t]);
        u64 hA = fma2(mA[t], agA, offA);
        u64 pA = mul2(hA, C001);
        float h0, h1, p0, p1;
        unpack2(hA, h0, h1); unpack2(pA, p0, p1);
        vA[2 * t] = fmaxf(h0, p0); vA[2 * t + 1] = fmaxf(h1, p1);

        u64 agB = mul2(rB2p, g2p[t]);
        u64 offB = fma2(nmB2, agB, be2p[t]);
        u64 hB = fma2(mB[t], agB, offB);
        u64 pB = mul2(hB, C001);
        unpack2(hB, h0, h1); unpack2(pB, p0, p1);
        vB[2 * t] = fmaxf(h0, p0); vB[2 * t + 1] = fmaxf(h1, p1);
    }

    float* rowA = &state_out[dstA * Ss + 8 * q];
    float* rowB = &state_out[dstB * Ss + 8 * q];
    atomicAdd((float4*)&rowA[0], make_float4(vA[0], vA[1], vA[2], vA[3]));
    atomicAdd((float4*)&rowA[4], make_float4(vA[4], vA[5], vA[6], vA[7]));
    atomicAdd((float4*)&rowB[0], make_float4(vB[0], vB[1], vB[2], vB[3]));
    atomicAdd((float4*)&rowB[4], make_float4(vB[4], vB[5], vB[6], vB[7]));
}

// ---------------------------------------------------------------------------
// Edge kernel: fp16 A single / B hi-lo, 32-edge groups, B-fragment reuse.
// y gathered as fp16 (uint2 per lane). Same 87KB / 16 warps per SM config.
template <bool ROUND0>
__global__ void __launch_bounds__(256, 2) edge_kernel(
    const int* __restrict__ nf, const int* __restrict__ nt,
    const float* __restrict__ ec,
    const float* __restrict__ W1, const float* __restrict__ b1,
    const float* __restrict__ g1, const float* __restrict__ be1,
    const float* __restrict__ W2, const float* __restrict__ b2,
    const float* __restrict__ g2, const float* __restrict__ be2)
{
    extern __shared__ char dsm[];
    uint32_t sbase = smem_u32(dsm);

    int tid = threadIdx.x;
    int lane = tid & 31;
    int wid = tid >> 5;

    // B staging (fp16 hi/lo) with column permutation pi(8t+2q+r) = 8q+2t+r
    for (int p = tid; p < 32 * 128; p += 256) {
        int n = p >> 7;
        int k = p & 127;
        int t = n >> 3, q0 = (n >> 1) & 3, r = n & 1;
        int pn = 8 * q0 + 2 * t + r;
        float wv = W2[k * 32 + pn];
        __half hb = __float2half_rn(wv);
        __half lb = __float2half_rn(wv - __half2float(hb));
        *(__half*)(dsm + OFF_B_H + n * APITCH + k * 2) = hb;
        *(__half*)(dsm + OFF_B_L + n * APITCH + k * 2) = lb;
    }
    __syncthreads();

    float4 w32v = *(const float4*)&W1[32 * 128 + 4 * lane];
    float4 g1v  = *(const float4*)&g1[4 * lane];
    float4 be1v = *(const float4*)&be1[4 * lane];
    float4 b1vr;  // round-0 path must use ROUNDED b1 for exact-stat consistency
    {
        float4 b1v = *(const float4*)&b1[4 * lane];
        __half2 h01 = __float22half2_rn(make_float2(b1v.x, b1v.y));
        __half2 h23 = __float22half2_rn(make_float2(b1v.z, b1v.w));
        float2 r01 = __half22float2(h01);
        float2 r23 = __half22float2(h23);
        b1vr = make_float4(r01.x, r01.y, r23.x, r23.y);
    }

    float Sw = w32v.x + w32v.y + w32v.z + w32v.w;
    float Qw = w32v.x * w32v.x + w32v.y * w32v.y + w32v.z * w32v.z + w32v.w * w32v.w;
    float Sb = b1vr.x + b1vr.y + b1vr.z + b1vr.w;
    float Qb = b1vr.x * b1vr.x + b1vr.y * b1vr.y + b1vr.z * b1vr.z + b1vr.w * b1vr.w;
    float Pb = b1vr.x * w32v.x + b1vr.y * w32v.y + b1vr.z * w32v.z + b1vr.w * w32v.w;
#pragma unroll
    for (int o = 16; o; o >>= 1) {
        Sw += __shfl_xor_sync(FULL, Sw, o);
        Qw += __shfl_xor_sync(FULL, Qw, o);
        Sb += __shfl_xor_sync(FULL, Sb, o);
        Qb += __shfl_xor_sync(FULL, Qb, o);
        Pb += __shfl_xor_sync(FULL, Pb, o);
    }

    int q = lane & 3;
    int rA = lane >> 2;
    int rB = rA + 8;

    u64 b2p[4], g2p[4], be2p[4];
#pragma unroll
    for (int t = 0; t < 4; t++) {
        int c = 8 * q + 2 * t;
        b2p[t]  = pack2(b2[c],  b2[c + 1]);
        g2p[t]  = pack2(g2[c],  g2[c + 1]);
        be2p[t] = pack2(be2[c], be2[c + 1]);
    }
    const u64 C001 = pack2(NEG_SLOPE, NEG_SLOPE);

    // staging: tile0 at wid*2*AWARP, tile1 at +AWARP
    char* aStore = dsm + wid * 2 * AWARP + lane * 8;

    int aRow = lane & 15;
    int aColB = ((lane >> 4) & 1) * 16;
    uint32_t ldA0 = sbase + wid * 2 * AWARP + aRow * APITCH + aColB;
    uint32_t ldA1 = ldA0 + AWARP;

    int bRow = ((lane >> 4) & 1) * 8 + (lane & 7);
    int bKB = ((lane >> 3) & 1) * 16;
    uint32_t ldBH01 = sbase + OFF_B_H + bRow * APITCH + bKB;
    uint32_t ldBH23 = ldBH01 + 16 * APITCH;
    uint32_t ldBL01 = sbase + OFF_B_L + bRow * APITCH + bKB;
    uint32_t ldBL23 = ldBL01 + 16 * APITCH;

    const __half* __restrict__ yh = g_y;
    float* __restrict__ state_out = g_state;

    int ngroups = Ee / 32;          // 50000
    int wg = blockIdx.x * EDGE_WARPS + wid;
    int nw = gridDim.x * EDGE_WARPS;

    for (int g = wg; g < ngroups; g += nw) {
        int base = g * 32;

        // ---- gather (fp16) + stats-based LN1 + fp16 convert + stage ----
#pragma unroll
        for (int j = 0; j < 8; j++) {
            float4 C = *(const float4*)&ec[base + 4 * j];
            float cs[4] = {C.x, C.y, C.z, C.w};
            int srcs[4];
            if constexpr (!ROUND0) {
                int4 NF = *(const int4*)&nf[base + 4 * j];
                srcs[0] = NF.x; srcs[1] = NF.y; srcs[2] = NF.z; srcs[3] = NF.w;
            }
#pragma unroll
            for (int e = 0; e < 4; e++) {
                float c = cs[e];
                float4 a;
                float s, qq;
                if constexpr (ROUND0) {
                    a = b1vr;                         // y == round(b1) (state == 0)
                    s = fmaf(c, Sw, Sb);
                    qq = fmaf(c * c, Qw, fmaf(2.f * c, Pb, Qb));
                } else {
                    int src = srcs[e];
                    float4 st = g_stats[src];
                    uint2 pk = *(const uint2*)&yh[src * Hh + 4 * lane];
                    float2 f01 = __half22float2(*(__half2*)&pk.x);
                    float2 f23 = __half22float2(*(__half2*)&pk.y);
                    a = make_float4(f01.x, f01.y, f23.x, f23.y);
                    s = fmaf(c, Sw, st.x);
                    qq = fmaf(c * c, Qw, fmaf(2.f * c, st.z, st.y));
                }
                a.x = fmaf(c, w32v.x, a.x);
                a.y = fmaf(c, w32v.y, a.y);
                a.z = fmaf(c, w32v.z, a.z);
                a.w = fmaf(c, w32v.w, a.w);

                float mean = s * (1.f / 128.f);
                float var = qq * (1.f / 128.f) - mean * mean;
                float rstd = rsqrtf(var + LN_EPS);

                float4 hv;
                hv.x = lrelu(fmaf((a.x - mean) * rstd, g1v.x, be1v.x));
                hv.y = lrelu(fmaf((a.y - mean) * rstd, g1v.y, be1v.y));
                hv.z = lrelu(fmaf((a.z - mean) * rstd, g1v.z, be1v.z));
                hv.w = lrelu(fmaf((a.w - mean) * rstd, g1v.w, be1v.w));

                __half2 h01 = __float22half2_rn(make_float2(hv.x, hv.y));
                __half2 h23 = __float22half2_rn(make_float2(hv.z, hv.w));
                u64 packh = (u64)(*(uint32_t*)&h01) | ((u64)(*(uint32_t*)&h23) << 32);
                int row = 4 * j + e;                 // 0..31
                char* dst = aStore + (row >> 4) * AWARP + (row & 15) * APITCH;
                *(u64*)dst = packh;
            }
        }
        __syncwarp();

        // hoist destination loads (latency hides behind MMA)
        int dstA0 = __ldg(&nt[base + rA]);
        int dstB0 = __ldg(&nt[base + rB]);
        int dstA1 = __ldg(&nt[base + 16 + rA]);
        int dstB1 = __ldg(&nt[base + 16 + rB]);

        // ---- MMA: D = A@Bh + A@Bl per tile; B fragments shared by both tiles
        float acc0[4][4], acc1[4][4];
#pragma unroll
        for (int t = 0; t < 4; t++)
#pragma unroll
            for (int j2 = 0; j2 < 4; j2++) { acc0[t][j2] = 0.f; acc1[t][j2] = 0.f; }

#pragma unroll
        for (int k = 0; k < 8; k++) {
            uint32_t bh01[4], bh23[4], bl01[4], bl23[4];
            ldsm4(bh01, ldBH01 + k * 32);
            ldsm4(bh23, ldBH23 + k * 32);
            ldsm4(bl01, ldBL01 + k * 32);
            ldsm4(bl23, ldBL23 + k * 32);

            uint32_t a0[4], a1[4];
            ldsm4(a0, ldA0 + k * 32);
            ldsm4(a1, ldA1 + k * 32);

            mma16816h(acc0[0], a0, bh01[0], bh01[1]);
            mma16816h(acc0[1], a0, bh01[2], bh01[3]);
            mma16816h(acc0[2], a0, bh23[0], bh23[1]);
            mma16816h(acc0[3], a0, bh23[2], bh23[3]);
            mma16816h(acc0[0], a0, bl01[0], bl01[1]);
            mma16816h(acc0[1], a0, bl01[2], bl01[3]);
            mma16816h(acc0[2], a0, bl23[0], bl23[1]);
            mma16816h(acc0[3], a0, bl23[2], bl23[3]);

            mma16816h(acc1[0], a1, bh01[0], bh01[1]);
            mma16816h(acc1[1], a1, bh01[2], bh01[3]);
            mma16816h(acc1[2], a1, bh23[0], bh23[1]);
            mma16816h(acc1[3], a1, bh23[2], bh23[3]);
            mma16816h(acc1[0], a1, bl01[0], bl01[1]);
            mma16816h(acc1[1], a1, bl01[2], bl01[3]);
            mma16816h(acc1[2], a1, bl23[0], bl23[1]);
            mma16816h(acc1[3], a1, bl23[2], bl23[3]);
        }
        __syncwarp();

        // ---- epilogues ----
        epilogue_tile(acc0, dstA0, dstB0, q, b2p, g2p, be2p, C001, state_out);
        epilogue_tile(acc1, dstA1, dstB1, q, b2p, g2p, be2p, C001, state_out);
    }
}

// ---------------------------------------------------------------------------
__global__ void graphsum_kernel(const int* __restrict__ ngi) {
    int t = blockIdx.x * blockDim.x + threadIdx.x;
    int total = Nn * (Ss / 4);
    if (t >= total) return;
    int n = t >> 3;
    int q = t & 7;
    const float4* s = reinterpret_cast<const float4*>(g_state);
    float4 v = s[t];
    int g = ngi[n];
    atomicAdd(reinterpret_cast<float4*>(&g_gs[g * Ss + 4 * q]), v);
}

// ---------------------------------------------------------------------------
__global__ void __launch_bounds__(128) readout_kernel(
    const float* __restrict__ Wo1, const float* __restrict__ bo1,
    const float* __restrict__ go, const float* __restrict__ beo,
    const float* __restrict__ Wo2, const float* __restrict__ bo2,
    float* __restrict__ out)
{
    __shared__ float sW[32 * 128];
    __shared__ float sb[128], sg[128], sbe[128];
    __shared__ float sW2[256];
    __shared__ float sb2[2];

    int tid = threadIdx.x;
    for (int i = tid; i < 32 * 128; i += 128) sW[i] = Wo1[i];
    sb[tid] = bo1[tid]; sg[tid] = go[tid]; sbe[tid] = beo[tid];
    sW2[tid] = Wo2[tid];
    sW2[tid + 128] = Wo2[tid + 128];
    if (tid < 2) sb2[tid] = bo2[tid];
    __syncthreads();

    int lane = tid & 31;
    int w = tid >> 5;
    int g = blockIdx.x * 4 + w;
    if (g >= Gg) return;

    float x = g_gs[g * Ss + lane];
    float4 a;
    a.x = sb[4 * lane]; a.y = sb[4 * lane + 1]; a.z = sb[4 * lane + 2]; a.w = sb[4 * lane + 3];
#pragma unroll
    for (int i = 0; i < 32; i++) {
        float xi = __shfl_sync(FULL, x, i);
        float4 wv = *(const float4*)&sW[i * 128 + 4 * lane];
        a.x += xi * wv.x; a.y += xi * wv.y; a.z += xi * wv.z; a.w += xi * wv.w;
    }
    float s = a.x + a.y + a.z + a.w;
    float s2 = a.x * a.x + a.y * a.y + a.z * a.z + a.w * a.w;
#pragma unroll
    for (int o = 16; o; o >>= 1) {
        s += __shfl_xor_sync(FULL, s, o);
        s2 += __shfl_xor_sync(FULL, s2, o);
    }
    float mean = s * (1.f / 128.f);
    float var = s2 * (1.f / 128.f) - mean * mean;
    float rstd = rsqrtf(var + LN_EPS);
    float h0 = lrelu((a.x - mean) * rstd * sg[4 * lane + 0] + sbe[4 * lane + 0]);
    float h1 = lrelu((a.y - mean) * rstd * sg[4 * lane + 1] + sbe[4 * lane + 1]);
    float h2 = lrelu((a.z - mean) * rstd * sg[4 * lane + 2] + sbe[4 * lane + 2]);
    float h3 = lrelu((a.w - mean) * rstd * sg[4 * lane + 3] + sbe[4 * lane + 3]);

    float p0 = h0 * sW2[(4 * lane + 0) * 2] + h1 * sW2[(4 * lane + 1) * 2]
             + h2 * sW2[(4 * lane + 2) * 2] + h3 * sW2[(4 * lane + 3) * 2];
    float p1 = h0 * sW2[(4 * lane + 0) * 2 + 1] + h1 * sW2[(4 * lane + 1) * 2 + 1]
             + h2 * sW2[(4 * lane + 2) * 2 + 1] + h3 * sW2[(4 * lane + 3) * 2 + 1];
#pragma unroll
    for (int o = 16; o; o >>= 1) {
        p0 += __shfl_xor_sync(FULL, p0, o);
        p1 += __shfl_xor_sync(FULL, p1, o);
    }
    if (lane == 0) {
        float mu = p0 + sb2[0];
        float v = p1 + sb2[1];
        float sp = (v > 0.f) ? v + log1pf(expf(-v)) : log1pf(expf(v));
        out[g * 2 + 0] = mu;
        out[g * 2 + 1] = sp;
    }
}

// ---------------------------------------------------------------------------
extern "C" void kernel_launch(void* const* d_in, const int* in_sizes, int n_in,
                              void* d_out, int out_size) {
    const int* nf = (const int*)d_in[0];
    const int* nt = (const int*)d_in[1];
    const float* ec = (const float*)d_in[2];
    const int* ngi = (const int*)d_in[3];
    const float* W1 = (const float*)d_in[6];
    const float* b1 = (const float*)d_in[7];
    const float* g1 = (const float*)d_in[8];
    const float* be1 = (const float*)d_in[9];
    const float* W2 = (const float*)d_in[10];
    const float* b2 = (const float*)d_in[11];
    const float* g2 = (const float*)d_in[12];
    const float* be2 = (const float*)d_in[13];
    const float* Wo1 = (const float*)d_in[14];
    const float* bo1 = (const float*)d_in[15];
    const float* go = (const float*)d_in[16];
    const float* beo = (const float*)d_in[17];
    const float* Wo2 = (const float*)d_in[18];
    const float* bo2 = (const float*)d_in[19];
    float* out = (float*)d_out;

    cudaFuncSetAttribute(edge_kernel<true>, cudaFuncAttributeMaxDynamicSharedMemorySize, EDGE_DSMEM);
    cudaFuncSetAttribute(edge_kernel<false>, cudaFuncAttributeMaxDynamicSharedMemorySize, EDGE_DSMEM);

    zero_kernel<<<4096, 256>>>();

    // round 0: state == 0 -> y == round(b1) uniform; skip node_gemm, no gather
    edge_kernel<true><<<EDGE_GRID, 256, EDGE_DSMEM>>>(nf, nt, ec,
                                                      W1, b1, g1, be1, W2, b2, g2, be2);
    // rounds 1..4
    for (int r = 1; r < ROUNDS; r++) {
        node_gemm_kernel<<<1024, 192>>>(W1, b1);
        edge_kernel<false><<<EDGE_GRID, 256, EDGE_DSMEM>>>(nf, nt, ec,
                                                           W1, b1, g1, be1, W2, b2, g2, be2);
    }

    graphsum_kernel<<<(Nn * 8 + 255) / 256, 256>>>(ngi);
    readout_kernel<<<(Gg + 3) / 4, 128>>>(Wo1, bo1, go, beo, Wo2, bo2, out);
}

// round 15
// speedup vs baseline: 1.7446x; 1.0883x over previous
#include <cuda_runtime.h>
#include <cuda_fp16.h>
#include <math.h>
#include <stdint.h>

#define FULL 0xffffffffu
typedef unsigned long long u64;

constexpr int Nn = 100000;
constexpr int Ee = 1600000;
constexpr int Gg = 1000;
constexpr int Ss = 32;
constexpr int Hh = 128;
constexpr int ROUNDS = 5;
constexpr float NEG_SLOPE = 0.01f;
constexpr float LN_EPS = 1e-5f;

constexpr int APITCH = 272;
constexpr int AWARP = 16 * APITCH;
constexpr int EDGE_WARPS = 8;                       // 256-thread blocks
constexpr int OFF_B_H = EDGE_WARPS * 2 * AWARP;     // 69632
constexpr int OFF_B_L = OFF_B_H + 32 * APITCH;      // 78336
constexpr int EDGE_DSMEM = OFF_B_L + 32 * APITCH;   // 87040  (2 blocks/SM, 16 warps/SM)
constexpr int EDGE_GRID = 296;

// single state buffer (in-place accumulation; edge kernel never reads it)
__device__ float g_state[Nn * Ss];
__device__ __half g_y[Nn * Hh];          // fp16 y (25.6MB)
__device__ float4 g_stats[Nn];           // stats computed from ROUNDED y
__device__ float g_gs[Gg * Ss];

__device__ __forceinline__ float lrelu(float v) { return v >= 0.f ? v : NEG_SLOPE * v; }

// ---- packed f32x2 helpers ----
__device__ __forceinline__ u64 pack2(float lo, float hi) {
    u64 r; asm("mov.b64 %0,{%1,%2};" : "=l"(r) : "f"(lo), "f"(hi)); return r;
}
__device__ __forceinline__ void unpack2(u64 v, float& lo, float& hi) {
    asm("mov.b64 {%0,%1},%2;" : "=f"(lo), "=f"(hi) : "l"(v));
}
__device__ __forceinline__ u64 fma2(u64 a, u64 b, u64 c) {
    u64 d; asm("fma.rn.f32x2 %0,%1,%2,%3;" : "=l"(d) : "l"(a), "l"(b), "l"(c)); return d;
}
__device__ __forceinline__ u64 add2(u64 a, u64 b) {
    u64 d; asm("add.rn.f32x2 %0,%1,%2;" : "=l"(d) : "l"(a), "l"(b)); return d;
}
__device__ __forceinline__ u64 mul2(u64 a, u64 b) {
    u64 d; asm("mul.rn.f32x2 %0,%1,%2;" : "=l"(d) : "l"(a), "l"(b)); return d;
}

__device__ __forceinline__ uint32_t smem_u32(const void* p) {
    uint32_t a;
    asm("{ .reg .u64 t; cvta.to.shared.u64 t, %1; cvt.u32.u64 %0, t; }" : "=r"(a) : "l"(p));
    return a;
}

__device__ __forceinline__ void ldsm4(uint32_t r[4], uint32_t addr) {
    asm volatile("ldmatrix.sync.aligned.m8n8.x4.shared.b16 {%0,%1,%2,%3}, [%4];"
                 : "=r"(r[0]), "=r"(r[1]), "=r"(r[2]), "=r"(r[3]) : "r"(addr));
}

__device__ __forceinline__ void mma16816h(float acc[4], const uint32_t a[4],
                                          uint32_t b0, uint32_t b1) {
    asm volatile(
        "mma.sync.aligned.m16n8k16.row.col.f32.f16.f16.f32 "
        "{%0,%1,%2,%3}, {%4,%5,%6,%7}, {%8,%9}, {%0,%1,%2,%3};"
        : "+f"(acc[0]), "+f"(acc[1]), "+f"(acc[2]), "+f"(acc[3])
        : "r"(a[0]), "r"(a[1]), "r"(a[2]), "r"(a[3]), "r"(b0), "r"(b1));
}

// ---------------------------------------------------------------------------
__global__ void zero_kernel() {
    int i = blockIdx.x * blockDim.x + threadIdx.x;
    int stride = gridDim.x * blockDim.x;
    for (int k = i; k < Nn * Ss; k += stride) g_state[k] = 0.f;
    for (int k = i; k < Gg * Ss; k += stride) g_gs[k] = 0.f;
}

// ---------------------------------------------------------------------------
// y = fp16(state @ W1[:32] + b1) ; stats (Sy,Qy,P) from the ROUNDED values.
__global__ void __launch_bounds__(192) node_gemm_kernel(
    const float* __restrict__ W1, const float* __restrict__ b1)
{
    __shared__ float sW1[32 * 128];
    __shared__ float sb1[128];
    const float* __restrict__ state_in = g_state;

    int tid = threadIdx.x;
    for (int i = tid; i < 32 * 128; i += 192) sW1[i] = W1[i];
    if (tid < 128) sb1[tid] = b1[tid];
    __syncthreads();

    int lane = tid & 31;
    int w = tid >> 5;
    int warp_global = blockIdx.x * 6 + w;
    int nwarps = gridDim.x * 6;
    int ngroups = Nn / 4;

    float4 b1v = *(const float4*)&sb1[4 * lane];
    float4 w32v = *(const float4*)&W1[32 * 128 + 4 * lane];

    for (int g = warp_global; g < ngroups; g += nwarps) {
        int nbase = g * 4;
        float x0 = state_in[(nbase + 0) * Ss + lane];
        float x1 = state_in[(nbase + 1) * Ss + lane];
        float x2 = state_in[(nbase + 2) * Ss + lane];
        float x3 = state_in[(nbase + 3) * Ss + lane];

        float4 a0 = b1v, a1 = b1v, a2 = b1v, a3 = b1v;
#pragma unroll
        for (int i = 0; i < 32; i++) {
            float4 wv = *(const float4*)&sW1[i * 128 + 4 * lane];
            float s0 = __shfl_sync(FULL, x0, i);
            float s1 = __shfl_sync(FULL, x1, i);
            float s2 = __shfl_sync(FULL, x2, i);
            float s3 = __shfl_sync(FULL, x3, i);
            a0.x += s0 * wv.x; a0.y += s0 * wv.y; a0.z += s0 * wv.z; a0.w += s0 * wv.w;
            a1.x += s1 * wv.x; a1.y += s1 * wv.y; a1.z += s1 * wv.z; a1.w += s1 * wv.w;
            a2.x += s2 * wv.x; a2.y += s2 * wv.y; a2.z += s2 * wv.z; a2.w += s2 * wv.w;
            a3.x += s3 * wv.x; a3.y += s3 * wv.y; a3.z += s3 * wv.z; a3.w += s3 * wv.w;
        }

#pragma unroll
        for (int e = 0; e < 4; e++) {
            float4 a = (e == 0) ? a0 : (e == 1) ? a1 : (e == 2) ? a2 : a3;
            __half2 h01 = __float22half2_rn(make_float2(a.x, a.y));
            __half2 h23 = __float22half2_rn(make_float2(a.z, a.w));
            uint2 pk;
            pk.x = *(uint32_t*)&h01;
            pk.y = *(uint32_t*)&h23;
            *(uint2*)&g_y[(nbase + e) * Hh + 4 * lane] = pk;

            float2 r01 = __half22float2(h01);
            float2 r23 = __half22float2(h23);
            float rx = r01.x, ry = r01.y, rz = r23.x, rw = r23.y;
            float s = rx + ry + rz + rw;
            float q = rx * rx + ry * ry + rz * rz + rw * rw;
            float p = rx * w32v.x + ry * w32v.y + rz * w32v.z + rw * w32v.w;
#pragma unroll
            for (int o = 16; o; o >>= 1) {
                s += __shfl_xor_sync(FULL, s, o);
                q += __shfl_xor_sync(FULL, q, o);
                p += __shfl_xor_sync(FULL, p, o);
            }
            if (lane == 0) g_stats[nbase + e] = make_float4(s, q, p, 0.f);
        }
    }
}

// ---------------------------------------------------------------------------
// per-tile epilogue: packed bias + LN2 (quad reduce) + 4 float4 atomics
__device__ __forceinline__ void epilogue_tile(
    const float acc[4][4], int dstA, int dstB, int q,
    const u64 b2p[4], const u64 g2p[4], const u64 be2p[4], u64 C001,
    float* __restrict__ state_out)
{
    u64 mA[4], mB[4];
#pragma unroll
    for (int t = 0; t < 4; t++) {
        mA[t] = add2(pack2(acc[t][0], acc[t][1]), b2p[t]);
        mB[t] = add2(pack2(acc[t][2], acc[t][3]), b2p[t]);
    }
    u64 sA2 = add2(add2(mA[0], mA[1]), add2(mA[2], mA[3]));
    u64 sB2 = add2(add2(mB[0], mB[1]), add2(mB[2], mB[3]));
    u64 qA2 = fma2(mA[0], mA[0], fma2(mA[1], mA[1], fma2(mA[2], mA[2], mul2(mA[3], mA[3]))));
    u64 qB2 = fma2(mB[0], mB[0], fma2(mB[1], mB[1], fma2(mB[2], mB[2], mul2(mB[3], mB[3]))));
    float t0, t1;
    unpack2(sA2, t0, t1); float sA = t0 + t1;
    unpack2(qA2, t0, t1); float qA = t0 + t1;
    unpack2(sB2, t0, t1); float sB = t0 + t1;
    unpack2(qB2, t0, t1); float qB = t0 + t1;
#pragma unroll
    for (int o = 2; o; o >>= 1) {
        sA += __shfl_xor_sync(FULL, sA, o);
        qA += __shfl_xor_sync(FULL, qA, o);
        sB += __shfl_xor_sync(FULL, sB, o);
        qB += __shfl_xor_sync(FULL, qB, o);
    }
    float meanA = sA * (1.f / 32.f);
    float rstdA = rsqrtf(qA * (1.f / 32.f) - meanA * meanA + LN_EPS);
    float meanB = sB * (1.f / 32.f);
    float rstdB = rsqrtf(qB * (1.f / 32.f) - meanB * meanB + LN_EPS);

    u64 rA2p = pack2(rstdA, rstdA), nmA2 = pack2(-meanA, -meanA);
    u64 rB2p = pack2(rstdB, rstdB), nmB2 = pack2(-meanB, -meanB);

    float vA[8], vB[8];
#pragma unroll
    for (int t = 0; t < 4; t++) {
        u64 agA = mul2(rA2p, g2p[t]);
        u64 offA = fma2(nmA2, agA, be2p[t]);
        u64 hA = fma2(mA[t], agA, offA);
        u64 pA = mul2(hA, C001);
        float h0, h1, p0, p1;
        unpack2(hA, h0, h1); unpack2(pA, p0, p1);
        vA[2 * t] = fmaxf(h0, p0); vA[2 * t + 1] = fmaxf(h1, p1);

        u64 agB = mul2(rB2p, g2p[t]);
        u64 offB = fma2(nmB2, agB, be2p[t]);
        u64 hB = fma2(mB[t], agB, offB);
        u64 pB = mul2(hB, C001);
        unpack2(hB, h0, h1); unpack2(pB, p0, p1);
        vB[2 * t] = fmaxf(h0, p0); vB[2 * t + 1] = fmaxf(h1, p1);
    }

    float* rowA = &state_out[dstA * Ss + 8 * q];
    float* rowB = &state_out[dstB * Ss + 8 * q];
    atomicAdd((float4*)&rowA[0], make_float4(vA[0], vA[1], vA[2], vA[3]));
    atomicAdd((float4*)&rowA[4], make_float4(vA[4], vA[5], vA[6], vA[7]));
    atomicAdd((float4*)&rowB[0], make_float4(vB[0], vB[1], vB[2], vB[3]));
    atomicAdd((float4*)&rowB[4], make_float4(vB[4], vB[5], vB[6], vB[7]));
}

// ---------------------------------------------------------------------------
// Edge kernel: fp16 A single / B hi-lo, 32-edge groups, B-fragment reuse.
// NEW: per-edge LN1 statistics computed DISTRIBUTED (lane l owns edge l),
// fetched via shfl — one rsqrt instruction per group instead of 32.
template <bool ROUND0>
__global__ void __launch_bounds__(256, 2) edge_kernel(
    const int* __restrict__ nf, const int* __restrict__ nt,
    const float* __restrict__ ec,
    const float* __restrict__ W1, const float* __restrict__ b1,
    const float* __restrict__ g1, const float* __restrict__ be1,
    const float* __restrict__ W2, const float* __restrict__ b2,
    const float* __restrict__ g2, const float* __restrict__ be2)
{
    extern __shared__ char dsm[];
    uint32_t sbase = smem_u32(dsm);

    int tid = threadIdx.x;
    int lane = tid & 31;
    int wid = tid >> 5;

    // B staging (fp16 hi/lo) with column permutation pi(8t+2q+r) = 8q+2t+r
    for (int p = tid; p < 32 * 128; p += 256) {
        int n = p >> 7;
        int k = p & 127;
        int t = n >> 3, q0 = (n >> 1) & 3, r = n & 1;
        int pn = 8 * q0 + 2 * t + r;
        float wv = W2[k * 32 + pn];
        __half hb = __float2half_rn(wv);
        __half lb = __float2half_rn(wv - __half2float(hb));
        *(__half*)(dsm + OFF_B_H + n * APITCH + k * 2) = hb;
        *(__half*)(dsm + OFF_B_L + n * APITCH + k * 2) = lb;
    }
    __syncthreads();

    float4 w32v = *(const float4*)&W1[32 * 128 + 4 * lane];
    float4 g1v  = *(const float4*)&g1[4 * lane];
    float4 be1v = *(const float4*)&be1[4 * lane];
    float4 b1vr;  // round-0 path uses ROUNDED b1 for exact-stat consistency
    {
        float4 b1v = *(const float4*)&b1[4 * lane];
        __half2 h01 = __float22half2_rn(make_float2(b1v.x, b1v.y));
        __half2 h23 = __float22half2_rn(make_float2(b1v.z, b1v.w));
        float2 r01 = __half22float2(h01);
        float2 r23 = __half22float2(h23);
        b1vr = make_float4(r01.x, r01.y, r23.x, r23.y);
    }

    float Sw = w32v.x + w32v.y + w32v.z + w32v.w;
    float Qw = w32v.x * w32v.x + w32v.y * w32v.y + w32v.z * w32v.z + w32v.w * w32v.w;
    float Sb = b1vr.x + b1vr.y + b1vr.z + b1vr.w;
    float Qb = b1vr.x * b1vr.x + b1vr.y * b1vr.y + b1vr.z * b1vr.z + b1vr.w * b1vr.w;
    float Pb = b1vr.x * w32v.x + b1vr.y * w32v.y + b1vr.z * w32v.z + b1vr.w * w32v.w;
#pragma unroll
    for (int o = 16; o; o >>= 1) {
        Sw += __shfl_xor_sync(FULL, Sw, o);
        Qw += __shfl_xor_sync(FULL, Qw, o);
        Sb += __shfl_xor_sync(FULL, Sb, o);
        Qb += __shfl_xor_sync(FULL, Qb, o);
        Pb += __shfl_xor_sync(FULL, Pb, o);
    }

    int q = lane & 3;
    int rA = lane >> 2;
    int rB = rA + 8;

    u64 b2p[4], g2p[4], be2p[4];
#pragma unroll
    for (int t = 0; t < 4; t++) {
        int c = 8 * q + 2 * t;
        b2p[t]  = pack2(b2[c],  b2[c + 1]);
        g2p[t]  = pack2(g2[c],  g2[c + 1]);
        be2p[t] = pack2(be2[c], be2[c + 1]);
    }
    const u64 C001 = pack2(NEG_SLOPE, NEG_SLOPE);

    // staging: tile0 at wid*2*AWARP, tile1 at +AWARP
    char* aStore = dsm + wid * 2 * AWARP + lane * 8;

    int aRow = lane & 15;
    int aColB = ((lane >> 4) & 1) * 16;
    uint32_t ldA0 = sbase + wid * 2 * AWARP + aRow * APITCH + aColB;
    uint32_t ldA1 = ldA0 + AWARP;

    int bRow = ((lane >> 4) & 1) * 8 + (lane & 7);
    int bKB = ((lane >> 3) & 1) * 16;
    uint32_t ldBH01 = sbase + OFF_B_H + bRow * APITCH + bKB;
    uint32_t ldBH23 = ldBH01 + 16 * APITCH;
    uint32_t ldBL01 = sbase + OFF_B_L + bRow * APITCH + bKB;
    uint32_t ldBL23 = ldBL01 + 16 * APITCH;

    const __half* __restrict__ yh = g_y;
    float* __restrict__ state_out = g_state;

    int ngroups = Ee / 32;          // 50000
    int wg = blockIdx.x * EDGE_WARPS + wid;
    int nw = gridDim.x * EDGE_WARPS;

    for (int g = wg; g < ngroups; g += nw) {
        int base = g * 32;

        // ---- distributed per-edge stats: lane l owns edge l ----
        float meanL, rstdL;
        {
            float cL = __ldg(&ec[base + lane]);
            float sL, qL;
            if constexpr (ROUND0) {
                sL = fmaf(cL, Sw, Sb);
                qL = fmaf(cL * cL, Qw, fmaf(2.f * cL, Pb, Qb));
            } else {
                int srcL = __ldg(&nf[base + lane]);
                float4 st = g_stats[srcL];
                sL = fmaf(cL, Sw, st.x);
                qL = fmaf(cL * cL, Qw, fmaf(2.f * cL, st.z, st.y));
            }
            meanL = sL * (1.f / 128.f);
            float varL = fmaf(qL, 1.f / 128.f, -meanL * meanL);
            rstdL = rsqrtf(varL + LN_EPS);
        }

        // ---- gather (fp16) + shfl'd LN1 + fp16 convert + stage (32 rows) ----
#pragma unroll
        for (int j = 0; j < 8; j++) {
            float4 C = *(const float4*)&ec[base + 4 * j];
            float cs[4] = {C.x, C.y, C.z, C.w};
            int srcs[4];
            if constexpr (!ROUND0) {
                int4 NF = *(const int4*)&nf[base + 4 * j];
                srcs[0] = NF.x; srcs[1] = NF.y; srcs[2] = NF.z; srcs[3] = NF.w;
            }
#pragma unroll
            for (int e = 0; e < 4; e++) {
                int row = 4 * j + e;                 // 0..31
                float c = cs[e];
                float mean = __shfl_sync(FULL, meanL, row);
                float rstd = __shfl_sync(FULL, rstdL, row);

                float4 a;
                if constexpr (ROUND0) {
                    a = b1vr;                         // y == round(b1)
                } else {
                    int src = srcs[e];
                    uint2 pk = *(const uint2*)&yh[src * Hh + 4 * lane];
                    float2 f01 = __half22float2(*(__half2*)&pk.x);
                    float2 f23 = __half22float2(*(__half2*)&pk.y);
                    a = make_float4(f01.x, f01.y, f23.x, f23.y);
                }
                a.x = fmaf(c, w32v.x, a.x);
                a.y = fmaf(c, w32v.y, a.y);
                a.z = fmaf(c, w32v.z, a.z);
                a.w = fmaf(c, w32v.w, a.w);

                float4 hv;
                hv.x = lrelu(fmaf((a.x - mean) * rstd, g1v.x, be1v.x));
                hv.y = lrelu(fmaf((a.y - mean) * rstd, g1v.y, be1v.y));
                hv.z = lrelu(fmaf((a.z - mean) * rstd, g1v.z, be1v.z));
                hv.w = lrelu(fmaf((a.w - mean) * rstd, g1v.w, be1v.w));

                __half2 h01 = __float22half2_rn(make_float2(hv.x, hv.y));
                __half2 h23 = __float22half2_rn(make_float2(hv.z, hv.w));
                u64 packh = (u64)(*(uint32_t*)&h01) | ((u64)(*(uint32_t*)&h23) << 32);
                char* dst = aStore + (row >> 4) * AWARP + (row & 15) * APITCH;
                *(u64*)dst = packh;
            }
        }
        __syncwarp();

        // hoist destination loads (latency hides behind MMA)
        int dstA0 = __ldg(&nt[base + rA]);
        int dstB0 = __ldg(&nt[base + rB]);
        int dstA1 = __ldg(&nt[base + 16 + rA]);
        int dstB1 = __ldg(&nt[base + 16 + rB]);

        // ---- MMA: D = A@Bh + A@Bl per tile; B fragments shared by both tiles
        float acc0[4][4], acc1[4][4];
#pragma unroll
        for (int t = 0; t < 4; t++)
#pragma unroll
            for (int j2 = 0; j2 < 4; j2++) { acc0[t][j2] = 0.f; acc1[t][j2] = 0.f; }

#pragma unroll
        for (int k = 0; k < 8; k++) {
            uint32_t bh01[4], bh23[4], bl01[4], bl23[4];
            ldsm4(bh01, ldBH01 + k * 32);
            ldsm4(bh23, ldBH23 + k * 32);
            ldsm4(bl01, ldBL01 + k * 32);
            ldsm4(bl23, ldBL23 + k * 32);

            uint32_t a0[4], a1[4];
            ldsm4(a0, ldA0 + k * 32);
            ldsm4(a1, ldA1 + k * 32);

            mma16816h(acc0[0], a0, bh01[0], bh01[1]);
            mma16816h(acc0[1], a0, bh01[2], bh01[3]);
            mma16816h(acc0[2], a0, bh23[0], bh23[1]);
            mma16816h(acc0[3], a0, bh23[2], bh23[3]);
            mma16816h(acc0[0], a0, bl01[0], bl01[1]);
            mma16816h(acc0[1], a0, bl01[2], bl01[3]);
            mma16816h(acc0[2], a0, bl23[0], bl23[1]);
            mma16816h(acc0[3], a0, bl23[2], bl23[3]);

            mma16816h(acc1[0], a1, bh01[0], bh01[1]);
            mma16816h(acc1[1], a1, bh01[2], bh01[3]);
            mma16816h(acc1[2], a1, bh23[0], bh23[1]);
            mma16816h(acc1[3], a1, bh23[2], bh23[3]);
            mma16816h(acc1[0], a1, bl01[0], bl01[1]);
            mma16816h(acc1[1], a1, bl01[2], bl01[3]);
            mma16816h(acc1[2], a1, bl23[0], bl23[1]);
            mma16816h(acc1[3], a1, bl23[2], bl23[3]);
        }
        __syncwarp();

        // ---- epilogues ----
        epilogue_tile(acc0, dstA0, dstB0, q, b2p, g2p, be2p, C001, state_out);
        epilogue_tile(acc1, dstA1, dstB1, q, b2p, g2p, be2p, C001, state_out);
    }
}

// ---------------------------------------------------------------------------
__global__ void graphsum_kernel(const int* __restrict__ ngi) {
    int t = blockIdx.x * blockDim.x + threadIdx.x;
    int total = Nn * (Ss / 4);
    if (t >= total) return;
    int n = t >> 3;
    int q = t & 7;
    const float4* s = reinterpret_cast<const float4*>(g_state);
    float4 v = s[t];
    int g = ngi[n];
    atomicAdd(reinterpret_cast<float4*>(&g_gs[g * Ss + 4 * q]), v);
}

// ---------------------------------------------------------------------------
__global__ void __launch_bounds__(128) readout_kernel(
    const float* __restrict__ Wo1, const float* __restrict__ bo1,
    const float* __restrict__ go, const float* __restrict__ beo,
    const float* __restrict__ Wo2, const float* __restrict__ bo2,
    float* __restrict__ out)
{
    __shared__ float sW[32 * 128];
    __shared__ float sb[128], sg[128], sbe[128];
    __shared__ float sW2[256];
    __shared__ float sb2[2];

    int tid = threadIdx.x;
    for (int i = tid; i < 32 * 128; i += 128) sW[i] = Wo1[i];
    sb[tid] = bo1[tid]; sg[tid] = go[tid]; sbe[tid] = beo[tid];
    sW2[tid] = Wo2[tid];
    sW2[tid + 128] = Wo2[tid + 128];
    if (tid < 2) sb2[tid] = bo2[tid];
    __syncthreads();

    int lane = tid & 31;
    int w = tid >> 5;
    int g = blockIdx.x * 4 + w;
    if (g >= Gg) return;

    float x = g_gs[g * Ss + lane];
    float4 a;
    a.x = sb[4 * lane]; a.y = sb[4 * lane + 1]; a.z = sb[4 * lane + 2]; a.w = sb[4 * lane + 3];
#pragma unroll
    for (int i = 0; i < 32; i++) {
        float xi = __shfl_sync(FULL, x, i);
        float4 wv = *(const float4*)&sW[i * 128 + 4 * lane];
        a.x += xi * wv.x; a.y += xi * wv.y; a.z += xi * wv.z; a.w += xi * wv.w;
    }
    float s = a.x + a.y + a.z + a.w;
    float s2 = a.x * a.x + a.y * a.y + a.z * a.z + a.w * a.w;
#pragma unroll
    for (int o = 16; o; o >>= 1) {
        s += __shfl_xor_sync(FULL, s, o);
        s2 += __shfl_xor_sync(FULL, s2, o);
    }
    float mean = s * (1.f / 128.f);
    float var = s2 * (1.f / 128.f) - mean * mean;
    float rstd = rsqrtf(var + LN_EPS);
    float h0 = lrelu((a.x - mean) * rstd * sg[4 * lane + 0] + sbe[4 * lane + 0]);
    float h1 = lrelu((a.y - mean) * rstd * sg[4 * lane + 1] + sbe[4 * lane + 1]);
    float h2 = lrelu((a.z - mean) * rstd * sg[4 * lane + 2] + sbe[4 * lane + 2]);
    float h3 = lrelu((a.w - mean) * rstd * sg[4 * lane + 3] + sbe[4 * lane + 3]);

    float p0 = h0 * sW2[(4 * lane + 0) * 2] + h1 * sW2[(4 * lane + 1) * 2]
             + h2 * sW2[(4 * lane + 2) * 2] + h3 * sW2[(4 * lane + 3) * 2];
    float p1 = h0 * sW2[(4 * lane + 0) * 2 + 1] + h1 * sW2[(4 * lane + 1) * 2 + 1]
             + h2 * sW2[(4 * lane + 2) * 2 + 1] + h3 * sW2[(4 * lane + 3) * 2 + 1];
#pragma unroll
    for (int o = 16; o; o >>= 1) {
        p0 += __shfl_xor_sync(FULL, p0, o);
        p1 += __shfl_xor_sync(FULL, p1, o);
    }
    if (lane == 0) {
        float mu = p0 + sb2[0];
        float v = p1 + sb2[1];
        float sp = (v > 0.f) ? v + log1pf(expf(-v)) : log1pf(expf(v));
        out[g * 2 + 0] = mu;
        out[g * 2 + 1] = sp;
    }
}

// ---------------------------------------------------------------------------
extern "C" void kernel_launch(void* const* d_in, const int* in_sizes, int n_in,
                              void* d_out, int out_size) {
    const int* nf = (const int*)d_in[0];
    const int* nt = (const int*)d_in[1];
    const float* ec = (const float*)d_in[2];
    const int* ngi = (const int*)d_in[3];
    const float* W1 = (const float*)d_in[6];
    const float* b1 = (const float*)d_in[7];
    const float* g1 = (const float*)d_in[8];
    const float* be1 = (const float*)d_in[9];
    const float* W2 = (const float*)d_in[10];
    const float* b2 = (const float*)d_in[11];
    const float* g2 = (const float*)d_in[12];
    const float* be2 = (const float*)d_in[13];
    const float* Wo1 = (const float*)d_in[14];
    const float* bo1 = (const float*)d_in[15];
    const float* go = (const float*)d_in[16];
    const float* beo = (const float*)d_in[17];
    const float* Wo2 = (const float*)d_in[18];
    const float* bo2 = (const float*)d_in[19];
    float* out = (float*)d_out;

    cudaFuncSetAttribute(edge_kernel<true>, cudaFuncAttributeMaxDynamicSharedMemorySize, EDGE_DSMEM);
    cudaFuncSetAttribute(edge_kernel<false>, cudaFuncAttributeMaxDynamicSharedMemorySize, EDGE_DSMEM);

    zero_kernel<<<4096, 256>>>();

    // round 0: state == 0 -> y == round(b1) uniform; skip node_gemm, no gather
    edge_kernel<true><<<EDGE_GRID, 256, EDGE_DSMEM>>>(nf, nt, ec,
                                                      W1, b1, g1, be1, W2, b2, g2, be2);
    // rounds 1..4
    for (int r = 1; r < ROUNDS; r++) {
        node_gemm_kernel<<<1024, 192>>>(W1, b1);
        edge_kernel<false><<<EDGE_GRID, 256, EDGE_DSMEM>>>(nf, nt, ec,
                                                           W1, b1, g1, be1, W2, b2, g2, be2);
    }

    graphsum_kernel<<<(Nn * 8 + 255) / 256, 256>>>(ngi);
    readout_kernel<<<(Gg + 3) / 4, 128>>>(Wo1, bo1, go, beo, Wo2, bo2, out);
}

// round 16
// speedup vs baseline: 1.8358x; 1.0522x over previous
#include <cuda_runtime.h>
#include <cuda_fp16.h>
#include <math.h>
#include <stdint.h>

#define FULL 0xffffffffu
typedef unsigned long long u64;

constexpr int Nn = 100000;
constexpr int Ee = 1600000;
constexpr int Gg = 1000;
constexpr int Ss = 32;
constexpr int Hh = 128;
constexpr int ROUNDS = 5;
constexpr float NEG_SLOPE = 0.01f;
constexpr float LN_EPS = 1e-5f;

constexpr int APITCH = 272;
constexpr int AWARP = 16 * APITCH;
constexpr int EDGE_WARPS = 8;                       // 256-thread blocks
constexpr int OFF_B_H = EDGE_WARPS * 2 * AWARP;     // 69632
constexpr int OFF_B_L = OFF_B_H + 32 * APITCH;      // 78336
constexpr int EDGE_DSMEM = OFF_B_L + 32 * APITCH;   // 87040  (2 blocks/SM, 16 warps/SM)
constexpr int EDGE_GRID = 296;

__device__ float g_state[Nn * Ss];
__device__ __half g_y[Nn * Hh];          // fp16 y (25.6MB)
__device__ float4 g_stats[Nn];           // stats computed from ROUNDED y
__device__ float g_gs[Gg * Ss];

__device__ __forceinline__ float lrelu(float v) { return v >= 0.f ? v : NEG_SLOPE * v; }

// ---- packed f32x2 helpers ----
__device__ __forceinline__ u64 pack2(float lo, float hi) {
    u64 r; asm("mov.b64 %0,{%1,%2};" : "=l"(r) : "f"(lo), "f"(hi)); return r;
}
__device__ __forceinline__ void unpack2(u64 v, float& lo, float& hi) {
    asm("mov.b64 {%0,%1},%2;" : "=f"(lo), "=f"(hi) : "l"(v));
}
__device__ __forceinline__ u64 fma2(u64 a, u64 b, u64 c) {
    u64 d; asm("fma.rn.f32x2 %0,%1,%2,%3;" : "=l"(d) : "l"(a), "l"(b), "l"(c)); return d;
}
__device__ __forceinline__ u64 add2(u64 a, u64 b) {
    u64 d; asm("add.rn.f32x2 %0,%1,%2;" : "=l"(d) : "l"(a), "l"(b)); return d;
}
__device__ __forceinline__ u64 mul2(u64 a, u64 b) {
    u64 d; asm("mul.rn.f32x2 %0,%1,%2;" : "=l"(d) : "l"(a), "l"(b)); return d;
}

__device__ __forceinline__ uint32_t smem_u32(const void* p) {
    uint32_t a;
    asm("{ .reg .u64 t; cvta.to.shared.u64 t, %1; cvt.u32.u64 %0, t; }" : "=r"(a) : "l"(p));
    return a;
}

__device__ __forceinline__ void ldsm4(uint32_t r[4], uint32_t addr) {
    asm volatile("ldmatrix.sync.aligned.m8n8.x4.shared.b16 {%0,%1,%2,%3}, [%4];"
                 : "=r"(r[0]), "=r"(r[1]), "=r"(r[2]), "=r"(r[3]) : "r"(addr));
}

__device__ __forceinline__ void mma16816h(float acc[4], const uint32_t a[4],
                                          uint32_t b0, uint32_t b1) {
    asm volatile(
        "mma.sync.aligned.m16n8k16.row.col.f32.f16.f16.f32 "
        "{%0,%1,%2,%3}, {%4,%5,%6,%7}, {%8,%9}, {%0,%1,%2,%3};"
        : "+f"(acc[0]), "+f"(acc[1]), "+f"(acc[2]), "+f"(acc[3])
        : "r"(a[0]), "r"(a[1]), "r"(a[2]), "r"(a[3]), "r"(b0), "r"(b1));
}

__device__ __forceinline__ uint32_t h2bits(__half2 h) { return *(uint32_t*)&h; }
__device__ __forceinline__ __half2 bits2h(uint32_t u) { return *(__half2*)&u; }

// ---------------------------------------------------------------------------
__global__ void zero_kernel() {
    int i = blockIdx.x * blockDim.x + threadIdx.x;
    int stride = gridDim.x * blockDim.x;
    for (int k = i; k < Nn * Ss; k += stride) g_state[k] = 0.f;
    for (int k = i; k < Gg * Ss; k += stride) g_gs[k] = 0.f;
}

// ---------------------------------------------------------------------------
// y = fp16(state @ W1[:32] + b1) ; stats (Sy,Qy,P) from ROUNDED values and
// ROUNDED w32 (consistent with the edge kernel's half2 arithmetic).
__global__ void __launch_bounds__(192) node_gemm_kernel(
    const float* __restrict__ W1, const float* __restrict__ b1)
{
    __shared__ float sW1[32 * 128];
    __shared__ float sb1[128];
    const float* __restrict__ state_in = g_state;

    int tid = threadIdx.x;
    for (int i = tid; i < 32 * 128; i += 192) sW1[i] = W1[i];
    if (tid < 128) sb1[tid] = b1[tid];
    __syncthreads();

    int lane = tid & 31;
    int w = tid >> 5;
    int warp_global = blockIdx.x * 6 + w;
    int nwarps = gridDim.x * 6;
    int ngroups = Nn / 4;

    float4 b1v = *(const float4*)&sb1[4 * lane];
    // rounded w32 (matches edge kernel half2 math)
    float4 w32v;
    {
        float4 wr = *(const float4*)&W1[32 * 128 + 4 * lane];
        __half2 h01 = __float22half2_rn(make_float2(wr.x, wr.y));
        __half2 h23 = __float22half2_rn(make_float2(wr.z, wr.w));
        float2 f01 = __half22float2(h01);
        float2 f23 = __half22float2(h23);
        w32v = make_float4(f01.x, f01.y, f23.x, f23.y);
    }

    for (int g = warp_global; g < ngroups; g += nwarps) {
        int nbase = g * 4;
        float x0 = state_in[(nbase + 0) * Ss + lane];
        float x1 = state_in[(nbase + 1) * Ss + lane];
        float x2 = state_in[(nbase + 2) * Ss + lane];
        float x3 = state_in[(nbase + 3) * Ss + lane];

        float4 a0 = b1v, a1 = b1v, a2 = b1v, a3 = b1v;
#pragma unroll
        for (int i = 0; i < 32; i++) {
            float4 wv = *(const float4*)&sW1[i * 128 + 4 * lane];
            float s0 = __shfl_sync(FULL, x0, i);
            float s1 = __shfl_sync(FULL, x1, i);
            float s2 = __shfl_sync(FULL, x2, i);
            float s3 = __shfl_sync(FULL, x3, i);
            a0.x += s0 * wv.x; a0.y += s0 * wv.y; a0.z += s0 * wv.z; a0.w += s0 * wv.w;
            a1.x += s1 * wv.x; a1.y += s1 * wv.y; a1.z += s1 * wv.z; a1.w += s1 * wv.w;
            a2.x += s2 * wv.x; a2.y += s2 * wv.y; a2.z += s2 * wv.z; a2.w += s2 * wv.w;
            a3.x += s3 * wv.x; a3.y += s3 * wv.y; a3.z += s3 * wv.z; a3.w += s3 * wv.w;
        }

#pragma unroll
        for (int e = 0; e < 4; e++) {
            float4 a = (e == 0) ? a0 : (e == 1) ? a1 : (e == 2) ? a2 : a3;
            __half2 h01 = __float22half2_rn(make_float2(a.x, a.y));
            __half2 h23 = __float22half2_rn(make_float2(a.z, a.w));
            uint2 pk;
            pk.x = h2bits(h01);
            pk.y = h2bits(h23);
            *(uint2*)&g_y[(nbase + e) * Hh + 4 * lane] = pk;

            float2 r01 = __half22float2(h01);
            float2 r23 = __half22float2(h23);
            float rx = r01.x, ry = r01.y, rz = r23.x, rw = r23.y;
            float s = rx + ry + rz + rw;
            float q = rx * rx + ry * ry + rz * rz + rw * rw;
            float p = rx * w32v.x + ry * w32v.y + rz * w32v.z + rw * w32v.w;
#pragma unroll
            for (int o = 16; o; o >>= 1) {
                s += __shfl_xor_sync(FULL, s, o);
                q += __shfl_xor_sync(FULL, q, o);
                p += __shfl_xor_sync(FULL, p, o);
            }
            if (lane == 0) g_stats[nbase + e] = make_float4(s, q, p, 0.f);
        }
    }
}

// ---------------------------------------------------------------------------
// per-tile epilogue: packed bias + LN2 (quad reduce) + 4 float4 atomics
__device__ __forceinline__ void epilogue_tile(
    const float acc[4][4], int dstA, int dstB, int q,
    const u64 b2p[4], const u64 g2p[4], const u64 be2p[4], u64 C001,
    float* __restrict__ state_out)
{
    u64 mA[4], mB[4];
#pragma unroll
    for (int t = 0; t < 4; t++) {
        mA[t] = add2(pack2(acc[t][0], acc[t][1]), b2p[t]);
        mB[t] = add2(pack2(acc[t][2], acc[t][3]), b2p[t]);
    }
    u64 sA2 = add2(add2(mA[0], mA[1]), add2(mA[2], mA[3]));
    u64 sB2 = add2(add2(mB[0], mB[1]), add2(mB[2], mB[3]));
    u64 qA2 = fma2(mA[0], mA[0], fma2(mA[1], mA[1], fma2(mA[2], mA[2], mul2(mA[3], mA[3]))));
    u64 qB2 = fma2(mB[0], mB[0], fma2(mB[1], mB[1], fma2(mB[2], mB[2], mul2(mB[3], mB[3]))));
    float t0, t1;
    unpack2(sA2, t0, t1); float sA = t0 + t1;
    unpack2(qA2, t0, t1); float qA = t0 + t1;
    unpack2(sB2, t0, t1); float sB = t0 + t1;
    unpack2(qB2, t0, t1); float qB = t0 + t1;
#pragma unroll
    for (int o = 2; o; o >>= 1) {
        sA += __shfl_xor_sync(FULL, sA, o);
        qA += __shfl_xor_sync(FULL, qA, o);
        sB += __shfl_xor_sync(FULL, sB, o);
        qB += __shfl_xor_sync(FULL, qB, o);
    }
    float meanA = sA * (1.f / 32.f);
    float rstdA = rsqrtf(qA * (1.f / 32.f) - meanA * meanA + LN_EPS);
    float meanB = sB * (1.f / 32.f);
    float rstdB = rsqrtf(qB * (1.f / 32.f) - meanB * meanB + LN_EPS);

    u64 rA2p = pack2(rstdA, rstdA), nmA2 = pack2(-meanA, -meanA);
    u64 rB2p = pack2(rstdB, rstdB), nmB2 = pack2(-meanB, -meanB);

    float vA[8], vB[8];
#pragma unroll
    for (int t = 0; t < 4; t++) {
        u64 agA = mul2(rA2p, g2p[t]);
        u64 offA = fma2(nmA2, agA, be2p[t]);
        u64 hA = fma2(mA[t], agA, offA);
        u64 pA = mul2(hA, C001);
        float h0, h1, p0, p1;
        unpack2(hA, h0, h1); unpack2(pA, p0, p1);
        vA[2 * t] = fmaxf(h0, p0); vA[2 * t + 1] = fmaxf(h1, p1);

        u64 agB = mul2(rB2p, g2p[t]);
        u64 offB = fma2(nmB2, agB, be2p[t]);
        u64 hB = fma2(mB[t], agB, offB);
        u64 pB = mul2(hB, C001);
        unpack2(hB, h0, h1); unpack2(pB, p0, p1);
        vB[2 * t] = fmaxf(h0, p0); vB[2 * t + 1] = fmaxf(h1, p1);
    }

    float* rowA = &state_out[dstA * Ss + 8 * q];
    float* rowB = &state_out[dstB * Ss + 8 * q];
    atomicAdd((float4*)&rowA[0], make_float4(vA[0], vA[1], vA[2], vA[3]));
    atomicAdd((float4*)&rowA[4], make_float4(vA[4], vA[5], vA[6], vA[7]));
    atomicAdd((float4*)&rowB[0], make_float4(vB[0], vB[1], vB[2], vB[3]));
    atomicAdd((float4*)&rowB[4], make_float4(vB[4], vB[5], vB[6], vB[7]));
}

// ---------------------------------------------------------------------------
// Edge kernel: half2 LN1 prologue (no fp32 round-trips), distributed stats,
// fp16 A single / B hi-lo, 32-edge groups with B reuse. Same 87KB config.
template <bool ROUND0>
__global__ void __launch_bounds__(256, 2) edge_kernel(
    const int* __restrict__ nf, const int* __restrict__ nt,
    const float* __restrict__ ec,
    const float* __restrict__ W1, const float* __restrict__ b1,
    const float* __restrict__ g1, const float* __restrict__ be1,
    const float* __restrict__ W2, const float* __restrict__ b2,
    const float* __restrict__ g2, const float* __restrict__ be2)
{
    extern __shared__ char dsm[];
    uint32_t sbase = smem_u32(dsm);

    int tid = threadIdx.x;
    int lane = tid & 31;
    int wid = tid >> 5;

    // B staging (fp16 hi/lo) with column permutation pi(8t+2q+r) = 8q+2t+r
    for (int p = tid; p < 32 * 128; p += 256) {
        int n = p >> 7;
        int k = p & 127;
        int t = n >> 3, q0 = (n >> 1) & 3, r = n & 1;
        int pn = 8 * q0 + 2 * t + r;
        float wv = W2[k * 32 + pn];
        __half hb = __float2half_rn(wv);
        __half lb = __float2half_rn(wv - __half2float(hb));
        *(__half*)(dsm + OFF_B_H + n * APITCH + k * 2) = hb;
        *(__half*)(dsm + OFF_B_L + n * APITCH + k * 2) = lb;
    }
    __syncthreads();

    // per-lane constants: rounded w32 / b1 as half2 AND rounded floats for stats
    __half2 w32h0, w32h1, b1h0, b1h1, g1h0, g1h1, be1h0, be1h1;
    float4 w32v, b1vr;
    {
        float4 wr = *(const float4*)&W1[32 * 128 + 4 * lane];
        w32h0 = __float22half2_rn(make_float2(wr.x, wr.y));
        w32h1 = __float22half2_rn(make_float2(wr.z, wr.w));
        float2 f0 = __half22float2(w32h0), f1 = __half22float2(w32h1);
        w32v = make_float4(f0.x, f0.y, f1.x, f1.y);

        float4 bv = *(const float4*)&b1[4 * lane];
        b1h0 = __float22half2_rn(make_float2(bv.x, bv.y));
        b1h1 = __float22half2_rn(make_float2(bv.z, bv.w));
        float2 g0 = __half22float2(b1h0), g1f = __half22float2(b1h1);
        b1vr = make_float4(g0.x, g0.y, g1f.x, g1f.y);

        float4 gv = *(const float4*)&g1[4 * lane];
        g1h0 = __float22half2_rn(make_float2(gv.x, gv.y));
        g1h1 = __float22half2_rn(make_float2(gv.z, gv.w));
        float4 bev = *(const float4*)&be1[4 * lane];
        be1h0 = __float22half2_rn(make_float2(bev.x, bev.y));
        be1h1 = __float22half2_rn(make_float2(bev.z, bev.w));
    }

    float Sw = w32v.x + w32v.y + w32v.z + w32v.w;
    float Qw = w32v.x * w32v.x + w32v.y * w32v.y + w32v.z * w32v.z + w32v.w * w32v.w;
    float Sb = b1vr.x + b1vr.y + b1vr.z + b1vr.w;
    float Qb = b1vr.x * b1vr.x + b1vr.y * b1vr.y + b1vr.z * b1vr.z + b1vr.w * b1vr.w;
    float Pb = b1vr.x * w32v.x + b1vr.y * w32v.y + b1vr.z * w32v.z + b1vr.w * w32v.w;
#pragma unroll
    for (int o = 16; o; o >>= 1) {
        Sw += __shfl_xor_sync(FULL, Sw, o);
        Qw += __shfl_xor_sync(FULL, Qw, o);
        Sb += __shfl_xor_sync(FULL, Sb, o);
        Qb += __shfl_xor_sync(FULL, Qb, o);
        Pb += __shfl_xor_sync(FULL, Pb, o);
    }

    int q = lane & 3;
    int rA = lane >> 2;
    int rB = rA + 8;

    u64 b2p[4], g2p[4], be2p[4];
#pragma unroll
    for (int t = 0; t < 4; t++) {
        int c = 8 * q + 2 * t;
        b2p[t]  = pack2(b2[c],  b2[c + 1]);
        g2p[t]  = pack2(g2[c],  g2[c + 1]);
        be2p[t] = pack2(be2[c], be2[c + 1]);
    }
    const u64 C001 = pack2(NEG_SLOPE, NEG_SLOPE);
    const __half2 slope2 = __float2half2_rn(NEG_SLOPE);

    char* aStore = dsm + wid * 2 * AWARP + lane * 8;

    int aRow = lane & 15;
    int aColB = ((lane >> 4) & 1) * 16;
    uint32_t ldA0 = sbase + wid * 2 * AWARP + aRow * APITCH + aColB;
    uint32_t ldA1 = ldA0 + AWARP;

    int bRow = ((lane >> 4) & 1) * 8 + (lane & 7);
    int bKB = ((lane >> 3) & 1) * 16;
    uint32_t ldBH01 = sbase + OFF_B_H + bRow * APITCH + bKB;
    uint32_t ldBH23 = ldBH01 + 16 * APITCH;
    uint32_t ldBL01 = sbase + OFF_B_L + bRow * APITCH + bKB;
    uint32_t ldBL23 = ldBL01 + 16 * APITCH;

    const __half* __restrict__ yh = g_y;
    float* __restrict__ state_out = g_state;

    int ngroups = Ee / 32;          // 50000
    int wg = blockIdx.x * EDGE_WARPS + wid;
    int nw = gridDim.x * EDGE_WARPS;

    for (int g = wg; g < ngroups; g += nw) {
        int base = g * 32;

        // ---- distributed per-edge stats: lane l owns edge l; packs half2 ----
        uint32_t nm2L, r2L;
        {
            float cL = __ldg(&ec[base + lane]);
            float sL, qL;
            if constexpr (ROUND0) {
                sL = fmaf(cL, Sw, Sb);
                qL = fmaf(cL * cL, Qw, fmaf(2.f * cL, Pb, Qb));
            } else {
                int srcL = __ldg(&nf[base + lane]);
                float4 st = g_stats[srcL];
                sL = fmaf(cL, Sw, st.x);
                qL = fmaf(cL * cL, Qw, fmaf(2.f * cL, st.z, st.y));
            }
            float meanL = sL * (1.f / 128.f);
            float varL = fmaf(qL, 1.f / 128.f, -meanL * meanL);
            float rstdL = rsqrtf(varL + LN_EPS);
            nm2L = h2bits(__float2half2_rn(-meanL));
            r2L  = h2bits(__float2half2_rn(rstdL));
        }

        // ---- gather + half2 LN1 + stage (32 rows) ----
#pragma unroll
        for (int j = 0; j < 8; j++) {
            float4 C = *(const float4*)&ec[base + 4 * j];
            float cs[4] = {C.x, C.y, C.z, C.w};
            int srcs[4];
            if constexpr (!ROUND0) {
                int4 NF = *(const int4*)&nf[base + 4 * j];
                srcs[0] = NF.x; srcs[1] = NF.y; srcs[2] = NF.z; srcs[3] = NF.w;
            }
#pragma unroll
            for (int e = 0; e < 4; e++) {
                int row = 4 * j + e;                 // 0..31
                __half2 nmh = bits2h(__shfl_sync(FULL, nm2L, row));
                __half2 rh  = bits2h(__shfl_sync(FULL, r2L, row));

                __half2 a0h, a1h;
                if constexpr (ROUND0) {
                    a0h = b1h0; a1h = b1h1;
                } else {
                    uint2 pk = *(const uint2*)&yh[srcs[e] * Hh + 4 * lane];
                    a0h = bits2h(pk.x);
                    a1h = bits2h(pk.y);
                }
                __half2 c2 = __float2half2_rn(cs[e]);
                a0h = __hfma2(c2, w32h0, a0h);
                a1h = __hfma2(c2, w32h1, a1h);

                __half2 rg0 = __hmul2(rh, g1h0);
                __half2 rg1 = __hmul2(rh, g1h1);
                __half2 off0 = __hfma2(nmh, rg0, be1h0);
                __half2 off1 = __hfma2(nmh, rg1, be1h1);
                __half2 h0 = __hfma2(a0h, rg0, off0);
                __half2 h1 = __hfma2(a1h, rg1, off1);
                h0 = __hmax2(h0, __hmul2(h0, slope2));
                h1 = __hmax2(h1, __hmul2(h1, slope2));

                u64 packh = (u64)h2bits(h0) | ((u64)h2bits(h1) << 32);
                char* dst = aStore + (row >> 4) * AWARP + (row & 15) * APITCH;
                *(u64*)dst = packh;
            }
        }
        __syncwarp();

        // hoist destination loads (latency hides behind MMA)
        int dstA0 = __ldg(&nt[base + rA]);
        int dstB0 = __ldg(&nt[base + rB]);
        int dstA1 = __ldg(&nt[base + 16 + rA]);
        int dstB1 = __ldg(&nt[base + 16 + rB]);

        // ---- MMA: D = A@Bh + A@Bl per tile; B fragments shared by both tiles
        float acc0[4][4], acc1[4][4];
#pragma unroll
        for (int t = 0; t < 4; t++)
#pragma unroll
            for (int j2 = 0; j2 < 4; j2++) { acc0[t][j2] = 0.f; acc1[t][j2] = 0.f; }

#pragma unroll
        for (int k = 0; k < 8; k++) {
            uint32_t bh01[4], bh23[4], bl01[4], bl23[4];
            ldsm4(bh01, ldBH01 + k * 32);
            ldsm4(bh23, ldBH23 + k * 32);
            ldsm4(bl01, ldBL01 + k * 32);
            ldsm4(bl23, ldBL23 + k * 32);

            uint32_t a0[4], a1[4];
            ldsm4(a0, ldA0 + k * 32);
            ldsm4(a1, ldA1 + k * 32);

            mma16816h(acc0[0], a0, bh01[0], bh01[1]);
            mma16816h(acc0[1], a0, bh01[2], bh01[3]);
            mma16816h(acc0[2], a0, bh23[0], bh23[1]);
            mma16816h(acc0[3], a0, bh23[2], bh23[3]);
            mma16816h(acc0[0], a0, bl01[0], bl01[1]);
            mma16816h(acc0[1], a0, bl01[2], bl01[3]);
            mma16816h(acc0[2], a0, bl23[0], bl23[1]);
            mma16816h(acc0[3], a0, bl23[2], bl23[3]);

            mma16816h(acc1[0], a1, bh01[0], bh01[1]);
            mma16816h(acc1[1], a1, bh01[2], bh01[3]);
            mma16816h(acc1[2], a1, bh23[0], bh23[1]);
            mma16816h(acc1[3], a1, bh23[2], bh23[3]);
            mma16816h(acc1[0], a1, bl01[0], bl01[1]);
            mma16816h(acc1[1], a1, bl01[2], bl01[3]);
            mma16816h(acc1[2], a1, bl23[0], bl23[1]);
            mma16816h(acc1[3], a1, bl23[2], bl23[3]);
        }
        __syncwarp();

        // ---- epilogues ----
        epilogue_tile(acc0, dstA0, dstB0, q, b2p, g2p, be2p, C001, state_out);
        epilogue_tile(acc1, dstA1, dstB1, q, b2p, g2p, be2p, C001, state_out);
    }
}

// ---------------------------------------------------------------------------
__global__ void graphsum_kernel(const int* __restrict__ ngi) {
    int t = blockIdx.x * blockDim.x + threadIdx.x;
    int total = Nn * (Ss / 4);
    if (t >= total) return;
    int n = t >> 3;
    int q = t & 7;
    const float4* s = reinterpret_cast<const float4*>(g_state);
    float4 v = s[t];
    int g = ngi[n];
    atomicAdd(reinterpret_cast<float4*>(&g_gs[g * Ss + 4 * q]), v);
}

// ---------------------------------------------------------------------------
__global__ void __launch_bounds__(128) readout_kernel(
    const float* __restrict__ Wo1, const float* __restrict__ bo1,
    const float* __restrict__ go, const float* __restrict__ beo,
    const float* __restrict__ Wo2, const float* __restrict__ bo2,
    float* __restrict__ out)
{
    __shared__ float sW[32 * 128];
    __shared__ float sb[128], sg[128], sbe[128];
    __shared__ float sW2[256];
    __shared__ float sb2[2];

    int tid = threadIdx.x;
    for (int i = tid; i < 32 * 128; i += 128) sW[i] = Wo1[i];
    sb[tid] = bo1[tid]; sg[tid] = go[tid]; sbe[tid] = beo[tid];
    sW2[tid] = Wo2[tid];
    sW2[tid + 128] = Wo2[tid + 128];
    if (tid < 2) sb2[tid] = bo2[tid];
    __syncthreads();

    int lane = tid & 31;
    int w = tid >> 5;
    int g = blockIdx.x * 4 + w;
    if (g >= Gg) return;

    float x = g_gs[g * Ss + lane];
    float4 a;
    a.x = sb[4 * lane]; a.y = sb[4 * lane + 1]; a.z = sb[4 * lane + 2]; a.w = sb[4 * lane + 3];
#pragma unroll
    for (int i = 0; i < 32; i++) {
        float xi = __shfl_sync(FULL, x, i);
        float4 wv = *(const float4*)&sW[i * 128 + 4 * lane];
        a.x += xi * wv.x; a.y += xi * wv.y; a.z += xi * wv.z; a.w += xi * wv.w;
    }
    float s = a.x + a.y + a.z + a.w;
    float s2 = a.x * a.x + a.y * a.y + a.z * a.z + a.w * a.w;
#pragma unroll
    for (int o = 16; o; o >>= 1) {
        s += __shfl_xor_sync(FULL, s, o);
        s2 += __shfl_xor_sync(FULL, s2, o);
    }
    float mean = s * (1.f / 128.f);
    float var = s2 * (1.f / 128.f) - mean * mean;
    float rstd = rsqrtf(var + LN_EPS);
    float h0 = lrelu((a.x - mean) * rstd * sg[4 * lane + 0] + sbe[4 * lane + 0]);
    float h1 = lrelu((a.y - mean) * rstd * sg[4 * lane + 1] + sbe[4 * lane + 1]);
    float h2 = lrelu((a.z - mean) * rstd * sg[4 * lane + 2] + sbe[4 * lane + 2]);
    float h3 = lrelu((a.w - mean) * rstd * sg[4 * lane + 3] + sbe[4 * lane + 3]);

    float p0 = h0 * sW2[(4 * lane + 0) * 2] + h1 * sW2[(4 * lane + 1) * 2]
             + h2 * sW2[(4 * lane + 2) * 2] + h3 * sW2[(4 * lane + 3) * 2];
    float p1 = h0 * sW2[(4 * lane + 0) * 2 + 1] + h1 * sW2[(4 * lane + 1) * 2 + 1]
             + h2 * sW2[(4 * lane + 2) * 2 + 1] + h3 * sW2[(4 * lane + 3) * 2 + 1];
#pragma unroll
    for (int o = 16; o; o >>= 1) {
        p0 += __shfl_xor_sync(FULL, p0, o);
        p1 += __shfl_xor_sync(FULL, p1, o);
    }
    if (lane == 0) {
        float mu = p0 + sb2[0];
        float v = p1 + sb2[1];
        float sp = (v > 0.f) ? v + log1pf(expf(-v)) : log1pf(expf(v));
        out[g * 2 + 0] = mu;
        out[g * 2 + 1] = sp;
    }
}

// ---------------------------------------------------------------------------
extern "C" void kernel_launch(void* const* d_in, const int* in_sizes, int n_in,
                              void* d_out, int out_size) {
    const int* nf = (const int*)d_in[0];
    const int* nt = (const int*)d_in[1];
    const float* ec = (const float*)d_in[2];
    const int* ngi = (const int*)d_in[3];
    const float* W1 = (const float*)d_in[6];
    const float* b1 = (const float*)d_in[7];
    const float* g1 = (const float*)d_in[8];
    const float* be1 = (const float*)d_in[9];
    const float* W2 = (const float*)d_in[10];
    const float* b2 = (const float*)d_in[11];
    const float* g2 = (const float*)d_in[12];
    const float* be2 = (const float*)d_in[13];
    const float* Wo1 = (const float*)d_in[14];
    const float* bo1 = (const float*)d_in[15];
    const float* go = (const float*)d_in[16];
    const float* beo = (const float*)d_in[17];
    const float* Wo2 = (const float*)d_in[18];
    const float* bo2 = (const float*)d_in[19];
    float* out = (float*)d_out;

    cudaFuncSetAttribute(edge_kernel<true>, cudaFuncAttributeMaxDynamicSharedMemorySize, EDGE_DSMEM);
    cudaFuncSetAttribute(edge_kernel<false>, cudaFuncAttributeMaxDynamicSharedMemorySize, EDGE_DSMEM);

    zero_kernel<<<4096, 256>>>();

    // round 0: state == 0 -> y == round(b1) uniform; skip node_gemm, no gather
    edge_kernel<true><<<EDGE_GRID, 256, EDGE_DSMEM>>>(nf, nt, ec,
                                                      W1, b1, g1, be1, W2, b2, g2, be2);
    // rounds 1..4
    for (int r = 1; r < ROUNDS; r++) {
        node_gemm_kernel<<<1024, 192>>>(W1, b1);
        edge_kernel<false><<<EDGE_GRID, 256, EDGE_DSMEM>>>(nf, nt, ec,
                                                           W1, b1, g1, be1, W2, b2, g2, be2);
    }

    graphsum_kernel<<<(Nn * 8 + 255) / 256, 256>>>(ngi);
    readout_kernel<<<(Gg + 3) / 4, 128>>>(Wo1, bo1, go, beo, Wo2, bo2, out);
}

// round 17
// speedup vs baseline: 1.9812x; 1.0792x over previous
#include <cuda_runtime.h>
#include <cuda_fp16.h>
#include <math.h>
#include <stdint.h>

#define FULL 0xffffffffu
typedef unsigned long long u64;

constexpr int Nn = 100000;
constexpr int Ee = 1600000;
constexpr int Gg = 1000;
constexpr int Ss = 32;
constexpr int Hh = 128;
constexpr int ROUNDS = 5;
constexpr float NEG_SLOPE = 0.01f;
constexpr float LN_EPS = 1e-5f;

constexpr int APITCH = 272;
constexpr int AWARP = 16 * APITCH;
constexpr int EDGE_WARPS = 8;                       // 256-thread blocks
constexpr int OFF_B_H = EDGE_WARPS * 2 * AWARP;     // 69632
constexpr int OFF_B_L = OFF_B_H + 32 * APITCH;      // 78336
constexpr int EDGE_DSMEM = OFF_B_L + 32 * APITCH;   // 87040  (2 blocks/SM, 16 warps/SM)
constexpr int EDGE_GRID = 296;

// node_gemm HMMA smem pitch (bytes): 64B of fp16 K + 16B pad -> conflict-free
constexpr int NGP = 80;

__device__ float g_state[Nn * Ss];
__device__ __half g_y[Nn * Hh];          // fp16 y (25.6MB)
__device__ float4 g_stats[Nn];           // stats computed from ROUNDED y
__device__ float g_gs[Gg * Ss];

__device__ __forceinline__ float lrelu(float v) { return v >= 0.f ? v : NEG_SLOPE * v; }

// ---- packed f32x2 helpers ----
__device__ __forceinline__ u64 pack2(float lo, float hi) {
    u64 r; asm("mov.b64 %0,{%1,%2};" : "=l"(r) : "f"(lo), "f"(hi)); return r;
}
__device__ __forceinline__ void unpack2(u64 v, float& lo, float& hi) {
    asm("mov.b64 {%0,%1},%2;" : "=f"(lo), "=f"(hi) : "l"(v));
}
__device__ __forceinline__ u64 fma2(u64 a, u64 b, u64 c) {
    u64 d; asm("fma.rn.f32x2 %0,%1,%2,%3;" : "=l"(d) : "l"(a), "l"(b), "l"(c)); return d;
}
__device__ __forceinline__ u64 add2(u64 a, u64 b) {
    u64 d; asm("add.rn.f32x2 %0,%1,%2;" : "=l"(d) : "l"(a), "l"(b)); return d;
}
__device__ __forceinline__ u64 mul2(u64 a, u64 b) {
    u64 d; asm("mul.rn.f32x2 %0,%1,%2;" : "=l"(d) : "l"(a), "l"(b)); return d;
}

__device__ __forceinline__ uint32_t smem_u32(const void* p) {
    uint32_t a;
    asm("{ .reg .u64 t; cvta.to.shared.u64 t, %1; cvt.u32.u64 %0, t; }" : "=r"(a) : "l"(p));
    return a;
}

__device__ __forceinline__ void ldsm4(uint32_t r[4], uint32_t addr) {
    asm volatile("ldmatrix.sync.aligned.m8n8.x4.shared.b16 {%0,%1,%2,%3}, [%4];"
                 : "=r"(r[0]), "=r"(r[1]), "=r"(r[2]), "=r"(r[3]) : "r"(addr));
}

__device__ __forceinline__ void mma16816h(float acc[4], const uint32_t a[4],
                                          uint32_t b0, uint32_t b1) {
    asm volatile(
        "mma.sync.aligned.m16n8k16.row.col.f32.f16.f16.f32 "
        "{%0,%1,%2,%3}, {%4,%5,%6,%7}, {%8,%9}, {%0,%1,%2,%3};"
        : "+f"(acc[0]), "+f"(acc[1]), "+f"(acc[2]), "+f"(acc[3])
        : "r"(a[0]), "r"(a[1]), "r"(a[2]), "r"(a[3]), "r"(b0), "r"(b1));
}

__device__ __forceinline__ uint32_t h2bits(__half2 h) { return *(uint32_t*)&h; }
__device__ __forceinline__ __half2 bits2h(uint32_t u) { return *(__half2*)&u; }

// ---------------------------------------------------------------------------
__global__ void zero_kernel() {
    int i = blockIdx.x * blockDim.x + threadIdx.x;
    int stride = gridDim.x * blockDim.x;
    for (int k = i; k < Nn * Ss; k += stride) g_state[k] = 0.f;
    for (int k = i; k < Gg * Ss; k += stride) g_gs[k] = 0.f;
}

// ---------------------------------------------------------------------------
// Tensorized node GEMM: y = fp16(state@W1[:32] + b1), stats from ROUNDED y.
// Warp tile = 16 nodes. A = state fp16 (random rounding), B = W1 fp16 hi+lo.
__global__ void __launch_bounds__(256) node_gemm_kernel(
    const float* __restrict__ W1, const float* __restrict__ b1)
{
    __shared__ char sA[8][16 * NGP];        // per-warp A staging (fp16)
    __shared__ char sBh[128 * NGP];         // W1 hi, [n][k] fp16
    __shared__ char sBl[128 * NGP];         // W1 lo
    __shared__ float sb1f[128];
    __shared__ __half sw32h[128];

    int tid = threadIdx.x;
    int lane = tid & 31;
    int wid = tid >> 5;

    // stage B = W1[:32] transposed, fp16 hi/lo
    for (int p = tid; p < 128 * 32; p += 256) {
        int n = p & 127;
        int k = p >> 7;
        float wv = W1[k * 128 + n];
        __half hb = __float2half_rn(wv);
        __half lb = __float2half_rn(wv - __half2float(hb));
        *(__half*)(sBh + n * NGP + k * 2) = hb;
        *(__half*)(sBl + n * NGP + k * 2) = lb;
    }
    if (tid < 128) {
        sb1f[tid] = b1[tid];
        sw32h[tid] = __float2half_rn(W1[32 * 128 + tid]);
    }
    __syncthreads();

    uint32_t sA_addr = smem_u32(&sA[wid][0]);
    uint32_t bh_addr = smem_u32(sBh);
    uint32_t bl_addr = smem_u32(sBl);

    int q = lane & 3;
    int rA = lane >> 2;          // 0..7
    int rB = rA + 8;

    uint32_t ldA = sA_addr + (lane & 15) * NGP + ((lane >> 4) & 1) * 16;
    int bRow = ((lane >> 4) & 1) * 8 + (lane & 7);
    int bKB = ((lane >> 3) & 1) * 16;
    uint32_t ldBh = bh_addr + bRow * NGP + bKB;
    uint32_t ldBl = bl_addr + bRow * NGP + bKB;

    int ntiles = Nn / 16;        // 6250
    int wg = blockIdx.x * 8 + wid;
    int nw = gridDim.x * 8;

    for (int t = wg; t < ntiles; t += nw) {
        int nbase = t * 16;

        // stage 16 state rows as fp16 (coalesced loads)
#pragma unroll
        for (int i = 0; i < 4; i++) {
            int fidx = lane + 32 * i;        // 0..127
            int row = fidx >> 3;
            int c8 = fidx & 7;
            float4 v = *(const float4*)&g_state[(nbase + row) * Ss + c8 * 4];
            __half2 h01 = __float22half2_rn(make_float2(v.x, v.y));
            __half2 h23 = __float22half2_rn(make_float2(v.z, v.w));
            u64 pk = (u64)h2bits(h01) | ((u64)h2bits(h23) << 32);
            *(u64*)(sA[wid] + row * NGP + c8 * 8) = pk;
        }
        __syncwarp();

        // MMA: acc[16 n-tiles][4]
        float acc[16][4];
#pragma unroll
        for (int nt = 0; nt < 16; nt++)
#pragma unroll
            for (int j = 0; j < 4; j++) acc[nt][j] = 0.f;

#pragma unroll
        for (int k = 0; k < 2; k++) {
            uint32_t a[4];
            ldsm4(a, ldA + k * 32);
#pragma unroll
            for (int nt2 = 0; nt2 < 8; nt2++) {
                uint32_t bh[4];
                ldsm4(bh, ldBh + nt2 * 16 * NGP + k * 32);
                mma16816h(acc[2 * nt2], a, bh[0], bh[1]);
                mma16816h(acc[2 * nt2 + 1], a, bh[2], bh[3]);
            }
#pragma unroll
            for (int nt2 = 0; nt2 < 8; nt2++) {
                uint32_t bl[4];
                ldsm4(bl, ldBl + nt2 * 16 * NGP + k * 32);
                mma16816h(acc[2 * nt2], a, bl[0], bl[1]);
                mma16816h(acc[2 * nt2 + 1], a, bl[2], bl[3]);
            }
        }
        __syncwarp();

        // epilogue: +b1, round to fp16, store y, accumulate stats from rounded
        float sSA = 0.f, qSA = 0.f, pSA = 0.f;
        float sSB = 0.f, qSB = 0.f, pSB = 0.f;
        __half* yrowA = &g_y[(nbase + rA) * Hh];
        __half* yrowB = &g_y[(nbase + rB) * Hh];
#pragma unroll
        for (int nt = 0; nt < 16; nt++) {
            int col = 8 * nt + 2 * q;
            float2 bv = *(const float2*)&sb1f[col];
            float2 wf = __half22float2(*(const __half2*)&sw32h[col]);

            __half2 hA = __float22half2_rn(make_float2(acc[nt][0] + bv.x,
                                                       acc[nt][1] + bv.y));
            *(uint32_t*)&yrowA[col] = h2bits(hA);
            float2 fA = __half22float2(hA);
            sSA += fA.x + fA.y;
            qSA += fA.x * fA.x + fA.y * fA.y;
            pSA += fA.x * wf.x + fA.y * wf.y;

            __half2 hB = __float22half2_rn(make_float2(acc[nt][2] + bv.x,
                                                       acc[nt][3] + bv.y));
            *(uint32_t*)&yrowB[col] = h2bits(hB);
            float2 fB = __half22float2(hB);
            sSB += fB.x + fB.y;
            qSB += fB.x * fB.x + fB.y * fB.y;
            pSB += fB.x * wf.x + fB.y * wf.y;
        }
#pragma unroll
        for (int o = 2; o; o >>= 1) {
            sSA += __shfl_xor_sync(FULL, sSA, o);
            qSA += __shfl_xor_sync(FULL, qSA, o);
            pSA += __shfl_xor_sync(FULL, pSA, o);
            sSB += __shfl_xor_sync(FULL, sSB, o);
            qSB += __shfl_xor_sync(FULL, qSB, o);
            pSB += __shfl_xor_sync(FULL, pSB, o);
        }
        if (q == 0) {
            g_stats[nbase + rA] = make_float4(sSA, qSA, pSA, 0.f);
            g_stats[nbase + rB] = make_float4(sSB, qSB, pSB, 0.f);
        }
        __syncwarp();
    }
}

// ---------------------------------------------------------------------------
// per-tile epilogue: packed bias + LN2 (quad reduce) + 4 float4 atomics
__device__ __forceinline__ void epilogue_tile(
    const float acc[4][4], int dstA, int dstB, int q,
    const u64 b2p[4], const u64 g2p[4], const u64 be2p[4], u64 C001,
    float* __restrict__ state_out)
{
    u64 mA[4], mB[4];
#pragma unroll
    for (int t = 0; t < 4; t++) {
        mA[t] = add2(pack2(acc[t][0], acc[t][1]), b2p[t]);
        mB[t] = add2(pack2(acc[t][2], acc[t][3]), b2p[t]);
    }
    u64 sA2 = add2(add2(mA[0], mA[1]), add2(mA[2], mA[3]));
    u64 sB2 = add2(add2(mB[0], mB[1]), add2(mB[2], mB[3]));
    u64 qA2 = fma2(mA[0], mA[0], fma2(mA[1], mA[1], fma2(mA[2], mA[2], mul2(mA[3], mA[3]))));
    u64 qB2 = fma2(mB[0], mB[0], fma2(mB[1], mB[1], fma2(mB[2], mB[2], mul2(mB[3], mB[3]))));
    float t0, t1;
    unpack2(sA2, t0, t1); float sA = t0 + t1;
    unpack2(qA2, t0, t1); float qA = t0 + t1;
    unpack2(sB2, t0, t1); float sB = t0 + t1;
    unpack2(qB2, t0, t1); float qB = t0 + t1;
#pragma unroll
    for (int o = 2; o; o >>= 1) {
        sA += __shfl_xor_sync(FULL, sA, o);
        qA += __shfl_xor_sync(FULL, qA, o);
        sB += __shfl_xor_sync(FULL, sB, o);
        qB += __shfl_xor_sync(FULL, qB, o);
    }
    float meanA = sA * (1.f / 32.f);
    float rstdA = rsqrtf(qA * (1.f / 32.f) - meanA * meanA + LN_EPS);
    float meanB = sB * (1.f / 32.f);
    float rstdB = rsqrtf(qB * (1.f / 32.f) - meanB * meanB + LN_EPS);

    u64 rA2p = pack2(rstdA, rstdA), nmA2 = pack2(-meanA, -meanA);
    u64 rB2p = pack2(rstdB, rstdB), nmB2 = pack2(-meanB, -meanB);

    float vA[8], vB[8];
#pragma unroll
    for (int t = 0; t < 4; t++) {
        u64 agA = mul2(rA2p, g2p[t]);
        u64 offA = fma2(nmA2, agA, be2p[t]);
        u64 hA = fma2(mA[t], agA, offA);
        u64 pA = mul2(hA, C001);
        float h0, h1, p0, p1;
        unpack2(hA, h0, h1); unpack2(pA, p0, p1);
        vA[2 * t] = fmaxf(h0, p0); vA[2 * t + 1] = fmaxf(h1, p1);

        u64 agB = mul2(rB2p, g2p[t]);
        u64 offB = fma2(nmB2, agB, be2p[t]);
        u64 hB = fma2(mB[t], agB, offB);
        u64 pB = mul2(hB, C001);
        unpack2(hB, h0, h1); unpack2(pB, p0, p1);
        vB[2 * t] = fmaxf(h0, p0); vB[2 * t + 1] = fmaxf(h1, p1);
    }

    float* rowA = &state_out[dstA * Ss + 8 * q];
    float* rowB = &state_out[dstB * Ss + 8 * q];
    atomicAdd((float4*)&rowA[0], make_float4(vA[0], vA[1], vA[2], vA[3]));
    atomicAdd((float4*)&rowA[4], make_float4(vA[4], vA[5], vA[6], vA[7]));
    atomicAdd((float4*)&rowB[0], make_float4(vB[0], vB[1], vB[2], vB[3]));
    atomicAdd((float4*)&rowB[4], make_float4(vB[4], vB[5], vB[6], vB[7]));
}

// ---------------------------------------------------------------------------
// Edge kernel (R16 champion): half2 LN1 prologue, distributed stats,
// fp16 A single / B hi-lo, 32-edge groups with B reuse.
template <bool ROUND0>
__global__ void __launch_bounds__(256, 2) edge_kernel(
    const int* __restrict__ nf, const int* __restrict__ nt,
    const float* __restrict__ ec,
    const float* __restrict__ W1, const float* __restrict__ b1,
    const float* __restrict__ g1, const float* __restrict__ be1,
    const float* __restrict__ W2, const float* __restrict__ b2,
    const float* __restrict__ g2, const float* __restrict__ be2)
{
    extern __shared__ char dsm[];
    uint32_t sbase = smem_u32(dsm);

    int tid = threadIdx.x;
    int lane = tid & 31;
    int wid = tid >> 5;

    for (int p = tid; p < 32 * 128; p += 256) {
        int n = p >> 7;
        int k = p & 127;
        int t = n >> 3, q0 = (n >> 1) & 3, r = n & 1;
        int pn = 8 * q0 + 2 * t + r;
        float wv = W2[k * 32 + pn];
        __half hb = __float2half_rn(wv);
        __half lb = __float2half_rn(wv - __half2float(hb));
        *(__half*)(dsm + OFF_B_H + n * APITCH + k * 2) = hb;
        *(__half*)(dsm + OFF_B_L + n * APITCH + k * 2) = lb;
    }
    __syncthreads();

    __half2 w32h0, w32h1, b1h0, b1h1, g1h0, g1h1, be1h0, be1h1;
    float4 w32v, b1vr;
    {
        float4 wr = *(const float4*)&W1[32 * 128 + 4 * lane];
        w32h0 = __float22half2_rn(make_float2(wr.x, wr.y));
        w32h1 = __float22half2_rn(make_float2(wr.z, wr.w));
        float2 f0 = __half22float2(w32h0), f1 = __half22float2(w32h1);
        w32v = make_float4(f0.x, f0.y, f1.x, f1.y);

        float4 bv = *(const float4*)&b1[4 * lane];
        b1h0 = __float22half2_rn(make_float2(bv.x, bv.y));
        b1h1 = __float22half2_rn(make_float2(bv.z, bv.w));
        float2 g0 = __half22float2(b1h0), g1f = __half22float2(b1h1);
        b1vr = make_float4(g0.x, g0.y, g1f.x, g1f.y);

        float4 gv = *(const float4*)&g1[4 * lane];
        g1h0 = __float22half2_rn(make_float2(gv.x, gv.y));
        g1h1 = __float22half2_rn(make_float2(gv.z, gv.w));
        float4 bev = *(const float4*)&be1[4 * lane];
        be1h0 = __float22half2_rn(make_float2(bev.x, bev.y));
        be1h1 = __float22half2_rn(make_float2(bev.z, bev.w));
    }

    float Sw = w32v.x + w32v.y + w32v.z + w32v.w;
    float Qw = w32v.x * w32v.x + w32v.y * w32v.y + w32v.z * w32v.z + w32v.w * w32v.w;
    float Sb = b1vr.x + b1vr.y + b1vr.z + b1vr.w;
    float Qb = b1vr.x * b1vr.x + b1vr.y * b1vr.y + b1vr.z * b1vr.z + b1vr.w * b1vr.w;
    float Pb = b1vr.x * w32v.x + b1vr.y * w32v.y + b1vr.z * w32v.z + b1vr.w * w32v.w;
#pragma unroll
    for (int o = 16; o; o >>= 1) {
        Sw += __shfl_xor_sync(FULL, Sw, o);
        Qw += __shfl_xor_sync(FULL, Qw, o);
        Sb += __shfl_xor_sync(FULL, Sb, o);
        Qb += __shfl_xor_sync(FULL, Qb, o);
        Pb += __shfl_xor_sync(FULL, Pb, o);
    }

    int q = lane & 3;
    int rA = lane >> 2;
    int rB = rA + 8;

    u64 b2p[4], g2p[4], be2p[4];
#pragma unroll
    for (int t = 0; t < 4; t++) {
        int c = 8 * q + 2 * t;
        b2p[t]  = pack2(b2[c],  b2[c + 1]);
        g2p[t]  = pack2(g2[c],  g2[c + 1]);
        be2p[t] = pack2(be2[c], be2[c + 1]);
    }
    const u64 C001 = pack2(NEG_SLOPE, NEG_SLOPE);
    const __half2 slope2 = __float2half2_rn(NEG_SLOPE);

    char* aStore = dsm + wid * 2 * AWARP + lane * 8;

    int aRow = lane & 15;
    int aColB = ((lane >> 4) & 1) * 16;
    uint32_t ldA0 = sbase + wid * 2 * AWARP + aRow * APITCH + aColB;
    uint32_t ldA1 = ldA0 + AWARP;

    int bRow = ((lane >> 4) & 1) * 8 + (lane & 7);
    int bKB = ((lane >> 3) & 1) * 16;
    uint32_t ldBH01 = sbase + OFF_B_H + bRow * APITCH + bKB;
    uint32_t ldBH23 = ldBH01 + 16 * APITCH;
    uint32_t ldBL01 = sbase + OFF_B_L + bRow * APITCH + bKB;
    uint32_t ldBL23 = ldBL01 + 16 * APITCH;

    const __half* __restrict__ yh = g_y;
    float* __restrict__ state_out = g_state;

    int ngroups = Ee / 32;          // 50000
    int wg = blockIdx.x * EDGE_WARPS + wid;
    int nw = gridDim.x * EDGE_WARPS;

    for (int g = wg; g < ngroups; g += nw) {
        int base = g * 32;

        uint32_t nm2L, r2L;
        {
            float cL = __ldg(&ec[base + lane]);
            float sL, qL;
            if constexpr (ROUND0) {
                sL = fmaf(cL, Sw, Sb);
                qL = fmaf(cL * cL, Qw, fmaf(2.f * cL, Pb, Qb));
            } else {
                int srcL = __ldg(&nf[base + lane]);
                float4 st = g_stats[srcL];
                sL = fmaf(cL, Sw, st.x);
                qL = fmaf(cL * cL, Qw, fmaf(2.f * cL, st.z, st.y));
            }
            float meanL = sL * (1.f / 128.f);
            float varL = fmaf(qL, 1.f / 128.f, -meanL * meanL);
            float rstdL = rsqrtf(varL + LN_EPS);
            nm2L = h2bits(__float2half2_rn(-meanL));
            r2L  = h2bits(__float2half2_rn(rstdL));
        }

#pragma unroll
        for (int j = 0; j < 8; j++) {
            float4 C = *(const float4*)&ec[base + 4 * j];
            float cs[4] = {C.x, C.y, C.z, C.w};
            int srcs[4];
            if constexpr (!ROUND0) {
                int4 NF = *(const int4*)&nf[base + 4 * j];
                srcs[0] = NF.x; srcs[1] = NF.y; srcs[2] = NF.z; srcs[3] = NF.w;
            }
#pragma unroll
            for (int e = 0; e < 4; e++) {
                int row = 4 * j + e;
                __half2 nmh = bits2h(__shfl_sync(FULL, nm2L, row));
                __half2 rh  = bits2h(__shfl_sync(FULL, r2L, row));

                __half2 a0h, a1h;
                if constexpr (ROUND0) {
                    a0h = b1h0; a1h = b1h1;
                } else {
                    uint2 pk = *(const uint2*)&yh[srcs[e] * Hh + 4 * lane];
                    a0h = bits2h(pk.x);
                    a1h = bits2h(pk.y);
                }
                __half2 c2 = __float2half2_rn(cs[e]);
                a0h = __hfma2(c2, w32h0, a0h);
                a1h = __hfma2(c2, w32h1, a1h);

                __half2 rg0 = __hmul2(rh, g1h0);
                __half2 rg1 = __hmul2(rh, g1h1);
                __half2 off0 = __hfma2(nmh, rg0, be1h0);
                __half2 off1 = __hfma2(nmh, rg1, be1h1);
                __half2 h0 = __hfma2(a0h, rg0, off0);
                __half2 h1 = __hfma2(a1h, rg1, off1);
                h0 = __hmax2(h0, __hmul2(h0, slope2));
                h1 = __hmax2(h1, __hmul2(h1, slope2));

                u64 packh = (u64)h2bits(h0) | ((u64)h2bits(h1) << 32);
                char* dst = aStore + (row >> 4) * AWARP + (row & 15) * APITCH;
                *(u64*)dst = packh;
            }
        }
        __syncwarp();

        int dstA0 = __ldg(&nt[base + rA]);
        int dstB0 = __ldg(&nt[base + rB]);
        int dstA1 = __ldg(&nt[base + 16 + rA]);
        int dstB1 = __ldg(&nt[base + 16 + rB]);

        float acc0[4][4], acc1[4][4];
#pragma unroll
        for (int t = 0; t < 4; t++)
#pragma unroll
            for (int j2 = 0; j2 < 4; j2++) { acc0[t][j2] = 0.f; acc1[t][j2] = 0.f; }

#pragma unroll
        for (int k = 0; k < 8; k++) {
            uint32_t bh01[4], bh23[4], bl01[4], bl23[4];
            ldsm4(bh01, ldBH01 + k * 32);
            ldsm4(bh23, ldBH23 + k * 32);
            ldsm4(bl01, ldBL01 + k * 32);
            ldsm4(bl23, ldBL23 + k * 32);

            uint32_t a0[4], a1[4];
            ldsm4(a0, ldA0 + k * 32);
            ldsm4(a1, ldA1 + k * 32);

            mma16816h(acc0[0], a0, bh01[0], bh01[1]);
            mma16816h(acc0[1], a0, bh01[2], bh01[3]);
            mma16816h(acc0[2], a0, bh23[0], bh23[1]);
            mma16816h(acc0[3], a0, bh23[2], bh23[3]);
            mma16816h(acc0[0], a0, bl01[0], bl01[1]);
            mma16816h(acc0[1], a0, bl01[2], bl01[3]);
            mma16816h(acc0[2], a0, bl23[0], bl23[1]);
            mma16816h(acc0[3], a0, bl23[2], bl23[3]);

            mma16816h(acc1[0], a1, bh01[0], bh01[1]);
            mma16816h(acc1[1], a1, bh01[2], bh01[3]);
            mma16816h(acc1[2], a1, bh23[0], bh23[1]);
            mma16816h(acc1[3], a1, bh23[2], bh23[3]);
            mma16816h(acc1[0], a1, bl01[0], bl01[1]);
            mma16816h(acc1[1], a1, bl01[2], bl01[3]);
            mma16816h(acc1[2], a1, bl23[0], bl23[1]);
            mma16816h(acc1[3], a1, bl23[2], bl23[3]);
        }
        __syncwarp();

        epilogue_tile(acc0, dstA0, dstB0, q, b2p, g2p, be2p, C001, state_out);
        epilogue_tile(acc1, dstA1, dstB1, q, b2p, g2p, be2p, C001, state_out);
    }
}

// ---------------------------------------------------------------------------
__global__ void graphsum_kernel(const int* __restrict__ ngi) {
    int t = blockIdx.x * blockDim.x + threadIdx.x;
    int total = Nn * (Ss / 4);
    if (t >= total) return;
    int n = t >> 3;
    int q = t & 7;
    const float4* s = reinterpret_cast<const float4*>(g_state);
    float4 v = s[t];
    int g = ngi[n];
    atomicAdd(reinterpret_cast<float4*>(&g_gs[g * Ss + 4 * q]), v);
}

// ---------------------------------------------------------------------------
__global__ void __launch_bounds__(128) readout_kernel(
    const float* __restrict__ Wo1, const float* __restrict__ bo1,
    const float* __restrict__ go, const float* __restrict__ beo,
    const float* __restrict__ Wo2, const float* __restrict__ bo2,
    float* __restrict__ out)
{
    __shared__ float sW[32 * 128];
    __shared__ float sb[128], sg[128], sbe[128];
    __shared__ float sW2[256];
    __shared__ float sb2[2];

    int tid = threadIdx.x;
    for (int i = tid; i < 32 * 128; i += 128) sW[i] = Wo1[i];
    sb[tid] = bo1[tid]; sg[tid] = go[tid]; sbe[tid] = beo[tid];
    sW2[tid] = Wo2[tid];
    sW2[tid + 128] = Wo2[tid + 128];
    if (tid < 2) sb2[tid] = bo2[tid];
    __syncthreads();

    int lane = tid & 31;
    int w = tid >> 5;
    int g = blockIdx.x * 4 + w;
    if (g >= Gg) return;

    float x = g_gs[g * Ss + lane];
    float4 a;
    a.x = sb[4 * lane]; a.y = sb[4 * lane + 1]; a.z = sb[4 * lane + 2]; a.w = sb[4 * lane + 3];
#pragma unroll
    for (int i = 0; i < 32; i++) {
        float xi = __shfl_sync(FULL, x, i);
        float4 wv = *(const float4*)&sW[i * 128 + 4 * lane];
        a.x += xi * wv.x; a.y += xi * wv.y; a.z += xi * wv.z; a.w += xi * wv.w;
    }
    float s = a.x + a.y + a.z + a.w;
    float s2 = a.x * a.x + a.y * a.y + a.z * a.z + a.w * a.w;
#pragma unroll
    for (int o = 16; o; o >>= 1) {
        s += __shfl_xor_sync(FULL, s, o);
        s2 += __shfl_xor_sync(FULL, s2, o);
    }
    float mean = s * (1.f / 128.f);
    float var = s2 * (1.f / 128.f) - mean * mean;
    float rstd = rsqrtf(var + LN_EPS);
    float h0 = lrelu((a.x - mean) * rstd * sg[4 * lane + 0] + sbe[4 * lane + 0]);
    float h1 = lrelu((a.y - mean) * rstd * sg[4 * lane + 1] + sbe[4 * lane + 1]);
    float h2 = lrelu((a.z - mean) * rstd * sg[4 * lane + 2] + sbe[4 * lane + 2]);
    float h3 = lrelu((a.w - mean) * rstd * sg[4 * lane + 3] + sbe[4 * lane + 3]);

    float p0 = h0 * sW2[(4 * lane + 0) * 2] + h1 * sW2[(4 * lane + 1) * 2]
             + h2 * sW2[(4 * lane + 2) * 2] + h3 * sW2[(4 * lane + 3) * 2];
    float p1 = h0 * sW2[(4 * lane + 0) * 2 + 1] + h1 * sW2[(4 * lane + 1) * 2 + 1]
             + h2 * sW2[(4 * lane + 2) * 2 + 1] + h3 * sW2[(4 * lane + 3) * 2 + 1];
#pragma unroll
    for (int o = 16; o; o >>= 1) {
        p0 += __shfl_xor_sync(FULL, p0, o);
        p1 += __shfl_xor_sync(FULL, p1, o);
    }
    if (lane == 0) {
        float mu = p0 + sb2[0];
        float v = p1 + sb2[1];
        float sp = (v > 0.f) ? v + log1pf(expf(-v)) : log1pf(expf(v));
        out[g * 2 + 0] = mu;
        out[g * 2 + 1] = sp;
    }
}

// ---------------------------------------------------------------------------
extern "C" void kernel_launch(void* const* d_in, const int* in_sizes, int n_in,
                              void* d_out, int out_size) {
    const int* nf = (const int*)d_in[0];
    const int* nt = (const int*)d_in[1];
    const float* ec = (const float*)d_in[2];
    const int* ngi = (const int*)d_in[3];
    const float* W1 = (const float*)d_in[6];
    const float* b1 = (const float*)d_in[7];
    const float* g1 = (const float*)d_in[8];
    const float* be1 = (const float*)d_in[9];
    const float* W2 = (const float*)d_in[10];
    const float* b2 = (const float*)d_in[11];
    const float* g2 = (const float*)d_in[12];
    const float* be2 = (const float*)d_in[13];
    const float* Wo1 = (const float*)d_in[14];
    const float* bo1 = (const float*)d_in[15];
    const float* go = (const float*)d_in[16];
    const float* beo = (const float*)d_in[17];
    const float* Wo2 = (const float*)d_in[18];
    const float* bo2 = (const float*)d_in[19];
    float* out = (float*)d_out;

    cudaFuncSetAttribute(edge_kernel<true>, cudaFuncAttributeMaxDynamicSharedMemorySize, EDGE_DSMEM);
    cudaFuncSetAttribute(edge_kernel<false>, cudaFuncAttributeMaxDynamicSharedMemorySize, EDGE_DSMEM);

    zero_kernel<<<4096, 256>>>();

    // round 0: state == 0 -> y == round(b1) uniform; skip node_gemm, no gather
    edge_kernel<true><<<EDGE_GRID, 256, EDGE_DSMEM>>>(nf, nt, ec,
                                                      W1, b1, g1, be1, W2, b2, g2, be2);
    // rounds 1..4
    for (int r = 1; r < ROUNDS; r++) {
        node_gemm_kernel<<<296, 256>>>(W1, b1);
        edge_kernel<false><<<EDGE_GRID, 256, EDGE_DSMEM>>>(nf, nt, ec,
                                                           W1, b1, g1, be1, W2, b2, g2, be2);
    }

    graphsum_kernel<<<(Nn * 8 + 255) / 256, 256>>>(ngi);
    readout_kernel<<<(Gg + 3) / 4, 128>>>(Wo1, bo1, go, beo, Wo2, bo2, out);
}